// round 11
// baseline (speedup 1.0000x reference)
#include <cuda_runtime.h>
#include <cuda_bf16.h>
#include <cstdint>
#include <cstddef>

// ---------------------------------------------------------------------------
// Problem constants
// ---------------------------------------------------------------------------
#define BB   2
#define LL   2048
#define DD   512
#define HH   8
#define DHH  64
#define DFCN 2048
#define MM   (BB * LL)        // 4096 rows

typedef unsigned long long u64;
typedef unsigned int u32;

// ---------------------------------------------------------------------------
// Scratch (device globals: allocation-guard-safe)
// ---------------------------------------------------------------------------
__device__ __nv_bfloat16 g_xh[MM * DD],   g_xl[MM * DD];      // split x
__device__ __nv_bfloat16 g_qh[MM * DD],   g_ql[MM * DD];      // split scaled Q
__device__ __nv_bfloat16 g_kh[MM * DD],   g_kl[MM * DD];      // split K
__device__ __nv_bfloat16 g_vth[BB*HH*DHH * LL], g_vtl[BB*HH*DHH * LL]; // V^T split
__device__ __nv_bfloat16 g_relh[LL * DD], g_rell[LL * DD];    // split rel_emb
__device__ __nv_bfloat16 g_ah[MM * DD],   g_al[MM * DD];      // split attn out
__device__ __nv_bfloat16 g_hh[MM * DFCN], g_hl[MM * DFCN];    // split FFN hidden

// Transposed + split weights: T[n][k] = W[k][n]
__device__ __nv_bfloat16 g_wqh[DD * DD],   g_wql[DD * DD];
__device__ __nv_bfloat16 g_wkh[DD * DD],   g_wkl[DD * DD];
__device__ __nv_bfloat16 g_wvh[DD * DD],   g_wvl[DD * DD];
__device__ __nv_bfloat16 g_w1h[DFCN * DD], g_w1l[DFCN * DD];
__device__ __nv_bfloat16 g_w2h[DD * DFCN], g_w2l[DD * DFCN];

// ---------------------------------------------------------------------------
// Helpers
// ---------------------------------------------------------------------------
__device__ __forceinline__ u32 smem_u32(const void* p) {
    u32 a;
    asm("{ .reg .u64 t; cvta.to.shared.u64 t, %1; cvt.u32.u64 %0, t; }"
        : "=r"(a) : "l"(p));
    return a;
}

__device__ __forceinline__ u32 pack_bf2(__nv_bfloat16 a, __nv_bfloat16 b) {
    return (u32)__bfloat16_as_ushort(a) | ((u32)__bfloat16_as_ushort(b) << 16);
}

__device__ __forceinline__ void split2(float x, float y, u32& hp, u32& lp) {
    __nv_bfloat16 hx = __float2bfloat16(x), hy = __float2bfloat16(y);
    hp = pack_bf2(hx, hy);
    lp = pack_bf2(__float2bfloat16(x - __bfloat162float(hx)),
                  __float2bfloat16(y - __bfloat162float(hy)));
}

#define LDSM_X4(r, addr) \
    asm volatile("ldmatrix.sync.aligned.m8n8.x4.shared.b16 {%0,%1,%2,%3}, [%4];" \
        : "=r"((r)[0]), "=r"((r)[1]), "=r"((r)[2]), "=r"((r)[3]) : "r"(addr))

#define MMA_BF16(d, a, b0, b1) \
    asm volatile("mma.sync.aligned.m16n8k16.row.col.f32.bf16.bf16.f32 " \
        "{%0,%1,%2,%3}, {%4,%5,%6,%7}, {%8,%9}, {%0,%1,%2,%3};" \
        : "+f"((d)[0]), "+f"((d)[1]), "+f"((d)[2]), "+f"((d)[3]) \
        : "r"((a)[0]), "r"((a)[1]), "r"((a)[2]), "r"((a)[3]), "r"(b0), "r"(b1))

__device__ __forceinline__ void cp16(u32 dst, const void* src) {
    asm volatile("cp.async.cg.shared.global [%0], [%1], 16;"
                 :: "r"(dst), "l"(src) : "memory");
}
#define CP_COMMIT()  asm volatile("cp.async.commit_group;" ::: "memory")
#define CP_WAIT(n)   asm volatile("cp.async.wait_group %0;" :: "n"(n) : "memory")

// ---------------------------------------------------------------------------
// Prep kernels
// ---------------------------------------------------------------------------
__global__ __launch_bounds__(256)
void tsplit3_kernel(const float* __restrict__ wq, const float* __restrict__ wk,
                    const float* __restrict__ wv,
                    __nv_bfloat16* __restrict__ qhh, __nv_bfloat16* __restrict__ qll,
                    __nv_bfloat16* __restrict__ khh, __nv_bfloat16* __restrict__ kll,
                    __nv_bfloat16* __restrict__ vhh, __nv_bfloat16* __restrict__ vll)
{
    const float* W = blockIdx.z == 0 ? wq : blockIdx.z == 1 ? wk : wv;
    __nv_bfloat16* Th = blockIdx.z == 0 ? qhh : blockIdx.z == 1 ? khh : vhh;
    __nv_bfloat16* Tl = blockIdx.z == 0 ? qll : blockIdx.z == 1 ? kll : vll;

    __shared__ float t[32][33];
    const int n0 = blockIdx.x * 32, k0 = blockIdx.y * 32;
    const int tx = threadIdx.x & 31, ty = threadIdx.x >> 5;
#pragma unroll
    for (int i = 0; i < 4; i++)
        t[ty + 8 * i][tx] = W[(size_t)(k0 + ty + 8 * i) * DD + n0 + tx];
    __syncthreads();
#pragma unroll
    for (int i = 0; i < 4; i++) {
        int n = n0 + ty + 8 * i;
        float v = t[tx][ty + 8 * i];
        __nv_bfloat16 h = __float2bfloat16(v);
        Th[(size_t)n * DD + k0 + tx] = h;
        Tl[(size_t)n * DD + k0 + tx] = __float2bfloat16(v - __bfloat162float(h));
    }
}

__global__ __launch_bounds__(256)
void tsplit_ffn_kernel(const float* __restrict__ w1, const float* __restrict__ w2,
                       __nv_bfloat16* __restrict__ w1h, __nv_bfloat16* __restrict__ w1l,
                       __nv_bfloat16* __restrict__ w2h, __nv_bfloat16* __restrict__ w2l)
{
    const int z = blockIdx.z;
    const float* W = z == 0 ? w1 : w2;
    __nv_bfloat16* Th = z == 0 ? w1h : w2h;
    __nv_bfloat16* Tl = z == 0 ? w1l : w2l;
    const int K = z == 0 ? DD : DFCN;
    const int N = z == 0 ? DFCN : DD;
    const int n0 = (z == 0 ? blockIdx.x : blockIdx.y) * 32;
    const int k0 = (z == 0 ? blockIdx.y : blockIdx.x) * 32;

    __shared__ float t[32][33];
    const int tx = threadIdx.x & 31, ty = threadIdx.x >> 5;
#pragma unroll
    for (int i = 0; i < 4; i++)
        t[ty + 8 * i][tx] = W[(size_t)(k0 + ty + 8 * i) * N + n0 + tx];
    __syncthreads();
#pragma unroll
    for (int i = 0; i < 4; i++) {
        int n = n0 + ty + 8 * i;
        float v = t[tx][ty + 8 * i];
        __nv_bfloat16 h = __float2bfloat16(v);
        Th[(size_t)n * K + k0 + tx] = h;
        Tl[(size_t)n * K + k0 + tx] = __float2bfloat16(v - __bfloat162float(h));
    }
}

#define N4X (MM * DD / 4)
#define N4R (LL * DD / 4)
__global__ __launch_bounds__(256)
void conv_xrel_kernel(const float4* __restrict__ X, const float4* __restrict__ R,
                      __nv_bfloat16* __restrict__ XH, __nv_bfloat16* __restrict__ XL,
                      __nv_bfloat16* __restrict__ RH, __nv_bfloat16* __restrict__ RL)
{
    int i = blockIdx.x * blockDim.x + threadIdx.x;
    const float4* src; __nv_bfloat16 *H, *L; int j;
    if (i < N4X) { src = X; H = XH; L = XL; j = i; }
    else if (i < N4X + N4R) { src = R; H = RH; L = RL; j = i - N4X; }
    else return;
    float4 v = src[j];
    u32 h0, l0, h1, l1;
    split2(v.x, v.y, h0, l0);
    split2(v.z, v.w, h1, l1);
    *(uint2*)(H + 4 * (size_t)j) = make_uint2(h0, h1);
    *(uint2*)(L + 4 * (size_t)j) = make_uint2(l0, l1);
}

// ---------------------------------------------------------------------------
// Split-bf16 HMMA GEMM core: BK=32, 3-stage cp.async ring, 128x128 CTA tile,
// 8 warps (2x4), 64x32 warp tile. Smem rows 64B (32 bf16), 16B-chunk swizzle
// c ^= (row>>1)&3. Designed for 2 CTAs/SM: 96KB smem, <=128 regs
// (B-frags preloaded per k16, A-frags loaded per-mt -> small live set).
// ---------------------------------------------------------------------------
#define TGN_TILE  8192                  // 128 x 32 x 2B
#define TGN_STAGE (4 * TGN_TILE)        // Ah, Al, Bh, Bl = 32KB
#define TGN_SMEM  (3 * TGN_STAGE)       // 96KB -> 2 CTAs/SM

__device__ __forceinline__ void load_tile32(const __nv_bfloat16* __restrict__ src,
                                            int ldk, u32 sdst, int tid)
{
    // 128 rows x 4 16B chunks = 512 chunks, 256 threads x 2
#pragma unroll
    for (int i = 0; i < 2; i++) {
        int idx = tid + 256 * i;
        int r = idx >> 2, c = idx & 3;
        cp16(sdst + r * 64 + 16 * (c ^ ((r >> 1) & 3)), src + (size_t)r * ldk + 8 * c);
    }
}

__device__ __forceinline__ void tgn_stage_load(
    u32 sdst, const __nv_bfloat16* Ah, const __nv_bfloat16* Al,
    const __nv_bfloat16* Bh, const __nv_bfloat16* Bl, int K, int kofs, int tid)
{
    load_tile32(Ah + kofs, K, sdst,                tid);
    load_tile32(Al + kofs, K, sdst +     TGN_TILE, tid);
    load_tile32(Bh + kofs, K, sdst + 2 * TGN_TILE, tid);
    load_tile32(Bl + kofs, K, sdst + 3 * TGN_TILE, tid);
}

__device__ __forceinline__ void tgn_compute_chunk(
    u32 base, int wm, int wn, int lr16, int lc, float acc[4][4][4])
{
    const u32 sAh = base, sAl = base + TGN_TILE,
              sBh = base + 2 * TGN_TILE, sBl = base + 3 * TGN_TILE;
#pragma unroll
    for (int ks = 0; ks < 2; ks++) {
        const int ch = 2 * ks + lc;
        // Preload B fragments for this k16 (16 regs live)
        u32 bh[2][4], bl[2][4];
#pragma unroll
        for (int ng = 0; ng < 2; ng++) {
            int r = wn * 32 + ng * 16 + lr16;
            u32 off = r * 64 + 16 * (ch ^ ((r >> 1) & 3));
            LDSM_X4(bh[ng], sBh + off);
            LDSM_X4(bl[ng], sBl + off);
        }
        // Per-mt: load A frags, fire 12 MMAs (pass-major within row)
#pragma unroll
        for (int mt = 0; mt < 4; mt++) {
            int r = wm * 64 + mt * 16 + lr16;
            u32 off = r * 64 + 16 * (ch ^ ((r >> 1) & 3));
            u32 ah[4], al[4];
            LDSM_X4(ah, sAh + off);
            LDSM_X4(al, sAl + off);
#pragma unroll
            for (int nt = 0; nt < 4; nt++) {
                const int ng = nt >> 1, hi = nt & 1;
                MMA_BF16(acc[mt][nt], ah, bh[ng][hi], bh[ng][2 + hi]);
            }
#pragma unroll
            for (int nt = 0; nt < 4; nt++) {
                const int ng = nt >> 1, hi = nt & 1;
                MMA_BF16(acc[mt][nt], ah, bl[ng][hi], bl[ng][2 + hi]);
            }
#pragma unroll
            for (int nt = 0; nt < 4; nt++) {
                const int ng = nt >> 1, hi = nt & 1;
                MMA_BF16(acc[mt][nt], al, bh[ng][hi], bh[ng][2 + hi]);
            }
        }
    }
}

__device__ __forceinline__ void tgn_mainloop(
    u32 sb, const __nv_bfloat16* Abase_h, const __nv_bfloat16* Abase_l,
    const __nv_bfloat16* Bbase_h, const __nv_bfloat16* Bbase_l,
    int K, int tid, int wm, int wn, int lr16, int lc, float acc[4][4][4])
{
    const int NC = K >> 5;
    tgn_stage_load(sb, Abase_h, Abase_l, Bbase_h, Bbase_l, K, 0, tid);
    CP_COMMIT();
    if (NC > 1) {
        tgn_stage_load(sb + TGN_STAGE, Abase_h, Abase_l, Bbase_h, Bbase_l, K, 32, tid);
        CP_COMMIT();
    }
    int sc = 0, sn = 2;   // compute slot, next-load slot
    for (int c = 0; c < NC; c++) {
        CP_WAIT(1);
        __syncthreads();
        if (c + 2 < NC) {
            tgn_stage_load(sb + sn * TGN_STAGE,
                           Abase_h, Abase_l, Bbase_h, Bbase_l, K, (c + 2) * 32, tid);
            CP_COMMIT();
        } else {
            CP_COMMIT();
        }
        tgn_compute_chunk(sb + sc * TGN_STAGE, wm, wn, lr16, lc, acc);
        sc = sc == 2 ? 0 : sc + 1;
        sn = sn == 2 ? 0 : sn + 1;
    }
}

// Generic GEMM: MODE 0 fp32 out, MODE 1 relu+split
template <int MODE>
__global__ __launch_bounds__(256, 2)
void tgemm_kernel(const __nv_bfloat16* __restrict__ Ah,
                  const __nv_bfloat16* __restrict__ Al,
                  const __nv_bfloat16* __restrict__ Bh,
                  const __nv_bfloat16* __restrict__ Bl,
                  const float* __restrict__ bias,
                  float* __restrict__ Cf,
                  __nv_bfloat16* __restrict__ Ch,
                  __nv_bfloat16* __restrict__ Cl,
                  int M, int N, int K)
{
    extern __shared__ char smem[];
    const u32 sb = smem_u32(smem);
    const int tid  = threadIdx.x;
    const int wid  = tid >> 5, lane = tid & 31;
    const int wm   = wid >> 2, wn = wid & 3;
    const int m0   = blockIdx.y * 128;
    const int n0   = blockIdx.x * 128;
    const int lr16 = lane & 15, lc = lane >> 4;

    float acc[4][4][4];
#pragma unroll
    for (int mt = 0; mt < 4; mt++)
#pragma unroll
        for (int nt = 0; nt < 4; nt++)
#pragma unroll
            for (int r = 0; r < 4; r++) acc[mt][nt][r] = 0.0f;

    tgn_mainloop(sb, Ah + (size_t)m0 * K, Al + (size_t)m0 * K,
                 Bh + (size_t)n0 * K, Bl + (size_t)n0 * K,
                 K, tid, wm, wn, lr16, lc, acc);

    const int tg = lane >> 2;
    const int tc = (lane & 3) * 2;
#pragma unroll
    for (int mt = 0; mt < 4; mt++) {
#pragma unroll
        for (int half = 0; half < 2; half++) {
            const int m = m0 + wm * 64 + mt * 16 + tg + 8 * half;
#pragma unroll
            for (int nt = 0; nt < 4; nt++) {
                const int n = n0 + wn * 32 + nt * 8 + tc;
                float v0 = acc[mt][nt][2 * half]     + bias[n];
                float v1 = acc[mt][nt][2 * half + 1] + bias[n + 1];
                if (MODE == 0) {
                    *(float2*)(Cf + (size_t)m * N + n) = make_float2(v0, v1);
                } else {
                    v0 = fmaxf(v0, 0.0f); v1 = fmaxf(v1, 0.0f);
                    u32 hp, lp;
                    split2(v0, v1, hp, lp);
                    *(u32*)(Ch + (size_t)m * N + n) = hp;
                    *(u32*)(Cl + (size_t)m * N + n) = lp;
                }
            }
        }
    }
}

// Fused QKV: z=0 Q (scale 1/8, split out), z=1 K (split out),
// z=2 V (smem-staged transpose -> split V^T out directly).
__global__ __launch_bounds__(256, 2)
void qkv_fused_kernel(const __nv_bfloat16* __restrict__ xh,
                      const __nv_bfloat16* __restrict__ xl,
                      const __nv_bfloat16* __restrict__ wqh, const __nv_bfloat16* __restrict__ wql,
                      const __nv_bfloat16* __restrict__ wkh, const __nv_bfloat16* __restrict__ wkl,
                      const __nv_bfloat16* __restrict__ wvh, const __nv_bfloat16* __restrict__ wvl,
                      const float* __restrict__ bq, const float* __restrict__ bk,
                      const float* __restrict__ bv,
                      __nv_bfloat16* __restrict__ qh, __nv_bfloat16* __restrict__ ql,
                      __nv_bfloat16* __restrict__ kh, __nv_bfloat16* __restrict__ kl,
                      __nv_bfloat16* __restrict__ vth, __nv_bfloat16* __restrict__ vtl)
{
    extern __shared__ char smem[];
    const u32 sb = smem_u32(smem);
    const int tid  = threadIdx.x;
    const int wid  = tid >> 5, lane = tid & 31;
    const int wm   = wid >> 2, wn = wid & 3;
    const int m0   = blockIdx.y * 128;
    const int n0   = blockIdx.x * 128;
    const int z    = blockIdx.z;
    const int lr16 = lane & 15, lc = lane >> 4;

    const __nv_bfloat16* Bh = z == 0 ? wqh : z == 1 ? wkh : wvh;
    const __nv_bfloat16* Bl = z == 0 ? wql : z == 1 ? wkl : wvl;
    const float* bias       = z == 0 ? bq  : z == 1 ? bk  : bv;

    float acc[4][4][4];
#pragma unroll
    for (int mt = 0; mt < 4; mt++)
#pragma unroll
        for (int nt = 0; nt < 4; nt++)
#pragma unroll
            for (int r = 0; r < 4; r++) acc[mt][nt][r] = 0.0f;

    tgn_mainloop(sb, xh + (size_t)m0 * DD, xl + (size_t)m0 * DD,
                 Bh + (size_t)n0 * DD, Bl + (size_t)n0 * DD,
                 DD, tid, wm, wn, lr16, lc, acc);

    const int tg = lane >> 2;
    const int tc = (lane & 3) * 2;

    if (z != 2) {
        const float scl = (z == 0) ? 0.125f : 1.0f;
        __nv_bfloat16* Ch = z == 0 ? qh : kh;
        __nv_bfloat16* Cl = z == 0 ? ql : kl;
#pragma unroll
        for (int mt = 0; mt < 4; mt++) {
#pragma unroll
            for (int half = 0; half < 2; half++) {
                const int m = m0 + wm * 64 + mt * 16 + tg + 8 * half;
#pragma unroll
                for (int nt = 0; nt < 4; nt++) {
                    const int n = n0 + wn * 32 + nt * 8 + tc;
                    float v0 = (acc[mt][nt][2 * half]     + bias[n])     * scl;
                    float v1 = (acc[mt][nt][2 * half + 1] + bias[n + 1]) * scl;
                    u32 hp, lp;
                    split2(v0, v1, hp, lp);
                    *(u32*)(Ch + (size_t)m * DD + n) = hp;
                    *(u32*)(Cl + (size_t)m * DD + n) = lp;
                }
            }
        }
    } else {
        // V: stage split-bf16 tile in smem transposed via 2 half-tiles
        // (64 cols x 128 rows each) to fit the 96KB allocation.
        // Layout per half: hi[64][132] u32-packed? Simpler: stage fp32 tile
        // in halves of 64 columns: tile[128][68] floats = 34.8KB.
        float* tile = (float*)smem;     // [128][68] fp32, one 64-col half
#pragma unroll 1
        for (int hf = 0; hf < 2; hf++) {
            __syncthreads();            // previous consumers done
            const int nc0 = hf * 64;    // local col base
#pragma unroll
            for (int mt = 0; mt < 4; mt++) {
#pragma unroll
                for (int half = 0; half < 2; half++) {
                    const int ml = wm * 64 + mt * 16 + tg + 8 * half;
#pragma unroll
                    for (int nt = 0; nt < 4; nt++) {
                        const int nl = wn * 32 + nt * 8 + tc;
                        if ((nl & 64) == (hf << 6)) {
                            const int nll = nl & 63;
                            tile[ml * 68 + nll]     = acc[mt][nt][2 * half]     + bias[n0 + nl];
                            tile[ml * 68 + nll + 1] = acc[mt][nt][2 * half + 1] + bias[n0 + nl + 1];
                        }
                    }
                }
            }
            __syncthreads();
            const int b    = m0 >> 11;
            const int tok0 = m0 & 2047;
            const int nl   = tid >> 2;           // 0..63 local col
            const int mh   = (tid & 3) * 32;     // token quarter
            const size_t orow = (size_t)(b * 512 + n0 + nc0 + nl) * LL + tok0 + mh;
#pragma unroll
            for (int it = 0; it < 4; it++) {
                u32 hp[4], lp[4];
#pragma unroll
                for (int j2 = 0; j2 < 4; j2++) {
                    float v0 = tile[(mh + 8 * it + 2 * j2)     * 68 + nl];
                    float v1 = tile[(mh + 8 * it + 2 * j2 + 1) * 68 + nl];
                    split2(v0, v1, hp[j2], lp[j2]);
                }
                *(uint4*)(vth + orow + 8 * it) = *(uint4*)hp;
                *(uint4*)(vtl + orow + 8 * it) = *(uint4*)lp;
            }
        }
    }
}

// ---------------------------------------------------------------------------
// HMMA flash attention with relative position bias (unchanged from round 9).
// ---------------------------------------------------------------------------
#define AT_STAGE 49152
#define AT_R3OFF (2 * AT_STAGE)
#define AT_RSTR  66
#define AT_SLOT  (128 * AT_RSTR)
#define AT_SMEM  (AT_R3OFF + 3 * AT_SLOT * 4)

__device__ __forceinline__ void attn_load_stage(
    u32 dstbase, int j0, int t, int tid, int b, int h,
    const __nv_bfloat16* __restrict__ kh, const __nv_bfloat16* __restrict__ kl,
    const __nv_bfloat16* __restrict__ relh, const __nv_bfloat16* __restrict__ rell,
    const __nv_bfloat16* __restrict__ vth, const __nv_bfloat16* __restrict__ vtl)
{
    const int r0 = tid >> 3, c = tid & 7;
#pragma unroll
    for (int i = 0; i < 2; i++) {
        const int r = r0 + 32 * i;
        const u32 sw = (u32)(r * 128 + 16 * (c ^ (r & 7)));
        const size_t krow = (size_t)(b * LL + j0 + r) * DD + h * DHH + 8 * c;
        const size_t frow = (size_t)(2047 - 64 * t - r) * DD + h * DHH + 8 * c;
        const size_t vrow = (size_t)((b * 8 + h) * 64 + r) * LL + j0 + 8 * c;
        cp16(dstbase +          sw, kh   + krow);
        cp16(dstbase +  8192 +  sw, kl   + krow);
        cp16(dstbase + 16384 +  sw, relh + frow);
        cp16(dstbase + 24576 +  sw, rell + frow);
        cp16(dstbase + 32768 +  sw, vth  + vrow);
        cp16(dstbase + 40960 +  sw, vtl  + vrow);
    }
}

__global__ __launch_bounds__(256, 1)
void attn_mma_kernel(const __nv_bfloat16* __restrict__ qh, const __nv_bfloat16* __restrict__ ql,
                     const __nv_bfloat16* __restrict__ kh, const __nv_bfloat16* __restrict__ kl,
                     const __nv_bfloat16* __restrict__ vth, const __nv_bfloat16* __restrict__ vtl,
                     const __nv_bfloat16* __restrict__ relh, const __nv_bfloat16* __restrict__ rell,
                     __nv_bfloat16* __restrict__ oh, __nv_bfloat16* __restrict__ ol)
{
    extern __shared__ char smem[];
    const u32 sb = smem_u32(smem);
    float* R3 = (float*)(smem + AT_R3OFF);

    const int tid = threadIdx.x, lane = tid & 31, w = tid >> 5;
    const int p   = blockIdx.x >> 4;
    const int bh  = blockIdx.x & 15;
    const int b   = bh >> 3, h = bh & 7;
    const int g   = lane >> 2, t4 = lane & 3;
    const int lr16 = lane & 15, lc = lane >> 4;

#pragma unroll 1
    for (int qq = 0; qq < 2; qq++) {
        const int q  = qq ? (15 - p) : p;
        const int i0 = q * 128;
        const int NT = 2 * q + 2;
        const int R0 = 16 * w + g, R1 = R0 + 8;
        const size_t rowg0 = (size_t)(b * LL + i0 + R0);

        u32 qfh[4][4], qfl[4][4];
        {
            const __nv_bfloat16* ph_ = qh + rowg0 * DD + h * DHH + 2 * t4;
            const __nv_bfloat16* pl_ = ql + rowg0 * DD + h * DHH + 2 * t4;
#pragma unroll
            for (int ks = 0; ks < 4; ks++) {
                qfh[ks][0] = *(const u32*)(ph_ + 16 * ks);
                qfh[ks][1] = *(const u32*)(ph_ + 16 * ks + 8 * DD);
                qfh[ks][2] = *(const u32*)(ph_ + 16 * ks + 8);
                qfh[ks][3] = *(const u32*)(ph_ + 16 * ks + 8 * DD + 8);
                qfl[ks][0] = *(const u32*)(pl_ + 16 * ks);
                qfl[ks][1] = *(const u32*)(pl_ + 16 * ks + 8 * DD);
                qfl[ks][2] = *(const u32*)(pl_ + 16 * ks + 8);
                qfl[ks][3] = *(const u32*)(pl_ + 16 * ks + 8 * DD + 8);
            }
        }

        float accO[8][4];
#pragma unroll
        for (int j = 0; j < 8; j++)
#pragma unroll
            for (int r = 0; r < 4; r++) accO[j][r] = 0.0f;
        float mrow0 = -1e30f, mrow1 = -1e30f, lrow0 = 0.0f, lrow1 = 0.0f;

        attn_load_stage(sb, i0 + 64, 0, tid, b, h, kh, kl, relh, rell, vth, vtl);
        CP_COMMIT();

#pragma unroll 1
        for (int t = 0; t < NT; t++) {
            const int j0 = i0 + 64 - 64 * t;
            if (t + 1 < NT) {
                attn_load_stage(sb + ((t + 1) & 1) * AT_STAGE, j0 - 64, t + 1,
                                tid, b, h, kh, kl, relh, rell, vth, vtl);
                CP_COMMIT();
                CP_WAIT(1);
            } else {
                CP_WAIT(0);
            }
            __syncthreads();

            const u32 st  = sb + (t & 1) * AT_STAGE;
            const u32 sKh = st, sKl = st + 8192, sFh = st + 16384,
                      sFl = st + 24576, sVh = st + 32768, sVl = st + 40960;

            // ---- R = Qs @ Fchunk^T ----
            {
                float racc[8][4];
#pragma unroll
                for (int j = 0; j < 8; j++)
#pragma unroll
                    for (int r = 0; r < 4; r++) racc[j][r] = 0.0f;
#pragma unroll
                for (int ks = 0; ks < 4; ks++) {
                    u32 fh[4][4], fl[4][4];
#pragma unroll
                    for (int ng = 0; ng < 4; ng++) {
                        const int row = 16 * ng + lr16;
                        const u32 off = (u32)(row * 128 + 16 * ((2 * ks + lc) ^ (row & 7)));
                        LDSM_X4(fh[ng], sFh + off);
                        LDSM_X4(fl[ng], sFl + off);
                    }
#pragma unroll
                    for (int ng = 0; ng < 4; ng++) {
                        MMA_BF16(racc[2*ng],   qfh[ks], fh[ng][0], fh[ng][2]);
                        MMA_BF16(racc[2*ng+1], qfh[ks], fh[ng][1], fh[ng][3]);
                    }
#pragma unroll
                    for (int ng = 0; ng < 4; ng++) {
                        MMA_BF16(racc[2*ng],   qfh[ks], fl[ng][0], fl[ng][2]);
                        MMA_BF16(racc[2*ng+1], qfh[ks], fl[ng][1], fl[ng][3]);
                    }
#pragma unroll
                    for (int ng = 0; ng < 4; ng++) {
                        MMA_BF16(racc[2*ng],   qfl[ks], fh[ng][0], fh[ng][2]);
                        MMA_BF16(racc[2*ng+1], qfl[ks], fh[ng][1], fh[ng][3]);
                    }
                }
                float* Rb = R3 + (t % 3) * AT_SLOT;
#pragma unroll
                for (int j = 0; j < 8; j++) {
                    *(float2*)&Rb[R0 * AT_RSTR + 8 * j + 2 * t4] = make_float2(racc[j][0], racc[j][1]);
                    *(float2*)&Rb[R1 * AT_RSTR + 8 * j + 2 * t4] = make_float2(racc[j][2], racc[j][3]);
                }
            }
            __syncwarp();

            // ---- S = Qs @ K^T ----
            float sacc[8][4];
#pragma unroll
            for (int j = 0; j < 8; j++)
#pragma unroll
                for (int r = 0; r < 4; r++) sacc[j][r] = 0.0f;
#pragma unroll
            for (int ks = 0; ks < 4; ks++) {
                u32 bkh_[4][4], bkl_[4][4];
#pragma unroll
                for (int ng = 0; ng < 4; ng++) {
                    const int row = 16 * ng + lr16;
                    const u32 off = (u32)(row * 128 + 16 * ((2 * ks + lc) ^ (row & 7)));
                    LDSM_X4(bkh_[ng], sKh + off);
                    LDSM_X4(bkl_[ng], sKl + off);
                }
#pragma unroll
                for (int ng = 0; ng < 4; ng++) {
                    MMA_BF16(sacc[2*ng],   qfh[ks], bkh_[ng][0], bkh_[ng][2]);
                    MMA_BF16(sacc[2*ng+1], qfh[ks], bkh_[ng][1], bkh_[ng][3]);
                }
#pragma unroll
                for (int ng = 0; ng < 4; ng++) {
                    MMA_BF16(sacc[2*ng],   qfh[ks], bkl_[ng][0], bkl_[ng][2]);
                    MMA_BF16(sacc[2*ng+1], qfh[ks], bkl_[ng][1], bkl_[ng][3]);
                }
#pragma unroll
                for (int ng = 0; ng < 4; ng++) {
                    MMA_BF16(sacc[2*ng],   qfl[ks], bkh_[ng][0], bkh_[ng][2]);
                    MMA_BF16(sacc[2*ng+1], qfl[ks], bkh_[ng][1], bkh_[ng][3]);
                }
            }

            // ---- gather skew bias + mask + online softmax ----
            float mx0 = -1e30f, mx1 = -1e30f;
#pragma unroll
            for (int j = 0; j < 8; j++) {
#pragma unroll
                for (int c2 = 0; c2 < 2; c2++) {
                    const int dj = 8 * j + 2 * t4 + c2;
                    {
                        const int e = 64 + R0 - dj;
                        const int slot = (t + 1 + (e >> 6)) % 3;
                        float sv = sacc[j][c2] + R3[slot * AT_SLOT + R0 * AT_RSTR + (e & 63)];
                        if (t < 2 && (64 * (t - 1) + R0 - dj) < 0) sv = -1e30f;
                        sacc[j][c2] = sv;
                        mx0 = fmaxf(mx0, sv);
                    }
                    {
                        const int e = 64 + R1 - dj;
                        const int slot = (t + 1 + (e >> 6)) % 3;
                        float sv = sacc[j][2 + c2] + R3[slot * AT_SLOT + R1 * AT_RSTR + (e & 63)];
                        if (t < 2 && (64 * (t - 1) + R1 - dj) < 0) sv = -1e30f;
                        sacc[j][2 + c2] = sv;
                        mx1 = fmaxf(mx1, sv);
                    }
                }
            }
            mx0 = fmaxf(mx0, __shfl_xor_sync(0xffffffffu, mx0, 1));
            mx0 = fmaxf(mx0, __shfl_xor_sync(0xffffffffu, mx0, 2));
            mx1 = fmaxf(mx1, __shfl_xor_sync(0xffffffffu, mx1, 1));
            mx1 = fmaxf(mx1, __shfl_xor_sync(0xffffffffu, mx1, 2));

            const float mn0 = fmaxf(mrow0, mx0), mn1 = fmaxf(mrow1, mx1);
            const float al0 = __expf(mrow0 - mn0), al1 = __expf(mrow1 - mn1);
            mrow0 = mn0; mrow1 = mn1;

            float rs0 = 0.0f, rs1 = 0.0f;
#pragma unroll
            for (int j = 0; j < 8; j++) {
#pragma unroll
                for (int c2 = 0; c2 < 2; c2++) {
                    float sv = sacc[j][c2];
                    float e  = __expf(sv - mn0);
                    if (sv < -1e29f) e = 0.0f;
                    rs0 += e; sacc[j][c2] = e;
                    sv = sacc[j][2 + c2];
                    e  = __expf(sv - mn1);
                    if (sv < -1e29f) e = 0.0f;
                    rs1 += e; sacc[j][2 + c2] = e;
                }
            }
            rs0 += __shfl_xor_sync(0xffffffffu, rs0, 1);
            rs0 += __shfl_xor_sync(0xffffffffu, rs0, 2);
            rs1 += __shfl_xor_sync(0xffffffffu, rs1, 1);
            rs1 += __shfl_xor_sync(0xffffffffu, rs1, 2);
            lrow0 = lrow0 * al0 + rs0;
            lrow1 = lrow1 * al1 + rs1;
#pragma unroll
            for (int j = 0; j < 8; j++) {
                accO[j][0] *= al0; accO[j][1] *= al0;
                accO[j][2] *= al1; accO[j][3] *= al1;
            }

            // ---- O += P @ V ----
#pragma unroll
            for (int ks = 0; ks < 4; ks++) {
                u32 ph_[4], pl_[4];
                split2(sacc[2*ks][0],   sacc[2*ks][1],   ph_[0], pl_[0]);
                split2(sacc[2*ks][2],   sacc[2*ks][3],   ph_[1], pl_[1]);
                split2(sacc[2*ks+1][0], sacc[2*ks+1][1], ph_[2], pl_[2]);
                split2(sacc[2*ks+1][2], sacc[2*ks+1][3], ph_[3], pl_[3]);
                u32 bvh_[4][4], bvl_[4][4];
#pragma unroll
                for (int ng = 0; ng < 4; ng++) {
                    const int row = 16 * ng + lr16;
                    const u32 off = (u32)(row * 128 + 16 * ((2 * ks + lc) ^ (row & 7)));
                    LDSM_X4(bvh_[ng], sVh + off);
                    LDSM_X4(bvl_[ng], sVl + off);
                }
#pragma unroll
                for (int ng = 0; ng < 4; ng++) {
                    MMA_BF16(accO[2*ng],   ph_, bvh_[ng][0], bvh_[ng][2]);
                    MMA_BF16(accO[2*ng+1], ph_, bvh_[ng][1], bvh_[ng][3]);
                }
#pragma unroll
                for (int ng = 0; ng < 4; ng++) {
                    MMA_BF16(accO[2*ng],   ph_, bvl_[ng][0], bvl_[ng][2]);
                    MMA_BF16(accO[2*ng+1], ph_, bvl_[ng][1], bvl_[ng][3]);
                }
#pragma unroll
                for (int ng = 0; ng < 4; ng++) {
                    MMA_BF16(accO[2*ng],   pl_, bvh_[ng][0], bvh_[ng][2]);
                    MMA_BF16(accO[2*ng+1], pl_, bvh_[ng][1], bvh_[ng][3]);
                }
            }
            __syncthreads();
        }

        const float inv0 = 1.0f / lrow0, inv1 = 1.0f / lrow1;
        __nv_bfloat16* o0h = oh + rowg0 * DD + h * DHH + 2 * t4;
        __nv_bfloat16* o0l = ol + rowg0 * DD + h * DHH + 2 * t4;
#pragma unroll
        for (int j = 0; j < 8; j++) {
            u32 hp, lp;
            split2(accO[j][0] * inv0, accO[j][1] * inv0, hp, lp);
            *(u32*)(o0h + 8 * j) = hp;
            *(u32*)(o0l + 8 * j) = lp;
            split2(accO[j][2] * inv1, accO[j][3] * inv1, hp, lp);
            *(u32*)(o0h + 8 * DD + 8 * j) = hp;
            *(u32*)(o0l + 8 * DD + 8 * j) = lp;
        }
    }
}

// ---------------------------------------------------------------------------
// Launch
// ---------------------------------------------------------------------------
extern "C" void kernel_launch(void* const* d_in, const int* in_sizes, int n_in,
                              void* d_out, int out_size)
{
    const float* x   = (const float*)d_in[0];
    // d_in[1] = mask — handled analytically
    const float* wq  = (const float*)d_in[2];
    const float* bq  = (const float*)d_in[3];
    const float* wk  = (const float*)d_in[4];
    const float* bk  = (const float*)d_in[5];
    const float* wv  = (const float*)d_in[6];
    const float* bv  = (const float*)d_in[7];
    const float* rel = (const float*)d_in[8];
    const float* w1  = (const float*)d_in[9];
    const float* b1  = (const float*)d_in[10];
    const float* w2  = (const float*)d_in[11];
    const float* b2  = (const float*)d_in[12];
    float* out = (float*)d_out;

    __nv_bfloat16 *xh, *xl, *qh, *ql, *kh, *kl, *vth, *vtl, *relh, *rell;
    __nv_bfloat16 *ah, *al, *hhp, *hlp;
    __nv_bfloat16 *wqh, *wql, *wkh, *wkl, *wvh, *wvl, *w1h, *w1l, *w2h, *w2l;
    cudaGetSymbolAddress((void**)&xh,  g_xh);   cudaGetSymbolAddress((void**)&xl,  g_xl);
    cudaGetSymbolAddress((void**)&qh,  g_qh);   cudaGetSymbolAddress((void**)&ql,  g_ql);
    cudaGetSymbolAddress((void**)&kh,  g_kh);   cudaGetSymbolAddress((void**)&kl,  g_kl);
    cudaGetSymbolAddress((void**)&vth, g_vth);  cudaGetSymbolAddress((void**)&vtl, g_vtl);
    cudaGetSymbolAddress((void**)&relh, g_relh); cudaGetSymbolAddress((void**)&rell, g_rell);
    cudaGetSymbolAddress((void**)&ah,  g_ah);   cudaGetSymbolAddress((void**)&al,  g_al);
    cudaGetSymbolAddress((void**)&hhp, g_hh);   cudaGetSymbolAddress((void**)&hlp, g_hl);
    cudaGetSymbolAddress((void**)&wqh, g_wqh);  cudaGetSymbolAddress((void**)&wql, g_wql);
    cudaGetSymbolAddress((void**)&wkh, g_wkh);  cudaGetSymbolAddress((void**)&wkl, g_wkl);
    cudaGetSymbolAddress((void**)&wvh, g_wvh);  cudaGetSymbolAddress((void**)&wvl, g_wvl);
    cudaGetSymbolAddress((void**)&w1h, g_w1h);  cudaGetSymbolAddress((void**)&w1l, g_w1l);
    cudaGetSymbolAddress((void**)&w2h, g_w2h);  cudaGetSymbolAddress((void**)&w2l, g_w2l);

    cudaFuncSetAttribute(tgemm_kernel<0>,  cudaFuncAttributeMaxDynamicSharedMemorySize, TGN_SMEM);
    cudaFuncSetAttribute(tgemm_kernel<1>,  cudaFuncAttributeMaxDynamicSharedMemorySize, TGN_SMEM);
    cudaFuncSetAttribute(qkv_fused_kernel, cudaFuncAttributeMaxDynamicSharedMemorySize, TGN_SMEM);
    cudaFuncSetAttribute(attn_mma_kernel,  cudaFuncAttributeMaxDynamicSharedMemorySize, AT_SMEM);

    // 0) Prep
    conv_xrel_kernel<<<(N4X + N4R + 255) / 256, 256>>>(
        (const float4*)x, (const float4*)rel, xh, xl, relh, rell);
    tsplit3_kernel<<<dim3(DD / 32, DD / 32, 3), 256>>>(
        wq, wk, wv, wqh, wql, wkh, wkl, wvh, wvl);
    tsplit_ffn_kernel<<<dim3(DFCN / 32, DD / 32, 2), 256>>>(
        w1, w2, w1h, w1l, w2h, w2l);

    // 1) Fused QKV (z=2 writes V^T split directly)
    qkv_fused_kernel<<<dim3(DD / 128, MM / 128, 3), 256, TGN_SMEM>>>(
        xh, xl, wqh, wql, wkh, wkl, wvh, wvl, bq, bk, bv, qh, ql, kh, kl, vth, vtl);

    // 2) HMMA flash attention with relative bias
    attn_mma_kernel<<<128, 256, AT_SMEM>>>(qh, ql, kh, kl, vth, vtl, relh, rell, ah, al);

    // 3) FFN
    tgemm_kernel<1><<<dim3(DFCN / 128, MM / 128), 256, TGN_SMEM>>>(
        ah, al, w1h, w1l, b1, nullptr, hhp, hlp, MM, DFCN, DD);
    tgemm_kernel<0><<<dim3(DD / 128, MM / 128), 256, TGN_SMEM>>>(
        hhp, hlp, w2h, w2l, b2, out, nullptr, nullptr, MM, DD, DFCN);
}

// round 12
// speedup vs baseline: 1.3672x; 1.3672x over previous
#include <cuda_runtime.h>
#include <cuda_fp16.h>
#include <cstdint>
#include <cstddef>

// ---------------------------------------------------------------------------
// Problem constants
// ---------------------------------------------------------------------------
#define BB   2
#define LL   2048
#define DD   512
#define HH   8
#define DHH  64
#define DFCN 2048
#define MM   (BB * LL)        // 4096 rows

typedef unsigned long long u64;
typedef unsigned int u32;

// ---------------------------------------------------------------------------
// Scratch (device globals: allocation-guard-safe)
// fp16 scheme: A-operands stored single-fp16; B-operands split hi/lo.
// ---------------------------------------------------------------------------
__device__ __half g_xh[MM * DD];                       // x (A op)
__device__ __half g_qh[MM * DD];                       // scaled Q (A op)
__device__ __half g_kh[MM * DD],  g_kl[MM * DD];       // K split (B op)
__device__ __half g_vth[BB*HH*DHH * LL], g_vtl[BB*HH*DHH * LL]; // V^T split
__device__ __half g_relh[LL * DD], g_rell[LL * DD];    // rel split (B op)
__device__ __half g_ah[MM * DD];                       // attn out (A op)
__device__ __half g_hh[MM * DFCN];                     // FFN hidden (A op)

// Transposed + split weights: T[n][k] = W[k][n]
__device__ __half g_wqh[DD * DD],   g_wql[DD * DD];
__device__ __half g_wkh[DD * DD],   g_wkl[DD * DD];
__device__ __half g_wvh[DD * DD],   g_wvl[DD * DD];
__device__ __half g_w1h[DFCN * DD], g_w1l[DFCN * DD];
__device__ __half g_w2h[DD * DFCN], g_w2l[DD * DFCN];

// ---------------------------------------------------------------------------
// Helpers
// ---------------------------------------------------------------------------
__device__ __forceinline__ u32 smem_u32(const void* p) {
    u32 a;
    asm("{ .reg .u64 t; cvta.to.shared.u64 t, %1; cvt.u32.u64 %0, t; }"
        : "=r"(a) : "l"(p));
    return a;
}

__device__ __forceinline__ u32 pack_h2(__half a, __half b) {
    return (u32)__half_as_ushort(a) | ((u32)__half_as_ushort(b) << 16);
}

// round pair to fp16 (A-operand path)
__device__ __forceinline__ u32 round2h(float x, float y) {
    __half2 h = __floats2half2_rn(x, y);
    return *(u32*)&h;
}

// split pair into hi/lo fp16 packs (B-operand path)
__device__ __forceinline__ void split2h(float x, float y, u32& hp, u32& lp) {
    __half hx = __float2half_rn(x), hy = __float2half_rn(y);
    hp = pack_h2(hx, hy);
    lp = pack_h2(__float2half_rn(x - __half2float(hx)),
                 __float2half_rn(y - __half2float(hy)));
}

#define LDSM_X4(r, addr) \
    asm volatile("ldmatrix.sync.aligned.m8n8.x4.shared.b16 {%0,%1,%2,%3}, [%4];" \
        : "=r"((r)[0]), "=r"((r)[1]), "=r"((r)[2]), "=r"((r)[3]) : "r"(addr))

#define MMA_F16(d, a, b0, b1) \
    asm volatile("mma.sync.aligned.m16n8k16.row.col.f32.f16.f16.f32 " \
        "{%0,%1,%2,%3}, {%4,%5,%6,%7}, {%8,%9}, {%0,%1,%2,%3};" \
        : "+f"((d)[0]), "+f"((d)[1]), "+f"((d)[2]), "+f"((d)[3]) \
        : "r"((a)[0]), "r"((a)[1]), "r"((a)[2]), "r"((a)[3]), "r"(b0), "r"(b1))

__device__ __forceinline__ void cp16(u32 dst, const void* src) {
    asm volatile("cp.async.cg.shared.global [%0], [%1], 16;"
                 :: "r"(dst), "l"(src) : "memory");
}
#define CP_COMMIT()  asm volatile("cp.async.commit_group;" ::: "memory")
#define CP_WAIT(n)   asm volatile("cp.async.wait_group %0;" :: "n"(n) : "memory")

// ---------------------------------------------------------------------------
// Prep kernels
// ---------------------------------------------------------------------------
__global__ __launch_bounds__(256)
void tsplit3_kernel(const float* __restrict__ wq, const float* __restrict__ wk,
                    const float* __restrict__ wv,
                    __half* __restrict__ qhh, __half* __restrict__ qll,
                    __half* __restrict__ khh, __half* __restrict__ kll,
                    __half* __restrict__ vhh, __half* __restrict__ vll)
{
    const float* W = blockIdx.z == 0 ? wq : blockIdx.z == 1 ? wk : wv;
    __half* Th = blockIdx.z == 0 ? qhh : blockIdx.z == 1 ? khh : vhh;
    __half* Tl = blockIdx.z == 0 ? qll : blockIdx.z == 1 ? kll : vll;

    __shared__ float t[32][33];
    const int n0 = blockIdx.x * 32, k0 = blockIdx.y * 32;
    const int tx = threadIdx.x & 31, ty = threadIdx.x >> 5;
#pragma unroll
    for (int i = 0; i < 4; i++)
        t[ty + 8 * i][tx] = W[(size_t)(k0 + ty + 8 * i) * DD + n0 + tx];
    __syncthreads();
#pragma unroll
    for (int i = 0; i < 4; i++) {
        int n = n0 + ty + 8 * i;
        float v = t[tx][ty + 8 * i];
        __half h = __float2half_rn(v);
        Th[(size_t)n * DD + k0 + tx] = h;
        Tl[(size_t)n * DD + k0 + tx] = __float2half_rn(v - __half2float(h));
    }
}

__global__ __launch_bounds__(256)
void tsplit_ffn_kernel(const float* __restrict__ w1, const float* __restrict__ w2,
                       __half* __restrict__ w1h, __half* __restrict__ w1l,
                       __half* __restrict__ w2h, __half* __restrict__ w2l)
{
    const int z = blockIdx.z;
    const float* W = z == 0 ? w1 : w2;
    __half* Th = z == 0 ? w1h : w2h;
    __half* Tl = z == 0 ? w1l : w2l;
    const int K = z == 0 ? DD : DFCN;
    const int N = z == 0 ? DFCN : DD;
    const int n0 = (z == 0 ? blockIdx.x : blockIdx.y) * 32;
    const int k0 = (z == 0 ? blockIdx.y : blockIdx.x) * 32;

    __shared__ float t[32][33];
    const int tx = threadIdx.x & 31, ty = threadIdx.x >> 5;
#pragma unroll
    for (int i = 0; i < 4; i++)
        t[ty + 8 * i][tx] = W[(size_t)(k0 + ty + 8 * i) * N + n0 + tx];
    __syncthreads();
#pragma unroll
    for (int i = 0; i < 4; i++) {
        int n = n0 + ty + 8 * i;
        float v = t[tx][ty + 8 * i];
        __half h = __float2half_rn(v);
        Th[(size_t)n * K + k0 + tx] = h;
        Tl[(size_t)n * K + k0 + tx] = __float2half_rn(v - __half2float(h));
    }
}

// x -> fp16 (A op, no split); rel -> split (B op). One launch.
#define N4X (MM * DD / 4)
#define N4R (LL * DD / 4)
__global__ __launch_bounds__(256)
void conv_xrel_kernel(const float4* __restrict__ X, const float4* __restrict__ R,
                      __half* __restrict__ XH,
                      __half* __restrict__ RH, __half* __restrict__ RL)
{
    int i = blockIdx.x * blockDim.x + threadIdx.x;
    if (i < N4X) {
        float4 v = X[i];
        uint2 hp;
        hp.x = round2h(v.x, v.y);
        hp.y = round2h(v.z, v.w);
        *(uint2*)(XH + 4 * (size_t)i) = hp;
    } else if (i < N4X + N4R) {
        int j = i - N4X;
        float4 v = R[j];
        u32 h0, l0, h1, l1;
        split2h(v.x, v.y, h0, l0);
        split2h(v.z, v.w, h1, l1);
        *(uint2*)(RH + 4 * (size_t)j) = make_uint2(h0, h1);
        *(uint2*)(RL + 4 * (size_t)j) = make_uint2(l0, l1);
    }
}

// ---------------------------------------------------------------------------
// fp16 2-pass HMMA GEMM core: C = A @ (Bh+Bl)^T + bias.
// BK=32, 3-stage cp.async ring, 128x128 CTA tile, 8 warps (2x4), 64x32 warp
// tile. Smem rows 64B, 16B-chunk swizzle c ^= (row>>1)&3. Stage = A + Bh + Bl
// = 24KB; 3 stages = 72KB -> 2 CTAs/SM.
// ---------------------------------------------------------------------------
#define TGN_TILE  8192                  // 128 x 32 x 2B
#define TGN_STAGE (3 * TGN_TILE)        // A, Bh, Bl = 24KB
#define TGN_SMEM  (3 * TGN_STAGE)       // 72KB

__device__ __forceinline__ void load_tile32(const __half* __restrict__ src,
                                            int ldk, u32 sdst, int tid)
{
#pragma unroll
    for (int i = 0; i < 2; i++) {
        int idx = tid + 256 * i;
        int r = idx >> 2, c = idx & 3;
        cp16(sdst + r * 64 + 16 * (c ^ ((r >> 1) & 3)), src + (size_t)r * ldk + 8 * c);
    }
}

__device__ __forceinline__ void tgn_stage_load(
    u32 sdst, const __half* A,
    const __half* Bh, const __half* Bl, int K, int kofs, int tid)
{
    load_tile32(A  + kofs, K, sdst,                tid);
    load_tile32(Bh + kofs, K, sdst +     TGN_TILE, tid);
    load_tile32(Bl + kofs, K, sdst + 2 * TGN_TILE, tid);
}

__device__ __forceinline__ void tgn_compute_chunk(
    u32 base, int wm, int wn, int lr16, int lc, float acc[4][4][4])
{
    const u32 sA  = base, sBh = base + TGN_TILE, sBl = base + 2 * TGN_TILE;
#pragma unroll
    for (int ks = 0; ks < 2; ks++) {
        const int ch = 2 * ks + lc;
        u32 bh[2][4], bl[2][4];
#pragma unroll
        for (int ng = 0; ng < 2; ng++) {
            int r = wn * 32 + ng * 16 + lr16;
            u32 off = r * 64 + 16 * (ch ^ ((r >> 1) & 3));
            LDSM_X4(bh[ng], sBh + off);
            LDSM_X4(bl[ng], sBl + off);
        }
#pragma unroll
        for (int mt = 0; mt < 4; mt++) {
            int r = wm * 64 + mt * 16 + lr16;
            u32 off = r * 64 + 16 * (ch ^ ((r >> 1) & 3));
            u32 ah[4];
            LDSM_X4(ah, sA + off);
#pragma unroll
            for (int nt = 0; nt < 4; nt++) {
                const int ng = nt >> 1, hi = nt & 1;
                MMA_F16(acc[mt][nt], ah, bh[ng][hi], bh[ng][2 + hi]);
            }
#pragma unroll
            for (int nt = 0; nt < 4; nt++) {
                const int ng = nt >> 1, hi = nt & 1;
                MMA_F16(acc[mt][nt], ah, bl[ng][hi], bl[ng][2 + hi]);
            }
        }
    }
}

__device__ __forceinline__ void tgn_mainloop(
    u32 sb, const __half* Abase,
    const __half* Bbase_h, const __half* Bbase_l,
    int K, int tid, int wm, int wn, int lr16, int lc, float acc[4][4][4])
{
    const int NC = K >> 5;
    tgn_stage_load(sb, Abase, Bbase_h, Bbase_l, K, 0, tid);
    CP_COMMIT();
    if (NC > 1) {
        tgn_stage_load(sb + TGN_STAGE, Abase, Bbase_h, Bbase_l, K, 32, tid);
        CP_COMMIT();
    }
    int sc = 0, sn = 2;
    for (int c = 0; c < NC; c++) {
        CP_WAIT(1);
        __syncthreads();
        if (c + 2 < NC) {
            tgn_stage_load(sb + sn * TGN_STAGE,
                           Abase, Bbase_h, Bbase_l, K, (c + 2) * 32, tid);
            CP_COMMIT();
        } else {
            CP_COMMIT();
        }
        tgn_compute_chunk(sb + sc * TGN_STAGE, wm, wn, lr16, lc, acc);
        sc = sc == 2 ? 0 : sc + 1;
        sn = sn == 2 ? 0 : sn + 1;
    }
}

// MODE 0: fp32 out. MODE 1: relu + fp16 out (A-op for next GEMM).
template <int MODE>
__global__ __launch_bounds__(256, 2)
void tgemm_kernel(const __half* __restrict__ A,
                  const __half* __restrict__ Bh,
                  const __half* __restrict__ Bl,
                  const float* __restrict__ bias,
                  float* __restrict__ Cf,
                  __half* __restrict__ Ch,
                  int M, int N, int K)
{
    extern __shared__ char smem[];
    const u32 sb = smem_u32(smem);
    const int tid  = threadIdx.x;
    const int wid  = tid >> 5, lane = tid & 31;
    const int wm   = wid >> 2, wn = wid & 3;
    const int m0   = blockIdx.y * 128;
    const int n0   = blockIdx.x * 128;
    const int lr16 = lane & 15, lc = lane >> 4;

    float acc[4][4][4];
#pragma unroll
    for (int mt = 0; mt < 4; mt++)
#pragma unroll
        for (int nt = 0; nt < 4; nt++)
#pragma unroll
            for (int r = 0; r < 4; r++) acc[mt][nt][r] = 0.0f;

    tgn_mainloop(sb, A + (size_t)m0 * K,
                 Bh + (size_t)n0 * K, Bl + (size_t)n0 * K,
                 K, tid, wm, wn, lr16, lc, acc);

    const int tg = lane >> 2;
    const int tc = (lane & 3) * 2;
#pragma unroll
    for (int mt = 0; mt < 4; mt++) {
#pragma unroll
        for (int half_ = 0; half_ < 2; half_++) {
            const int m = m0 + wm * 64 + mt * 16 + tg + 8 * half_;
#pragma unroll
            for (int nt = 0; nt < 4; nt++) {
                const int n = n0 + wn * 32 + nt * 8 + tc;
                float v0 = acc[mt][nt][2 * half_]     + bias[n];
                float v1 = acc[mt][nt][2 * half_ + 1] + bias[n + 1];
                if (MODE == 0) {
                    *(float2*)(Cf + (size_t)m * N + n) = make_float2(v0, v1);
                } else {
                    v0 = fmaxf(v0, 0.0f); v1 = fmaxf(v1, 0.0f);
                    *(u32*)(Ch + (size_t)m * N + n) = round2h(v0, v1);
                }
            }
        }
    }
}

// Fused QKV: z=0 Q (scale 1/8, fp16 out), z=1 K (split out),
// z=2 V (smem-staged transpose -> split V^T out).
__global__ __launch_bounds__(256, 2)
void qkv_fused_kernel(const __half* __restrict__ xh,
                      const __half* __restrict__ wqh, const __half* __restrict__ wql,
                      const __half* __restrict__ wkh, const __half* __restrict__ wkl,
                      const __half* __restrict__ wvh, const __half* __restrict__ wvl,
                      const float* __restrict__ bq, const float* __restrict__ bk,
                      const float* __restrict__ bv,
                      __half* __restrict__ qh,
                      __half* __restrict__ kh, __half* __restrict__ kl,
                      __half* __restrict__ vth, __half* __restrict__ vtl)
{
    extern __shared__ char smem[];
    const u32 sb = smem_u32(smem);
    const int tid  = threadIdx.x;
    const int wid  = tid >> 5, lane = tid & 31;
    const int wm   = wid >> 2, wn = wid & 3;
    const int m0   = blockIdx.y * 128;
    const int n0   = blockIdx.x * 128;
    const int z    = blockIdx.z;
    const int lr16 = lane & 15, lc = lane >> 4;

    const __half* Bh = z == 0 ? wqh : z == 1 ? wkh : wvh;
    const __half* Bl = z == 0 ? wql : z == 1 ? wkl : wvl;
    const float* bias = z == 0 ? bq : z == 1 ? bk : bv;

    float acc[4][4][4];
#pragma unroll
    for (int mt = 0; mt < 4; mt++)
#pragma unroll
        for (int nt = 0; nt < 4; nt++)
#pragma unroll
            for (int r = 0; r < 4; r++) acc[mt][nt][r] = 0.0f;

    tgn_mainloop(sb, xh + (size_t)m0 * DD,
                 Bh + (size_t)n0 * DD, Bl + (size_t)n0 * DD,
                 DD, tid, wm, wn, lr16, lc, acc);

    const int tg = lane >> 2;
    const int tc = (lane & 3) * 2;

    if (z == 0) {
        // Q: scale by 1/8, fp16 out (A-op of attention)
#pragma unroll
        for (int mt = 0; mt < 4; mt++)
#pragma unroll
            for (int half_ = 0; half_ < 2; half_++) {
                const int m = m0 + wm * 64 + mt * 16 + tg + 8 * half_;
#pragma unroll
                for (int nt = 0; nt < 4; nt++) {
                    const int n = n0 + wn * 32 + nt * 8 + tc;
                    float v0 = (acc[mt][nt][2 * half_]     + bias[n])     * 0.125f;
                    float v1 = (acc[mt][nt][2 * half_ + 1] + bias[n + 1]) * 0.125f;
                    *(u32*)(qh + (size_t)m * DD + n) = round2h(v0, v1);
                }
            }
    } else if (z == 1) {
        // K: split out (B-op of attention)
#pragma unroll
        for (int mt = 0; mt < 4; mt++)
#pragma unroll
            for (int half_ = 0; half_ < 2; half_++) {
                const int m = m0 + wm * 64 + mt * 16 + tg + 8 * half_;
#pragma unroll
                for (int nt = 0; nt < 4; nt++) {
                    const int n = n0 + wn * 32 + nt * 8 + tc;
                    float v0 = acc[mt][nt][2 * half_]     + bias[n];
                    float v1 = acc[mt][nt][2 * half_ + 1] + bias[n + 1];
                    u32 hp, lp;
                    split2h(v0, v1, hp, lp);
                    *(u32*)(kh + (size_t)m * DD + n) = hp;
                    *(u32*)(kl + (size_t)m * DD + n) = lp;
                }
            }
    } else {
        // V: stage fp32 tile (64-col halves), write transposed split fp16 V^T.
        float* tile = (float*)smem;     // [128][68] fp32
#pragma unroll 1
        for (int hf = 0; hf < 2; hf++) {
            __syncthreads();
#pragma unroll
            for (int mt = 0; mt < 4; mt++) {
#pragma unroll
                for (int half_ = 0; half_ < 2; half_++) {
                    const int ml = wm * 64 + mt * 16 + tg + 8 * half_;
#pragma unroll
                    for (int nt = 0; nt < 4; nt++) {
                        const int nl = wn * 32 + nt * 8 + tc;
                        if ((nl & 64) == (hf << 6)) {
                            const int nll = nl & 63;
                            tile[ml * 68 + nll]     = acc[mt][nt][2 * half_]     + bias[n0 + nl];
                            tile[ml * 68 + nll + 1] = acc[mt][nt][2 * half_ + 1] + bias[n0 + nl + 1];
                        }
                    }
                }
            }
            __syncthreads();
            const int b    = m0 >> 11;
            const int tok0 = m0 & 2047;
            const int nl   = tid >> 2;
            const int mh   = (tid & 3) * 32;
            const size_t orow = (size_t)(b * 512 + n0 + hf * 64 + nl) * LL + tok0 + mh;
#pragma unroll
            for (int it = 0; it < 4; it++) {
                u32 hp[4], lp[4];
#pragma unroll
                for (int j2 = 0; j2 < 4; j2++) {
                    float v0 = tile[(mh + 8 * it + 2 * j2)     * 68 + nl];
                    float v1 = tile[(mh + 8 * it + 2 * j2 + 1) * 68 + nl];
                    split2h(v0, v1, hp[j2], lp[j2]);
                }
                *(uint4*)(vth + orow + 8 * it) = *(uint4*)hp;
                *(uint4*)(vtl + orow + 8 * it) = *(uint4*)lp;
            }
        }
    }
}

// ---------------------------------------------------------------------------
// HMMA flash attention, fp16 2-pass.
//   logits[i,j] = Qs_i.K_j + Qs_i.rel[2047-(i-j)]  (Qs pre-scaled 1/8)
// ---------------------------------------------------------------------------
#define AT_STAGE 49152                 // 6 tiles x 8KB (kh,kl,fh,fl,vh,vl)
#define AT_R3OFF (2 * AT_STAGE)
#define AT_RSTR  66
#define AT_SLOT  (128 * AT_RSTR)
#define AT_SMEM  (AT_R3OFF + 3 * AT_SLOT * 4)

__device__ __forceinline__ void attn_load_stage(
    u32 dstbase, int j0, int t, int tid, int b, int h,
    const __half* __restrict__ kh, const __half* __restrict__ kl,
    const __half* __restrict__ relh, const __half* __restrict__ rell,
    const __half* __restrict__ vth, const __half* __restrict__ vtl)
{
    const int r0 = tid >> 3, c = tid & 7;
#pragma unroll
    for (int i = 0; i < 2; i++) {
        const int r = r0 + 32 * i;
        const u32 sw = (u32)(r * 128 + 16 * (c ^ (r & 7)));
        const size_t krow = (size_t)(b * LL + j0 + r) * DD + h * DHH + 8 * c;
        const size_t frow = (size_t)(2047 - 64 * t - r) * DD + h * DHH + 8 * c;
        const size_t vrow = (size_t)((b * 8 + h) * 64 + r) * LL + j0 + 8 * c;
        cp16(dstbase +          sw, kh   + krow);
        cp16(dstbase +  8192 +  sw, kl   + krow);
        cp16(dstbase + 16384 +  sw, relh + frow);
        cp16(dstbase + 24576 +  sw, rell + frow);
        cp16(dstbase + 32768 +  sw, vth  + vrow);
        cp16(dstbase + 40960 +  sw, vtl  + vrow);
    }
}

__global__ __launch_bounds__(256, 1)
void attn_mma_kernel(const __half* __restrict__ qh,
                     const __half* __restrict__ kh, const __half* __restrict__ kl,
                     const __half* __restrict__ vth, const __half* __restrict__ vtl,
                     const __half* __restrict__ relh, const __half* __restrict__ rell,
                     __half* __restrict__ oh)
{
    extern __shared__ char smem[];
    const u32 sb = smem_u32(smem);
    float* R3 = (float*)(smem + AT_R3OFF);

    const int tid = threadIdx.x, lane = tid & 31, w = tid >> 5;
    const int p   = blockIdx.x >> 4;
    const int bh  = blockIdx.x & 15;
    const int b   = bh >> 3, h = bh & 7;
    const int g   = lane >> 2, t4 = lane & 3;
    const int lr16 = lane & 15, lc = lane >> 4;

#pragma unroll 1
    for (int qq = 0; qq < 2; qq++) {
        const int q  = qq ? (15 - p) : p;
        const int i0 = q * 128;
        const int NT = 2 * q + 2;
        const int R0 = 16 * w + g, R1 = R0 + 8;
        const size_t rowg0 = (size_t)(b * LL + i0 + R0);

        u32 qfh[4][4];
        {
            const __half* ph_ = qh + rowg0 * DD + h * DHH + 2 * t4;
#pragma unroll
            for (int ks = 0; ks < 4; ks++) {
                qfh[ks][0] = *(const u32*)(ph_ + 16 * ks);
                qfh[ks][1] = *(const u32*)(ph_ + 16 * ks + 8 * DD);
                qfh[ks][2] = *(const u32*)(ph_ + 16 * ks + 8);
                qfh[ks][3] = *(const u32*)(ph_ + 16 * ks + 8 * DD + 8);
            }
        }

        float accO[8][4];
#pragma unroll
        for (int j = 0; j < 8; j++)
#pragma unroll
            for (int r = 0; r < 4; r++) accO[j][r] = 0.0f;
        float mrow0 = -1e30f, mrow1 = -1e30f, lrow0 = 0.0f, lrow1 = 0.0f;

        attn_load_stage(sb, i0 + 64, 0, tid, b, h, kh, kl, relh, rell, vth, vtl);
        CP_COMMIT();

#pragma unroll 1
        for (int t = 0; t < NT; t++) {
            const int j0 = i0 + 64 - 64 * t;
            if (t + 1 < NT) {
                attn_load_stage(sb + ((t + 1) & 1) * AT_STAGE, j0 - 64, t + 1,
                                tid, b, h, kh, kl, relh, rell, vth, vtl);
                CP_COMMIT();
                CP_WAIT(1);
            } else {
                CP_WAIT(0);
            }
            __syncthreads();

            const u32 st  = sb + (t & 1) * AT_STAGE;
            const u32 sKh = st, sKl = st + 8192, sFh = st + 16384,
                      sFl = st + 24576, sVh = st + 32768, sVl = st + 40960;

            // ---- R = Qs @ Fchunk^T (2 passes) ----
            {
                float racc[8][4];
#pragma unroll
                for (int j = 0; j < 8; j++)
#pragma unroll
                    for (int r = 0; r < 4; r++) racc[j][r] = 0.0f;
#pragma unroll
                for (int ks = 0; ks < 4; ks++) {
                    u32 fh[4][4], fl[4][4];
#pragma unroll
                    for (int ng = 0; ng < 4; ng++) {
                        const int row = 16 * ng + lr16;
                        const u32 off = (u32)(row * 128 + 16 * ((2 * ks + lc) ^ (row & 7)));
                        LDSM_X4(fh[ng], sFh + off);
                        LDSM_X4(fl[ng], sFl + off);
                    }
#pragma unroll
                    for (int ng = 0; ng < 4; ng++) {
                        MMA_F16(racc[2*ng],   qfh[ks], fh[ng][0], fh[ng][2]);
                        MMA_F16(racc[2*ng+1], qfh[ks], fh[ng][1], fh[ng][3]);
                    }
#pragma unroll
                    for (int ng = 0; ng < 4; ng++) {
                        MMA_F16(racc[2*ng],   qfh[ks], fl[ng][0], fl[ng][2]);
                        MMA_F16(racc[2*ng+1], qfh[ks], fl[ng][1], fl[ng][3]);
                    }
                }
                float* Rb = R3 + (t % 3) * AT_SLOT;
#pragma unroll
                for (int j = 0; j < 8; j++) {
                    *(float2*)&Rb[R0 * AT_RSTR + 8 * j + 2 * t4] = make_float2(racc[j][0], racc[j][1]);
                    *(float2*)&Rb[R1 * AT_RSTR + 8 * j + 2 * t4] = make_float2(racc[j][2], racc[j][3]);
                }
            }
            __syncwarp();

            // ---- S = Qs @ K^T (2 passes) ----
            float sacc[8][4];
#pragma unroll
            for (int j = 0; j < 8; j++)
#pragma unroll
                for (int r = 0; r < 4; r++) sacc[j][r] = 0.0f;
#pragma unroll
            for (int ks = 0; ks < 4; ks++) {
                u32 bkh_[4][4], bkl_[4][4];
#pragma unroll
                for (int ng = 0; ng < 4; ng++) {
                    const int row = 16 * ng + lr16;
                    const u32 off = (u32)(row * 128 + 16 * ((2 * ks + lc) ^ (row & 7)));
                    LDSM_X4(bkh_[ng], sKh + off);
                    LDSM_X4(bkl_[ng], sKl + off);
                }
#pragma unroll
                for (int ng = 0; ng < 4; ng++) {
                    MMA_F16(sacc[2*ng],   qfh[ks], bkh_[ng][0], bkh_[ng][2]);
                    MMA_F16(sacc[2*ng+1], qfh[ks], bkh_[ng][1], bkh_[ng][3]);
                }
#pragma unroll
                for (int ng = 0; ng < 4; ng++) {
                    MMA_F16(sacc[2*ng],   qfh[ks], bkl_[ng][0], bkl_[ng][2]);
                    MMA_F16(sacc[2*ng+1], qfh[ks], bkl_[ng][1], bkl_[ng][3]);
                }
            }

            // ---- gather skew bias + mask + online softmax ----
            float mx0 = -1e30f, mx1 = -1e30f;
#pragma unroll
            for (int j = 0; j < 8; j++) {
#pragma unroll
                for (int c2 = 0; c2 < 2; c2++) {
                    const int dj = 8 * j + 2 * t4 + c2;
                    {
                        const int e = 64 + R0 - dj;
                        const int slot = (t + 1 + (e >> 6)) % 3;
                        float sv = sacc[j][c2] + R3[slot * AT_SLOT + R0 * AT_RSTR + (e & 63)];
                        if (t < 2 && (64 * (t - 1) + R0 - dj) < 0) sv = -1e30f;
                        sacc[j][c2] = sv;
                        mx0 = fmaxf(mx0, sv);
                    }
                    {
                        const int e = 64 + R1 - dj;
                        const int slot = (t + 1 + (e >> 6)) % 3;
                        float sv = sacc[j][2 + c2] + R3[slot * AT_SLOT + R1 * AT_RSTR + (e & 63)];
                        if (t < 2 && (64 * (t - 1) + R1 - dj) < 0) sv = -1e30f;
                        sacc[j][2 + c2] = sv;
                        mx1 = fmaxf(mx1, sv);
                    }
                }
            }
            mx0 = fmaxf(mx0, __shfl_xor_sync(0xffffffffu, mx0, 1));
            mx0 = fmaxf(mx0, __shfl_xor_sync(0xffffffffu, mx0, 2));
            mx1 = fmaxf(mx1, __shfl_xor_sync(0xffffffffu, mx1, 1));
            mx1 = fmaxf(mx1, __shfl_xor_sync(0xffffffffu, mx1, 2));

            const float mn0 = fmaxf(mrow0, mx0), mn1 = fmaxf(mrow1, mx1);
            const float al0 = __expf(mrow0 - mn0), al1 = __expf(mrow1 - mn1);
            mrow0 = mn0; mrow1 = mn1;

            float rs0 = 0.0f, rs1 = 0.0f;
#pragma unroll
            for (int j = 0; j < 8; j++) {
#pragma unroll
                for (int c2 = 0; c2 < 2; c2++) {
                    float sv = sacc[j][c2];
                    float e  = __expf(sv - mn0);
                    if (sv < -1e29f) e = 0.0f;
                    rs0 += e; sacc[j][c2] = e;
                    sv = sacc[j][2 + c2];
                    e  = __expf(sv - mn1);
                    if (sv < -1e29f) e = 0.0f;
                    rs1 += e; sacc[j][2 + c2] = e;
                }
            }
            rs0 += __shfl_xor_sync(0xffffffffu, rs0, 1);
            rs0 += __shfl_xor_sync(0xffffffffu, rs0, 2);
            rs1 += __shfl_xor_sync(0xffffffffu, rs1, 1);
            rs1 += __shfl_xor_sync(0xffffffffu, rs1, 2);
            lrow0 = lrow0 * al0 + rs0;
            lrow1 = lrow1 * al1 + rs1;
#pragma unroll
            for (int j = 0; j < 8; j++) {
                accO[j][0] *= al0; accO[j][1] *= al0;
                accO[j][2] *= al1; accO[j][3] *= al1;
            }

            // ---- O += P @ V (P -> fp16, 2 passes over V split) ----
#pragma unroll
            for (int ks = 0; ks < 4; ks++) {
                u32 ph_[4];
                ph_[0] = round2h(sacc[2*ks][0],   sacc[2*ks][1]);
                ph_[1] = round2h(sacc[2*ks][2],   sacc[2*ks][3]);
                ph_[2] = round2h(sacc[2*ks+1][0], sacc[2*ks+1][1]);
                ph_[3] = round2h(sacc[2*ks+1][2], sacc[2*ks+1][3]);
                u32 bvh_[4][4], bvl_[4][4];
#pragma unroll
                for (int ng = 0; ng < 4; ng++) {
                    const int row = 16 * ng + lr16;
                    const u32 off = (u32)(row * 128 + 16 * ((2 * ks + lc) ^ (row & 7)));
                    LDSM_X4(bvh_[ng], sVh + off);
                    LDSM_X4(bvl_[ng], sVl + off);
                }
#pragma unroll
                for (int ng = 0; ng < 4; ng++) {
                    MMA_F16(accO[2*ng],   ph_, bvh_[ng][0], bvh_[ng][2]);
                    MMA_F16(accO[2*ng+1], ph_, bvh_[ng][1], bvh_[ng][3]);
                }
#pragma unroll
                for (int ng = 0; ng < 4; ng++) {
                    MMA_F16(accO[2*ng],   ph_, bvl_[ng][0], bvl_[ng][2]);
                    MMA_F16(accO[2*ng+1], ph_, bvl_[ng][1], bvl_[ng][3]);
                }
            }
            __syncthreads();
        }

        // ---- epilogue: normalize, fp16 out (A-op of FFN1) ----
        const float inv0 = 1.0f / lrow0, inv1 = 1.0f / lrow1;
        __half* o0h = oh + rowg0 * DD + h * DHH + 2 * t4;
#pragma unroll
        for (int j = 0; j < 8; j++) {
            *(u32*)(o0h + 8 * j)          = round2h(accO[j][0] * inv0, accO[j][1] * inv0);
            *(u32*)(o0h + 8 * DD + 8 * j) = round2h(accO[j][2] * inv1, accO[j][3] * inv1);
        }
    }
}

// ---------------------------------------------------------------------------
// Launch
// ---------------------------------------------------------------------------
extern "C" void kernel_launch(void* const* d_in, const int* in_sizes, int n_in,
                              void* d_out, int out_size)
{
    const float* x   = (const float*)d_in[0];
    // d_in[1] = mask — handled analytically
    const float* wq  = (const float*)d_in[2];
    const float* bq  = (const float*)d_in[3];
    const float* wk  = (const float*)d_in[4];
    const float* bk  = (const float*)d_in[5];
    const float* wv  = (const float*)d_in[6];
    const float* bv  = (const float*)d_in[7];
    const float* rel = (const float*)d_in[8];
    const float* w1  = (const float*)d_in[9];
    const float* b1  = (const float*)d_in[10];
    const float* w2  = (const float*)d_in[11];
    const float* b2  = (const float*)d_in[12];
    float* out = (float*)d_out;

    __half *xh, *qh, *kh, *kl, *vth, *vtl, *relh, *rell, *ah, *hhp;
    __half *wqh, *wql, *wkh, *wkl, *wvh, *wvl, *w1h, *w1l, *w2h, *w2l;
    cudaGetSymbolAddress((void**)&xh,  g_xh);
    cudaGetSymbolAddress((void**)&qh,  g_qh);
    cudaGetSymbolAddress((void**)&kh,  g_kh);   cudaGetSymbolAddress((void**)&kl,  g_kl);
    cudaGetSymbolAddress((void**)&vth, g_vth);  cudaGetSymbolAddress((void**)&vtl, g_vtl);
    cudaGetSymbolAddress((void**)&relh, g_relh); cudaGetSymbolAddress((void**)&rell, g_rell);
    cudaGetSymbolAddress((void**)&ah,  g_ah);
    cudaGetSymbolAddress((void**)&hhp, g_hh);
    cudaGetSymbolAddress((void**)&wqh, g_wqh);  cudaGetSymbolAddress((void**)&wql, g_wql);
    cudaGetSymbolAddress((void**)&wkh, g_wkh);  cudaGetSymbolAddress((void**)&wkl, g_wkl);
    cudaGetSymbolAddress((void**)&wvh, g_wvh);  cudaGetSymbolAddress((void**)&wvl, g_wvl);
    cudaGetSymbolAddress((void**)&w1h, g_w1h);  cudaGetSymbolAddress((void**)&w1l, g_w1l);
    cudaGetSymbolAddress((void**)&w2h, g_w2h);  cudaGetSymbolAddress((void**)&w2l, g_w2l);

    cudaFuncSetAttribute(tgemm_kernel<0>,  cudaFuncAttributeMaxDynamicSharedMemorySize, TGN_SMEM);
    cudaFuncSetAttribute(tgemm_kernel<1>,  cudaFuncAttributeMaxDynamicSharedMemorySize, TGN_SMEM);
    cudaFuncSetAttribute(qkv_fused_kernel, cudaFuncAttributeMaxDynamicSharedMemorySize, TGN_SMEM);
    cudaFuncSetAttribute(attn_mma_kernel,  cudaFuncAttributeMaxDynamicSharedMemorySize, AT_SMEM);

    // 0) Prep
    conv_xrel_kernel<<<(N4X + N4R + 255) / 256, 256>>>(
        (const float4*)x, (const float4*)rel, xh, relh, rell);
    tsplit3_kernel<<<dim3(DD / 32, DD / 32, 3), 256>>>(
        wq, wk, wv, wqh, wql, wkh, wkl, wvh, wvl);
    tsplit_ffn_kernel<<<dim3(DFCN / 32, DD / 32, 2), 256>>>(
        w1, w2, w1h, w1l, w2h, w2l);

    // 1) Fused QKV
    qkv_fused_kernel<<<dim3(DD / 128, MM / 128, 3), 256, TGN_SMEM>>>(
        xh, wqh, wql, wkh, wkl, wvh, wvl, bq, bk, bv, qh, kh, kl, vth, vtl);

    // 2) HMMA flash attention with relative bias
    attn_mma_kernel<<<128, 256, AT_SMEM>>>(qh, kh, kl, vth, vtl, relh, rell, ah);

    // 3) FFN
    tgemm_kernel<1><<<dim3(DFCN / 128, MM / 128), 256, TGN_SMEM>>>(
        ah, w1h, w1l, b1, nullptr, hhp, MM, DFCN, DD);
    tgemm_kernel<0><<<dim3(DD / 128, MM / 128), 256, TGN_SMEM>>>(
        hhp, w2h, w2l, b2, out, nullptr, MM, DD, DFCN);
}

// round 13
// speedup vs baseline: 1.5226x; 1.1136x over previous
#include <cuda_runtime.h>
#include <cuda_fp16.h>
#include <cstdint>
#include <cstddef>

// ---------------------------------------------------------------------------
// Problem constants
// ---------------------------------------------------------------------------
#define BB   2
#define LL   2048
#define DD   512
#define HH   8
#define DHH  64
#define DFCN 2048
#define MM   (BB * LL)        // 4096 rows

typedef unsigned long long u64;
typedef unsigned int u32;

// ---------------------------------------------------------------------------
// Scratch (device globals)
// fp16 scheme: A-ops single fp16. Logit-side B-ops (K, rel) single fp16
// (error analysis: ~5e-5 logit perturbation). Value-side B-ops (V, w1, w2)
// split hi/lo 2-pass.
// ---------------------------------------------------------------------------
__device__ __half g_xh[MM * DD];                       // x (A op)
__device__ __half g_qh[MM * DD];                       // scaled Q (A op)
__device__ __half g_kh[MM * DD];                       // K (B op, single)
__device__ __half g_vth[BB*HH*DHH * LL], g_vtl[BB*HH*DHH * LL]; // V^T split
__device__ __half g_relh[LL * DD];                     // rel (B op, single)
__device__ __half g_ah[MM * DD];                       // attn out (A op)
__device__ __half g_hh[MM * DFCN];                     // FFN hidden (A op)

// Transposed weights: T[n][k] = W[k][n]
__device__ __half g_wqh[DD * DD];                      // single
__device__ __half g_wkh[DD * DD];                      // single
__device__ __half g_wvh[DD * DD],   g_wvl[DD * DD];    // split
__device__ __half g_w1h[DFCN * DD], g_w1l[DFCN * DD];  // split
__device__ __half g_w2h[DD * DFCN], g_w2l[DD * DFCN];  // split

// ---------------------------------------------------------------------------
// Helpers
// ---------------------------------------------------------------------------
__device__ __forceinline__ u32 smem_u32(const void* p) {
    u32 a;
    asm("{ .reg .u64 t; cvta.to.shared.u64 t, %1; cvt.u32.u64 %0, t; }"
        : "=r"(a) : "l"(p));
    return a;
}

__device__ __forceinline__ u32 pack_h2(__half a, __half b) {
    return (u32)__half_as_ushort(a) | ((u32)__half_as_ushort(b) << 16);
}

__device__ __forceinline__ u32 round2h(float x, float y) {
    __half2 h = __floats2half2_rn(x, y);
    return *(u32*)&h;
}

__device__ __forceinline__ void split2h(float x, float y, u32& hp, u32& lp) {
    __half hx = __float2half_rn(x), hy = __float2half_rn(y);
    hp = pack_h2(hx, hy);
    lp = pack_h2(__float2half_rn(x - __half2float(hx)),
                 __float2half_rn(y - __half2float(hy)));
}

#define LDSM_X4(r, addr) \
    asm volatile("ldmatrix.sync.aligned.m8n8.x4.shared.b16 {%0,%1,%2,%3}, [%4];" \
        : "=r"((r)[0]), "=r"((r)[1]), "=r"((r)[2]), "=r"((r)[3]) : "r"(addr))

#define MMA_F16(d, a, b0, b1) \
    asm volatile("mma.sync.aligned.m16n8k16.row.col.f32.f16.f16.f32 " \
        "{%0,%1,%2,%3}, {%4,%5,%6,%7}, {%8,%9}, {%0,%1,%2,%3};" \
        : "+f"((d)[0]), "+f"((d)[1]), "+f"((d)[2]), "+f"((d)[3]) \
        : "r"((a)[0]), "r"((a)[1]), "r"((a)[2]), "r"((a)[3]), "r"(b0), "r"(b1))

__device__ __forceinline__ void cp16(u32 dst, const void* src) {
    asm volatile("cp.async.cg.shared.global [%0], [%1], 16;"
                 :: "r"(dst), "l"(src) : "memory");
}
#define CP_COMMIT()  asm volatile("cp.async.commit_group;" ::: "memory")
#define CP_WAIT(n)   asm volatile("cp.async.wait_group %0;" :: "n"(n) : "memory")

// ---------------------------------------------------------------------------
// Prep kernels
// ---------------------------------------------------------------------------
// wq, wk -> single fp16 transpose; wv -> split transpose. One launch (z).
__global__ __launch_bounds__(256)
void tsplit3_kernel(const float* __restrict__ wq, const float* __restrict__ wk,
                    const float* __restrict__ wv,
                    __half* __restrict__ qhh, __half* __restrict__ khh,
                    __half* __restrict__ vhh, __half* __restrict__ vll)
{
    const int z = blockIdx.z;
    const float* W = z == 0 ? wq : z == 1 ? wk : wv;
    __half* Th = z == 0 ? qhh : z == 1 ? khh : vhh;

    __shared__ float t[32][33];
    const int n0 = blockIdx.x * 32, k0 = blockIdx.y * 32;
    const int tx = threadIdx.x & 31, ty = threadIdx.x >> 5;
#pragma unroll
    for (int i = 0; i < 4; i++)
        t[ty + 8 * i][tx] = W[(size_t)(k0 + ty + 8 * i) * DD + n0 + tx];
    __syncthreads();
#pragma unroll
    for (int i = 0; i < 4; i++) {
        int n = n0 + ty + 8 * i;
        float v = t[tx][ty + 8 * i];
        __half h = __float2half_rn(v);
        Th[(size_t)n * DD + k0 + tx] = h;
        if (z == 2)
            vll[(size_t)n * DD + k0 + tx] = __float2half_rn(v - __half2float(h));
    }
}

__global__ __launch_bounds__(256)
void tsplit_ffn_kernel(const float* __restrict__ w1, const float* __restrict__ w2,
                       __half* __restrict__ w1h, __half* __restrict__ w1l,
                       __half* __restrict__ w2h, __half* __restrict__ w2l)
{
    const int z = blockIdx.z;
    const float* W = z == 0 ? w1 : w2;
    __half* Th = z == 0 ? w1h : w2h;
    __half* Tl = z == 0 ? w1l : w2l;
    const int K = z == 0 ? DD : DFCN;
    const int N = z == 0 ? DFCN : DD;
    const int n0 = (z == 0 ? blockIdx.x : blockIdx.y) * 32;
    const int k0 = (z == 0 ? blockIdx.y : blockIdx.x) * 32;

    __shared__ float t[32][33];
    const int tx = threadIdx.x & 31, ty = threadIdx.x >> 5;
#pragma unroll
    for (int i = 0; i < 4; i++)
        t[ty + 8 * i][tx] = W[(size_t)(k0 + ty + 8 * i) * N + n0 + tx];
    __syncthreads();
#pragma unroll
    for (int i = 0; i < 4; i++) {
        int n = n0 + ty + 8 * i;
        float v = t[tx][ty + 8 * i];
        __half h = __float2half_rn(v);
        Th[(size_t)n * K + k0 + tx] = h;
        Tl[(size_t)n * K + k0 + tx] = __float2half_rn(v - __half2float(h));
    }
}

// x -> fp16; rel -> fp16 (both single). One launch.
#define N4X (MM * DD / 4)
#define N4R (LL * DD / 4)
__global__ __launch_bounds__(256)
void conv_xrel_kernel(const float4* __restrict__ X, const float4* __restrict__ R,
                      __half* __restrict__ XH, __half* __restrict__ RH)
{
    int i = blockIdx.x * blockDim.x + threadIdx.x;
    const float4* src; __half* H; int j;
    if (i < N4X) { src = X; H = XH; j = i; }
    else if (i < N4X + N4R) { src = R; H = RH; j = i - N4X; }
    else return;
    float4 v = src[j];
    uint2 hp;
    hp.x = round2h(v.x, v.y);
    hp.y = round2h(v.z, v.w);
    *(uint2*)(H + 4 * (size_t)j) = hp;
}

// ---------------------------------------------------------------------------
// fp16 HMMA GEMM core, templated pass count P (1 or 2):
//   C = A @ Bh^T (+ A @ Bl^T if P==2) + bias.
// BK=32, 3-stage cp.async ring, 128x128 CTA tile, 8 warps (2x4), 64x32 warp
// tile. Smem rows 64B, 16B-chunk swizzle c ^= (row>>1)&3.
// ---------------------------------------------------------------------------
#define TGN_TILE  8192                  // 128 x 32 x 2B

__device__ __forceinline__ void load_tile32(const __half* __restrict__ src,
                                            int ldk, u32 sdst, int tid)
{
#pragma unroll
    for (int i = 0; i < 2; i++) {
        int idx = tid + 256 * i;
        int r = idx >> 2, c = idx & 3;
        cp16(sdst + r * 64 + 16 * (c ^ ((r >> 1) & 3)), src + (size_t)r * ldk + 8 * c);
    }
}

template <int P>
__device__ __forceinline__ void tgn_stage_load(
    u32 sdst, const __half* A,
    const __half* Bh, const __half* Bl, int K, int kofs, int tid)
{
    load_tile32(A  + kofs, K, sdst,            tid);
    load_tile32(Bh + kofs, K, sdst + TGN_TILE, tid);
    if (P == 2)
        load_tile32(Bl + kofs, K, sdst + 2 * TGN_TILE, tid);
}

template <int P>
__device__ __forceinline__ void tgn_compute_chunk(
    u32 base, int wm, int wn, int lr16, int lc, float acc[4][4][4])
{
    const u32 sA = base, sBh = base + TGN_TILE, sBl = base + 2 * TGN_TILE;
#pragma unroll
    for (int ks = 0; ks < 2; ks++) {
        const int ch = 2 * ks + lc;
        u32 bh[2][4], bl[2][4];
#pragma unroll
        for (int ng = 0; ng < 2; ng++) {
            int r = wn * 32 + ng * 16 + lr16;
            u32 off = r * 64 + 16 * (ch ^ ((r >> 1) & 3));
            LDSM_X4(bh[ng], sBh + off);
            if (P == 2) LDSM_X4(bl[ng], sBl + off);
        }
#pragma unroll
        for (int mt = 0; mt < 4; mt++) {
            int r = wm * 64 + mt * 16 + lr16;
            u32 off = r * 64 + 16 * (ch ^ ((r >> 1) & 3));
            u32 ah[4];
            LDSM_X4(ah, sA + off);
#pragma unroll
            for (int nt = 0; nt < 4; nt++) {
                const int ng = nt >> 1, hi = nt & 1;
                MMA_F16(acc[mt][nt], ah, bh[ng][hi], bh[ng][2 + hi]);
            }
            if (P == 2) {
#pragma unroll
                for (int nt = 0; nt < 4; nt++) {
                    const int ng = nt >> 1, hi = nt & 1;
                    MMA_F16(acc[mt][nt], ah, bl[ng][hi], bl[ng][2 + hi]);
                }
            }
        }
    }
}

template <int P>
__device__ __forceinline__ void tgn_mainloop(
    u32 sb, const __half* Abase,
    const __half* Bbase_h, const __half* Bbase_l,
    int K, int tid, int wm, int wn, int lr16, int lc, float acc[4][4][4])
{
    const int STG = (1 + P) * TGN_TILE;
    const int NC = K >> 5;
    tgn_stage_load<P>(sb, Abase, Bbase_h, Bbase_l, K, 0, tid);
    CP_COMMIT();
    if (NC > 1) {
        tgn_stage_load<P>(sb + STG, Abase, Bbase_h, Bbase_l, K, 32, tid);
        CP_COMMIT();
    }
    int sc = 0, sn = 2;
    for (int c = 0; c < NC; c++) {
        CP_WAIT(1);
        __syncthreads();
        if (c + 2 < NC) {
            tgn_stage_load<P>(sb + sn * STG,
                              Abase, Bbase_h, Bbase_l, K, (c + 2) * 32, tid);
            CP_COMMIT();
        } else {
            CP_COMMIT();
        }
        tgn_compute_chunk<P>(sb + sc * STG, wm, wn, lr16, lc, acc);
        sc = sc == 2 ? 0 : sc + 1;
        sn = sn == 2 ? 0 : sn + 1;
    }
}

#define TGN_SMEM (3 * 3 * TGN_TILE)     // worst case P=2: 72KB

// FFN GEMMs (P=2). MODE 0: fp32 out. MODE 1: relu + fp16 out.
template <int MODE>
__global__ __launch_bounds__(256, 2)
void tgemm_kernel(const __half* __restrict__ A,
                  const __half* __restrict__ Bh,
                  const __half* __restrict__ Bl,
                  const float* __restrict__ bias,
                  float* __restrict__ Cf,
                  __half* __restrict__ Ch,
                  int M, int N, int K)
{
    extern __shared__ char smem[];
    const u32 sb = smem_u32(smem);
    const int tid  = threadIdx.x;
    const int wid  = tid >> 5, lane = tid & 31;
    const int wm   = wid >> 2, wn = wid & 3;
    const int m0   = blockIdx.y * 128;
    const int n0   = blockIdx.x * 128;
    const int lr16 = lane & 15, lc = lane >> 4;

    float acc[4][4][4];
#pragma unroll
    for (int mt = 0; mt < 4; mt++)
#pragma unroll
        for (int nt = 0; nt < 4; nt++)
#pragma unroll
            for (int r = 0; r < 4; r++) acc[mt][nt][r] = 0.0f;

    tgn_mainloop<2>(sb, A + (size_t)m0 * K,
                    Bh + (size_t)n0 * K, Bl + (size_t)n0 * K,
                    K, tid, wm, wn, lr16, lc, acc);

    const int tg = lane >> 2;
    const int tc = (lane & 3) * 2;
#pragma unroll
    for (int mt = 0; mt < 4; mt++) {
#pragma unroll
        for (int half_ = 0; half_ < 2; half_++) {
            const int m = m0 + wm * 64 + mt * 16 + tg + 8 * half_;
#pragma unroll
            for (int nt = 0; nt < 4; nt++) {
                const int n = n0 + wn * 32 + nt * 8 + tc;
                float v0 = acc[mt][nt][2 * half_]     + bias[n];
                float v1 = acc[mt][nt][2 * half_ + 1] + bias[n + 1];
                if (MODE == 0) {
                    *(float2*)(Cf + (size_t)m * N + n) = make_float2(v0, v1);
                } else {
                    v0 = fmaxf(v0, 0.0f); v1 = fmaxf(v1, 0.0f);
                    *(u32*)(Ch + (size_t)m * N + n) = round2h(v0, v1);
                }
            }
        }
    }
}

// Fused QKV: z=0 Q (P=1, scale 1/8, fp16 out), z=1 K (P=1, fp16 out),
// z=2 V (P=2, smem-staged transpose -> split V^T out).
__global__ __launch_bounds__(256, 2)
void qkv_fused_kernel(const __half* __restrict__ xh,
                      const __half* __restrict__ wqh,
                      const __half* __restrict__ wkh,
                      const __half* __restrict__ wvh, const __half* __restrict__ wvl,
                      const float* __restrict__ bq, const float* __restrict__ bk,
                      const float* __restrict__ bv,
                      __half* __restrict__ qh, __half* __restrict__ kh,
                      __half* __restrict__ vth, __half* __restrict__ vtl)
{
    extern __shared__ char smem[];
    const u32 sb = smem_u32(smem);
    const int tid  = threadIdx.x;
    const int wid  = tid >> 5, lane = tid & 31;
    const int wm   = wid >> 2, wn = wid & 3;
    const int m0   = blockIdx.y * 128;
    const int n0   = blockIdx.x * 128;
    const int z    = blockIdx.z;
    const int lr16 = lane & 15, lc = lane >> 4;

    float acc[4][4][4];
#pragma unroll
    for (int mt = 0; mt < 4; mt++)
#pragma unroll
        for (int nt = 0; nt < 4; nt++)
#pragma unroll
            for (int r = 0; r < 4; r++) acc[mt][nt][r] = 0.0f;

    const int tg = lane >> 2;
    const int tc = (lane & 3) * 2;

    if (z < 2) {
        const __half* Bh = z == 0 ? wqh : wkh;
        const float* bias = z == 0 ? bq : bk;
        tgn_mainloop<1>(sb, xh + (size_t)m0 * DD,
                        Bh + (size_t)n0 * DD, nullptr,
                        DD, tid, wm, wn, lr16, lc, acc);
        const float scl = (z == 0) ? 0.125f : 1.0f;
        __half* C = z == 0 ? qh : kh;
#pragma unroll
        for (int mt = 0; mt < 4; mt++)
#pragma unroll
            for (int half_ = 0; half_ < 2; half_++) {
                const int m = m0 + wm * 64 + mt * 16 + tg + 8 * half_;
#pragma unroll
                for (int nt = 0; nt < 4; nt++) {
                    const int n = n0 + wn * 32 + nt * 8 + tc;
                    float v0 = (acc[mt][nt][2 * half_]     + bias[n])     * scl;
                    float v1 = (acc[mt][nt][2 * half_ + 1] + bias[n + 1]) * scl;
                    *(u32*)(C + (size_t)m * DD + n) = round2h(v0, v1);
                }
            }
    } else {
        tgn_mainloop<2>(sb, xh + (size_t)m0 * DD,
                        wvh + (size_t)n0 * DD, wvl + (size_t)n0 * DD,
                        DD, tid, wm, wn, lr16, lc, acc);
        // V: stage fp32 tile (64-col halves), write transposed split fp16 V^T.
        float* tile = (float*)smem;     // [128][68] fp32
#pragma unroll 1
        for (int hf = 0; hf < 2; hf++) {
            __syncthreads();
#pragma unroll
            for (int mt = 0; mt < 4; mt++) {
#pragma unroll
                for (int half_ = 0; half_ < 2; half_++) {
                    const int ml = wm * 64 + mt * 16 + tg + 8 * half_;
#pragma unroll
                    for (int nt = 0; nt < 4; nt++) {
                        const int nl = wn * 32 + nt * 8 + tc;
                        if ((nl & 64) == (hf << 6)) {
                            const int nll = nl & 63;
                            tile[ml * 68 + nll]     = acc[mt][nt][2 * half_]     + bv[n0 + nl];
                            tile[ml * 68 + nll + 1] = acc[mt][nt][2 * half_ + 1] + bv[n0 + nl + 1];
                        }
                    }
                }
            }
            __syncthreads();
            const int b    = m0 >> 11;
            const int tok0 = m0 & 2047;
            const int nl   = tid >> 2;
            const int mh   = (tid & 3) * 32;
            const size_t orow = (size_t)(b * 512 + n0 + hf * 64 + nl) * LL + tok0 + mh;
#pragma unroll
            for (int it = 0; it < 4; it++) {
                u32 hp[4], lp[4];
#pragma unroll
                for (int j2 = 0; j2 < 4; j2++) {
                    float v0 = tile[(mh + 8 * it + 2 * j2)     * 68 + nl];
                    float v1 = tile[(mh + 8 * it + 2 * j2 + 1) * 68 + nl];
                    split2h(v0, v1, hp[j2], lp[j2]);
                }
                *(uint4*)(vth + orow + 8 * it) = *(uint4*)hp;
                *(uint4*)(vtl + orow + 8 * it) = *(uint4*)lp;
            }
        }
    }
}

// ---------------------------------------------------------------------------
// HMMA flash attention: S, R single-pass; PV 2-pass.
//   logits[i,j] = Qs_i.K_j + Qs_i.rel[2047-(i-j)]  (Qs pre-scaled 1/8)
// Stage tiles: kh, fh, vh, vl (4 x 8KB = 32KB).
// ---------------------------------------------------------------------------
#define AT_STAGE 32768
#define AT_R3OFF (2 * AT_STAGE)        // 65536
#define AT_RSTR  66
#define AT_SLOT  (128 * AT_RSTR)
#define AT_SMEM  (AT_R3OFF + 3 * AT_SLOT * 4)   // 166912

__device__ __forceinline__ void attn_load_stage(
    u32 dstbase, int j0, int t, int tid, int b, int h,
    const __half* __restrict__ kh,
    const __half* __restrict__ relh,
    const __half* __restrict__ vth, const __half* __restrict__ vtl)
{
    const int r0 = tid >> 3, c = tid & 7;
#pragma unroll
    for (int i = 0; i < 2; i++) {
        const int r = r0 + 32 * i;
        const u32 sw = (u32)(r * 128 + 16 * (c ^ (r & 7)));
        const size_t krow = (size_t)(b * LL + j0 + r) * DD + h * DHH + 8 * c;
        const size_t frow = (size_t)(2047 - 64 * t - r) * DD + h * DHH + 8 * c;
        const size_t vrow = (size_t)((b * 8 + h) * 64 + r) * LL + j0 + 8 * c;
        cp16(dstbase +          sw, kh   + krow);
        cp16(dstbase +  8192 +  sw, relh + frow);
        cp16(dstbase + 16384 +  sw, vth  + vrow);
        cp16(dstbase + 24576 +  sw, vtl  + vrow);
    }
}

__global__ __launch_bounds__(256, 1)
void attn_mma_kernel(const __half* __restrict__ qh,
                     const __half* __restrict__ kh,
                     const __half* __restrict__ vth, const __half* __restrict__ vtl,
                     const __half* __restrict__ relh,
                     __half* __restrict__ oh)
{
    extern __shared__ char smem[];
    const u32 sb = smem_u32(smem);
    float* R3 = (float*)(smem + AT_R3OFF);

    const int tid = threadIdx.x, lane = tid & 31, w = tid >> 5;
    const int p   = blockIdx.x >> 4;
    const int bh  = blockIdx.x & 15;
    const int b   = bh >> 3, h = bh & 7;
    const int g   = lane >> 2, t4 = lane & 3;
    const int lr16 = lane & 15, lc = lane >> 4;

#pragma unroll 1
    for (int qq = 0; qq < 2; qq++) {
        const int q  = qq ? (15 - p) : p;
        const int i0 = q * 128;
        const int NT = 2 * q + 2;
        const int R0 = 16 * w + g, R1 = R0 + 8;
        const size_t rowg0 = (size_t)(b * LL + i0 + R0);

        u32 qfh[4][4];
        {
            const __half* ph_ = qh + rowg0 * DD + h * DHH + 2 * t4;
#pragma unroll
            for (int ks = 0; ks < 4; ks++) {
                qfh[ks][0] = *(const u32*)(ph_ + 16 * ks);
                qfh[ks][1] = *(const u32*)(ph_ + 16 * ks + 8 * DD);
                qfh[ks][2] = *(const u32*)(ph_ + 16 * ks + 8);
                qfh[ks][3] = *(const u32*)(ph_ + 16 * ks + 8 * DD + 8);
            }
        }

        float accO[8][4];
#pragma unroll
        for (int j = 0; j < 8; j++)
#pragma unroll
            for (int r = 0; r < 4; r++) accO[j][r] = 0.0f;
        float mrow0 = -1e30f, mrow1 = -1e30f, lrow0 = 0.0f, lrow1 = 0.0f;

        attn_load_stage(sb, i0 + 64, 0, tid, b, h, kh, relh, vth, vtl);
        CP_COMMIT();

#pragma unroll 1
        for (int t = 0; t < NT; t++) {
            const int j0 = i0 + 64 - 64 * t;
            if (t + 1 < NT) {
                attn_load_stage(sb + ((t + 1) & 1) * AT_STAGE, j0 - 64, t + 1,
                                tid, b, h, kh, relh, vth, vtl);
                CP_COMMIT();
                CP_WAIT(1);
            } else {
                CP_WAIT(0);
            }
            __syncthreads();

            const u32 st  = sb + (t & 1) * AT_STAGE;
            const u32 sKh = st, sFh = st + 8192,
                      sVh = st + 16384, sVl = st + 24576;

            // ---- R = Qs @ Fchunk^T (single pass) ----
            {
                float racc[8][4];
#pragma unroll
                for (int j = 0; j < 8; j++)
#pragma unroll
                    for (int r = 0; r < 4; r++) racc[j][r] = 0.0f;
#pragma unroll
                for (int ks = 0; ks < 4; ks++) {
                    u32 fh[4][4];
#pragma unroll
                    for (int ng = 0; ng < 4; ng++) {
                        const int row = 16 * ng + lr16;
                        const u32 off = (u32)(row * 128 + 16 * ((2 * ks + lc) ^ (row & 7)));
                        LDSM_X4(fh[ng], sFh + off);
                    }
#pragma unroll
                    for (int ng = 0; ng < 4; ng++) {
                        MMA_F16(racc[2*ng],   qfh[ks], fh[ng][0], fh[ng][2]);
                        MMA_F16(racc[2*ng+1], qfh[ks], fh[ng][1], fh[ng][3]);
                    }
                }
                float* Rb = R3 + (t % 3) * AT_SLOT;
#pragma unroll
                for (int j = 0; j < 8; j++) {
                    *(float2*)&Rb[R0 * AT_RSTR + 8 * j + 2 * t4] = make_float2(racc[j][0], racc[j][1]);
                    *(float2*)&Rb[R1 * AT_RSTR + 8 * j + 2 * t4] = make_float2(racc[j][2], racc[j][3]);
                }
            }
            __syncwarp();

            // ---- S = Qs @ K^T (single pass) ----
            float sacc[8][4];
#pragma unroll
            for (int j = 0; j < 8; j++)
#pragma unroll
                for (int r = 0; r < 4; r++) sacc[j][r] = 0.0f;
#pragma unroll
            for (int ks = 0; ks < 4; ks++) {
                u32 bkh_[4][4];
#pragma unroll
                for (int ng = 0; ng < 4; ng++) {
                    const int row = 16 * ng + lr16;
                    const u32 off = (u32)(row * 128 + 16 * ((2 * ks + lc) ^ (row & 7)));
                    LDSM_X4(bkh_[ng], sKh + off);
                }
#pragma unroll
                for (int ng = 0; ng < 4; ng++) {
                    MMA_F16(sacc[2*ng],   qfh[ks], bkh_[ng][0], bkh_[ng][2]);
                    MMA_F16(sacc[2*ng+1], qfh[ks], bkh_[ng][1], bkh_[ng][3]);
                }
            }

            // ---- gather skew bias + mask + online softmax ----
            float mx0 = -1e30f, mx1 = -1e30f;
#pragma unroll
            for (int j = 0; j < 8; j++) {
#pragma unroll
                for (int c2 = 0; c2 < 2; c2++) {
                    const int dj = 8 * j + 2 * t4 + c2;
                    {
                        const int e = 64 + R0 - dj;
                        const int slot = (t + 1 + (e >> 6)) % 3;
                        float sv = sacc[j][c2] + R3[slot * AT_SLOT + R0 * AT_RSTR + (e & 63)];
                        if (t < 2 && (64 * (t - 1) + R0 - dj) < 0) sv = -1e30f;
                        sacc[j][c2] = sv;
                        mx0 = fmaxf(mx0, sv);
                    }
                    {
                        const int e = 64 + R1 - dj;
                        const int slot = (t + 1 + (e >> 6)) % 3;
                        float sv = sacc[j][2 + c2] + R3[slot * AT_SLOT + R1 * AT_RSTR + (e & 63)];
                        if (t < 2 && (64 * (t - 1) + R1 - dj) < 0) sv = -1e30f;
                        sacc[j][2 + c2] = sv;
                        mx1 = fmaxf(mx1, sv);
                    }
                }
            }
            mx0 = fmaxf(mx0, __shfl_xor_sync(0xffffffffu, mx0, 1));
            mx0 = fmaxf(mx0, __shfl_xor_sync(0xffffffffu, mx0, 2));
            mx1 = fmaxf(mx1, __shfl_xor_sync(0xffffffffu, mx1, 1));
            mx1 = fmaxf(mx1, __shfl_xor_sync(0xffffffffu, mx1, 2));

            const float mn0 = fmaxf(mrow0, mx0), mn1 = fmaxf(mrow1, mx1);
            const float al0 = __expf(mrow0 - mn0), al1 = __expf(mrow1 - mn1);
            mrow0 = mn0; mrow1 = mn1;

            float rs0 = 0.0f, rs1 = 0.0f;
#pragma unroll
            for (int j = 0; j < 8; j++) {
#pragma unroll
                for (int c2 = 0; c2 < 2; c2++) {
                    float sv = sacc[j][c2];
                    float e  = __expf(sv - mn0);
                    if (sv < -1e29f) e = 0.0f;
                    rs0 += e; sacc[j][c2] = e;
                    sv = sacc[j][2 + c2];
                    e  = __expf(sv - mn1);
                    if (sv < -1e29f) e = 0.0f;
                    rs1 += e; sacc[j][2 + c2] = e;
                }
            }
            rs0 += __shfl_xor_sync(0xffffffffu, rs0, 1);
            rs0 += __shfl_xor_sync(0xffffffffu, rs0, 2);
            rs1 += __shfl_xor_sync(0xffffffffu, rs1, 1);
            rs1 += __shfl_xor_sync(0xffffffffu, rs1, 2);
            lrow0 = lrow0 * al0 + rs0;
            lrow1 = lrow1 * al1 + rs1;
#pragma unroll
            for (int j = 0; j < 8; j++) {
                accO[j][0] *= al0; accO[j][1] *= al0;
                accO[j][2] *= al1; accO[j][3] *= al1;
            }

            // ---- O += P @ V (P -> fp16, 2 passes over V split) ----
#pragma unroll
            for (int ks = 0; ks < 4; ks++) {
                u32 ph_[4];
                ph_[0] = round2h(sacc[2*ks][0],   sacc[2*ks][1]);
                ph_[1] = round2h(sacc[2*ks][2],   sacc[2*ks][3]);
                ph_[2] = round2h(sacc[2*ks+1][0], sacc[2*ks+1][1]);
                ph_[3] = round2h(sacc[2*ks+1][2], sacc[2*ks+1][3]);
                u32 bvh_[4][4], bvl_[4][4];
#pragma unroll
                for (int ng = 0; ng < 4; ng++) {
                    const int row = 16 * ng + lr16;
                    const u32 off = (u32)(row * 128 + 16 * ((2 * ks + lc) ^ (row & 7)));
                    LDSM_X4(bvh_[ng], sVh + off);
                    LDSM_X4(bvl_[ng], sVl + off);
                }
#pragma unroll
                for (int ng = 0; ng < 4; ng++) {
                    MMA_F16(accO[2*ng],   ph_, bvh_[ng][0], bvh_[ng][2]);
                    MMA_F16(accO[2*ng+1], ph_, bvh_[ng][1], bvh_[ng][3]);
                }
#pragma unroll
                for (int ng = 0; ng < 4; ng++) {
                    MMA_F16(accO[2*ng],   ph_, bvl_[ng][0], bvl_[ng][2]);
                    MMA_F16(accO[2*ng+1], ph_, bvl_[ng][1], bvl_[ng][3]);
                }
            }
            __syncthreads();
        }

        // ---- epilogue: normalize, fp16 out (A-op of FFN1) ----
        const float inv0 = 1.0f / lrow0, inv1 = 1.0f / lrow1;
        __half* o0h = oh + rowg0 * DD + h * DHH + 2 * t4;
#pragma unroll
        for (int j = 0; j < 8; j++) {
            *(u32*)(o0h + 8 * j)          = round2h(accO[j][0] * inv0, accO[j][1] * inv0);
            *(u32*)(o0h + 8 * DD + 8 * j) = round2h(accO[j][2] * inv1, accO[j][3] * inv1);
        }
    }
}

// ---------------------------------------------------------------------------
// Launch
// ---------------------------------------------------------------------------
extern "C" void kernel_launch(void* const* d_in, const int* in_sizes, int n_in,
                              void* d_out, int out_size)
{
    const float* x   = (const float*)d_in[0];
    // d_in[1] = mask — handled analytically
    const float* wq  = (const float*)d_in[2];
    const float* bq  = (const float*)d_in[3];
    const float* wk  = (const float*)d_in[4];
    const float* bk  = (const float*)d_in[5];
    const float* wv  = (const float*)d_in[6];
    const float* bv  = (const float*)d_in[7];
    const float* rel = (const float*)d_in[8];
    const float* w1  = (const float*)d_in[9];
    const float* b1  = (const float*)d_in[10];
    const float* w2  = (const float*)d_in[11];
    const float* b2  = (const float*)d_in[12];
    float* out = (float*)d_out;

    __half *xh, *qh, *kh, *vth, *vtl, *relh, *ah, *hhp;
    __half *wqh, *wkh, *wvh, *wvl, *w1h, *w1l, *w2h, *w2l;
    cudaGetSymbolAddress((void**)&xh,  g_xh);
    cudaGetSymbolAddress((void**)&qh,  g_qh);
    cudaGetSymbolAddress((void**)&kh,  g_kh);
    cudaGetSymbolAddress((void**)&vth, g_vth);  cudaGetSymbolAddress((void**)&vtl, g_vtl);
    cudaGetSymbolAddress((void**)&relh, g_relh);
    cudaGetSymbolAddress((void**)&ah,  g_ah);
    cudaGetSymbolAddress((void**)&hhp, g_hh);
    cudaGetSymbolAddress((void**)&wqh, g_wqh);
    cudaGetSymbolAddress((void**)&wkh, g_wkh);
    cudaGetSymbolAddress((void**)&wvh, g_wvh);  cudaGetSymbolAddress((void**)&wvl, g_wvl);
    cudaGetSymbolAddress((void**)&w1h, g_w1h);  cudaGetSymbolAddress((void**)&w1l, g_w1l);
    cudaGetSymbolAddress((void**)&w2h, g_w2h);  cudaGetSymbolAddress((void**)&w2l, g_w2l);

    cudaFuncSetAttribute(tgemm_kernel<0>,  cudaFuncAttributeMaxDynamicSharedMemorySize, TGN_SMEM);
    cudaFuncSetAttribute(tgemm_kernel<1>,  cudaFuncAttributeMaxDynamicSharedMemorySize, TGN_SMEM);
    cudaFuncSetAttribute(qkv_fused_kernel, cudaFuncAttributeMaxDynamicSharedMemorySize, TGN_SMEM);
    cudaFuncSetAttribute(attn_mma_kernel,  cudaFuncAttributeMaxDynamicSharedMemorySize, AT_SMEM);

    // 0) Prep
    conv_xrel_kernel<<<(N4X + N4R + 255) / 256, 256>>>(
        (const float4*)x, (const float4*)rel, xh, relh);
    tsplit3_kernel<<<dim3(DD / 32, DD / 32, 3), 256>>>(
        wq, wk, wv, wqh, wkh, wvh, wvl);
    tsplit_ffn_kernel<<<dim3(DFCN / 32, DD / 32, 2), 256>>>(
        w1, w2, w1h, w1l, w2h, w2l);

    // 1) Fused QKV (Q,K single-pass; V 2-pass with V^T split epilogue)
    qkv_fused_kernel<<<dim3(DD / 128, MM / 128, 3), 256, TGN_SMEM>>>(
        xh, wqh, wkh, wvh, wvl, bq, bk, bv, qh, kh, vth, vtl);

    // 2) HMMA flash attention with relative bias
    attn_mma_kernel<<<128, 256, AT_SMEM>>>(qh, kh, vth, vtl, relh, ah);

    // 3) FFN (2-pass)
    tgemm_kernel<1><<<dim3(DFCN / 128, MM / 128), 256, TGN_SMEM>>>(
        ah, w1h, w1l, b1, nullptr, hhp, MM, DFCN, DD);
    tgemm_kernel<0><<<dim3(DD / 128, MM / 128), 256, TGN_SMEM>>>(
        hhp, w2h, w2l, b2, out, nullptr, MM, DD, DFCN);
}

// round 14
// speedup vs baseline: 2.0515x; 1.3474x over previous
#include <cuda_runtime.h>
#include <cuda_fp16.h>
#include <cstdint>
#include <cstddef>

// ---------------------------------------------------------------------------
// Problem constants
// ---------------------------------------------------------------------------
#define BB   2
#define LL   2048
#define DD   512
#define HH   8
#define DHH  64
#define DFCN 2048
#define MM   (BB * LL)        // 4096 rows

typedef unsigned long long u64;
typedef unsigned int u32;

// ---------------------------------------------------------------------------
// Scratch (device globals) — full single-fp16 pipeline, fp32 accumulate.
// ---------------------------------------------------------------------------
__device__ __half g_xh[MM * DD];                       // x
__device__ __half g_qh[MM * DD];                       // scaled Q
__device__ __half g_kh[MM * DD];                       // K
__device__ __half g_vth[BB*HH*DHH * LL];               // V^T
__device__ __half g_relh[LL * DD];                     // rel
__device__ __half g_ah[MM * DD];                       // attn out
__device__ __half g_hh[MM * DFCN];                     // FFN hidden

// Transposed weights: T[n][k] = W[k][n]
__device__ __half g_wqh[DD * DD];
__device__ __half g_wkh[DD * DD];
__device__ __half g_wvh[DD * DD];
__device__ __half g_w1h[DFCN * DD];
__device__ __half g_w2h[DD * DFCN];

// ---------------------------------------------------------------------------
// Helpers
// ---------------------------------------------------------------------------
__device__ __forceinline__ u32 smem_u32(const void* p) {
    u32 a;
    asm("{ .reg .u64 t; cvta.to.shared.u64 t, %1; cvt.u32.u64 %0, t; }"
        : "=r"(a) : "l"(p));
    return a;
}

__device__ __forceinline__ u32 round2h(float x, float y) {
    __half2 h = __floats2half2_rn(x, y);
    return *(u32*)&h;
}

#define LDSM_X4(r, addr) \
    asm volatile("ldmatrix.sync.aligned.m8n8.x4.shared.b16 {%0,%1,%2,%3}, [%4];" \
        : "=r"((r)[0]), "=r"((r)[1]), "=r"((r)[2]), "=r"((r)[3]) : "r"(addr))

#define MMA_F16(d, a, b0, b1) \
    asm volatile("mma.sync.aligned.m16n8k16.row.col.f32.f16.f16.f32 " \
        "{%0,%1,%2,%3}, {%4,%5,%6,%7}, {%8,%9}, {%0,%1,%2,%3};" \
        : "+f"((d)[0]), "+f"((d)[1]), "+f"((d)[2]), "+f"((d)[3]) \
        : "r"((a)[0]), "r"((a)[1]), "r"((a)[2]), "r"((a)[3]), "r"(b0), "r"(b1))

__device__ __forceinline__ void cp16(u32 dst, const void* src) {
    asm volatile("cp.async.cg.shared.global [%0], [%1], 16;"
                 :: "r"(dst), "l"(src) : "memory");
}
#define CP_COMMIT()  asm volatile("cp.async.commit_group;" ::: "memory")
#define CP_WAIT(n)   asm volatile("cp.async.wait_group %0;" :: "n"(n) : "memory")

// ---------------------------------------------------------------------------
// Prep kernels
// ---------------------------------------------------------------------------
// wq, wk, wv -> single fp16 transpose. One launch (z).
__global__ __launch_bounds__(256)
void tsplit3_kernel(const float* __restrict__ wq, const float* __restrict__ wk,
                    const float* __restrict__ wv,
                    __half* __restrict__ qhh, __half* __restrict__ khh,
                    __half* __restrict__ vhh)
{
    const int z = blockIdx.z;
    const float* W = z == 0 ? wq : z == 1 ? wk : wv;
    __half* Th = z == 0 ? qhh : z == 1 ? khh : vhh;

    __shared__ float t[32][33];
    const int n0 = blockIdx.x * 32, k0 = blockIdx.y * 32;
    const int tx = threadIdx.x & 31, ty = threadIdx.x >> 5;
#pragma unroll
    for (int i = 0; i < 4; i++)
        t[ty + 8 * i][tx] = W[(size_t)(k0 + ty + 8 * i) * DD + n0 + tx];
    __syncthreads();
#pragma unroll
    for (int i = 0; i < 4; i++) {
        int n = n0 + ty + 8 * i;
        Th[(size_t)n * DD + k0 + tx] = __float2half_rn(t[tx][ty + 8 * i]);
    }
}

__global__ __launch_bounds__(256)
void tsplit_ffn_kernel(const float* __restrict__ w1, const float* __restrict__ w2,
                       __half* __restrict__ w1h, __half* __restrict__ w2h)
{
    const int z = blockIdx.z;
    const float* W = z == 0 ? w1 : w2;
    __half* Th = z == 0 ? w1h : w2h;
    const int K = z == 0 ? DD : DFCN;
    const int N = z == 0 ? DFCN : DD;
    const int n0 = (z == 0 ? blockIdx.x : blockIdx.y) * 32;
    const int k0 = (z == 0 ? blockIdx.y : blockIdx.x) * 32;

    __shared__ float t[32][33];
    const int tx = threadIdx.x & 31, ty = threadIdx.x >> 5;
#pragma unroll
    for (int i = 0; i < 4; i++)
        t[ty + 8 * i][tx] = W[(size_t)(k0 + ty + 8 * i) * N + n0 + tx];
    __syncthreads();
#pragma unroll
    for (int i = 0; i < 4; i++) {
        int n = n0 + ty + 8 * i;
        Th[(size_t)n * K + k0 + tx] = __float2half_rn(t[tx][ty + 8 * i]);
    }
}

// x -> fp16; rel -> fp16. One launch.
#define N4X (MM * DD / 4)
#define N4R (LL * DD / 4)
__global__ __launch_bounds__(256)
void conv_xrel_kernel(const float4* __restrict__ X, const float4* __restrict__ R,
                      __half* __restrict__ XH, __half* __restrict__ RH)
{
    int i = blockIdx.x * blockDim.x + threadIdx.x;
    const float4* src; __half* H; int j;
    if (i < N4X) { src = X; H = XH; j = i; }
    else if (i < N4X + N4R) { src = R; H = RH; j = i - N4X; }
    else return;
    float4 v = src[j];
    uint2 hp;
    hp.x = round2h(v.x, v.y);
    hp.y = round2h(v.z, v.w);
    *(uint2*)(H + 4 * (size_t)j) = hp;
}

// ---------------------------------------------------------------------------
// fp16 HMMA GEMM core (single pass): C = A @ B^T + bias.
// BK=32, 3-stage cp.async ring, 128x128 CTA tile, 8 warps (2x4), 64x32 warp
// tile. Smem rows 64B, 16B-chunk swizzle c ^= (row>>1)&3. Stage = 16KB.
// ---------------------------------------------------------------------------
#define TGN_TILE  8192                  // 128 x 32 x 2B
#define TGN_STAGE (2 * TGN_TILE)        // A, B = 16KB
#define TGN_SMEM  (3 * TGN_STAGE)       // 48KB

__device__ __forceinline__ void load_tile32(const __half* __restrict__ src,
                                            int ldk, u32 sdst, int tid)
{
#pragma unroll
    for (int i = 0; i < 2; i++) {
        int idx = tid + 256 * i;
        int r = idx >> 2, c = idx & 3;
        cp16(sdst + r * 64 + 16 * (c ^ ((r >> 1) & 3)), src + (size_t)r * ldk + 8 * c);
    }
}

__device__ __forceinline__ void tgn_stage_load(
    u32 sdst, const __half* A, const __half* B, int K, int kofs, int tid)
{
    load_tile32(A + kofs, K, sdst,            tid);
    load_tile32(B + kofs, K, sdst + TGN_TILE, tid);
}

__device__ __forceinline__ void tgn_compute_chunk(
    u32 base, int wm, int wn, int lr16, int lc, float acc[4][4][4])
{
    const u32 sA = base, sB = base + TGN_TILE;
#pragma unroll
    for (int ks = 0; ks < 2; ks++) {
        const int ch = 2 * ks + lc;
        u32 bh[2][4];
#pragma unroll
        for (int ng = 0; ng < 2; ng++) {
            int r = wn * 32 + ng * 16 + lr16;
            u32 off = r * 64 + 16 * (ch ^ ((r >> 1) & 3));
            LDSM_X4(bh[ng], sB + off);
        }
#pragma unroll
        for (int mt = 0; mt < 4; mt++) {
            int r = wm * 64 + mt * 16 + lr16;
            u32 off = r * 64 + 16 * (ch ^ ((r >> 1) & 3));
            u32 ah[4];
            LDSM_X4(ah, sA + off);
#pragma unroll
            for (int nt = 0; nt < 4; nt++) {
                const int ng = nt >> 1, hi = nt & 1;
                MMA_F16(acc[mt][nt], ah, bh[ng][hi], bh[ng][2 + hi]);
            }
        }
    }
}

__device__ __forceinline__ void tgn_mainloop(
    u32 sb, const __half* Abase, const __half* Bbase,
    int K, int tid, int wm, int wn, int lr16, int lc, float acc[4][4][4])
{
    const int NC = K >> 5;
    tgn_stage_load(sb, Abase, Bbase, K, 0, tid);
    CP_COMMIT();
    if (NC > 1) {
        tgn_stage_load(sb + TGN_STAGE, Abase, Bbase, K, 32, tid);
        CP_COMMIT();
    }
    int sc = 0, sn = 2;
    for (int c = 0; c < NC; c++) {
        CP_WAIT(1);
        __syncthreads();
        if (c + 2 < NC) {
            tgn_stage_load(sb + sn * TGN_STAGE, Abase, Bbase, K, (c + 2) * 32, tid);
            CP_COMMIT();
        } else {
            CP_COMMIT();
        }
        tgn_compute_chunk(sb + sc * TGN_STAGE, wm, wn, lr16, lc, acc);
        sc = sc == 2 ? 0 : sc + 1;
        sn = sn == 2 ? 0 : sn + 1;
    }
}

// FFN GEMMs. MODE 0: fp32 out. MODE 1: relu + fp16 out.
template <int MODE>
__global__ __launch_bounds__(256, 2)
void tgemm_kernel(const __half* __restrict__ A,
                  const __half* __restrict__ B,
                  const float* __restrict__ bias,
                  float* __restrict__ Cf,
                  __half* __restrict__ Ch,
                  int M, int N, int K)
{
    extern __shared__ char smem[];
    const u32 sb = smem_u32(smem);
    const int tid  = threadIdx.x;
    const int wid  = tid >> 5, lane = tid & 31;
    const int wm   = wid >> 2, wn = wid & 3;
    const int m0   = blockIdx.y * 128;
    const int n0   = blockIdx.x * 128;
    const int lr16 = lane & 15, lc = lane >> 4;

    float acc[4][4][4];
#pragma unroll
    for (int mt = 0; mt < 4; mt++)
#pragma unroll
        for (int nt = 0; nt < 4; nt++)
#pragma unroll
            for (int r = 0; r < 4; r++) acc[mt][nt][r] = 0.0f;

    tgn_mainloop(sb, A + (size_t)m0 * K, B + (size_t)n0 * K,
                 K, tid, wm, wn, lr16, lc, acc);

    const int tg = lane >> 2;
    const int tc = (lane & 3) * 2;
#pragma unroll
    for (int mt = 0; mt < 4; mt++) {
#pragma unroll
        for (int half_ = 0; half_ < 2; half_++) {
            const int m = m0 + wm * 64 + mt * 16 + tg + 8 * half_;
#pragma unroll
            for (int nt = 0; nt < 4; nt++) {
                const int n = n0 + wn * 32 + nt * 8 + tc;
                float v0 = acc[mt][nt][2 * half_]     + bias[n];
                float v1 = acc[mt][nt][2 * half_ + 1] + bias[n + 1];
                if (MODE == 0) {
                    *(float2*)(Cf + (size_t)m * N + n) = make_float2(v0, v1);
                } else {
                    v0 = fmaxf(v0, 0.0f); v1 = fmaxf(v1, 0.0f);
                    *(u32*)(Ch + (size_t)m * N + n) = round2h(v0, v1);
                }
            }
        }
    }
}

// Fused QKV: z=0 Q (scale 1/8), z=1 K, z=2 V (smem transpose -> V^T fp16).
__global__ __launch_bounds__(256, 2)
void qkv_fused_kernel(const __half* __restrict__ xh,
                      const __half* __restrict__ wqh,
                      const __half* __restrict__ wkh,
                      const __half* __restrict__ wvh,
                      const float* __restrict__ bq, const float* __restrict__ bk,
                      const float* __restrict__ bv,
                      __half* __restrict__ qh, __half* __restrict__ kh,
                      __half* __restrict__ vth)
{
    extern __shared__ char smem[];
    const u32 sb = smem_u32(smem);
    const int tid  = threadIdx.x;
    const int wid  = tid >> 5, lane = tid & 31;
    const int wm   = wid >> 2, wn = wid & 3;
    const int m0   = blockIdx.y * 128;
    const int n0   = blockIdx.x * 128;
    const int z    = blockIdx.z;
    const int lr16 = lane & 15, lc = lane >> 4;

    const __half* B = z == 0 ? wqh : z == 1 ? wkh : wvh;
    const float* bias = z == 0 ? bq : z == 1 ? bk : bv;

    float acc[4][4][4];
#pragma unroll
    for (int mt = 0; mt < 4; mt++)
#pragma unroll
        for (int nt = 0; nt < 4; nt++)
#pragma unroll
            for (int r = 0; r < 4; r++) acc[mt][nt][r] = 0.0f;

    tgn_mainloop(sb, xh + (size_t)m0 * DD, B + (size_t)n0 * DD,
                 DD, tid, wm, wn, lr16, lc, acc);

    const int tg = lane >> 2;
    const int tc = (lane & 3) * 2;

    if (z < 2) {
        const float scl = (z == 0) ? 0.125f : 1.0f;
        __half* C = z == 0 ? qh : kh;
#pragma unroll
        for (int mt = 0; mt < 4; mt++)
#pragma unroll
            for (int half_ = 0; half_ < 2; half_++) {
                const int m = m0 + wm * 64 + mt * 16 + tg + 8 * half_;
#pragma unroll
                for (int nt = 0; nt < 4; nt++) {
                    const int n = n0 + wn * 32 + nt * 8 + tc;
                    float v0 = (acc[mt][nt][2 * half_]     + bias[n])     * scl;
                    float v1 = (acc[mt][nt][2 * half_ + 1] + bias[n + 1]) * scl;
                    *(u32*)(C + (size_t)m * DD + n) = round2h(v0, v1);
                }
            }
    } else {
        // V: stage fp32 tile (64-col halves), write transposed fp16 V^T.
        float* tile = (float*)smem;     // [128][68] fp32
#pragma unroll 1
        for (int hf = 0; hf < 2; hf++) {
            __syncthreads();
#pragma unroll
            for (int mt = 0; mt < 4; mt++) {
#pragma unroll
                for (int half_ = 0; half_ < 2; half_++) {
                    const int ml = wm * 64 + mt * 16 + tg + 8 * half_;
#pragma unroll
                    for (int nt = 0; nt < 4; nt++) {
                        const int nl = wn * 32 + nt * 8 + tc;
                        if ((nl & 64) == (hf << 6)) {
                            const int nll = nl & 63;
                            tile[ml * 68 + nll]     = acc[mt][nt][2 * half_]     + bias[n0 + nl];
                            tile[ml * 68 + nll + 1] = acc[mt][nt][2 * half_ + 1] + bias[n0 + nl + 1];
                        }
                    }
                }
            }
            __syncthreads();
            const int b    = m0 >> 11;
            const int tok0 = m0 & 2047;
            const int nl   = tid >> 2;
            const int mh   = (tid & 3) * 32;
            const size_t orow = (size_t)(b * 512 + n0 + hf * 64 + nl) * LL + tok0 + mh;
#pragma unroll
            for (int it = 0; it < 4; it++) {
                u32 hp[4];
#pragma unroll
                for (int j2 = 0; j2 < 4; j2++) {
                    float v0 = tile[(mh + 8 * it + 2 * j2)     * 68 + nl];
                    float v1 = tile[(mh + 8 * it + 2 * j2 + 1) * 68 + nl];
                    hp[j2] = round2h(v0, v1);
                }
                *(uint4*)(vth + orow + 8 * it) = *(uint4*)hp;
            }
        }
    }
}

// ---------------------------------------------------------------------------
// HMMA flash attention: all single-pass fp16 (S, R, PV), fp32 accumulate.
//   logits[i,j] = Qs_i.K_j + Qs_i.rel[2047-(i-j)]  (Qs pre-scaled 1/8)
// Stage tiles: kh, fh, vh (3 x 8KB = 24KB).
// ---------------------------------------------------------------------------
#define AT_STAGE 24576
#define AT_R3OFF (2 * AT_STAGE)        // 49152
#define AT_RSTR  66
#define AT_SLOT  (128 * AT_RSTR)
#define AT_SMEM  (AT_R3OFF + 3 * AT_SLOT * 4)   // 150528

__device__ __forceinline__ void attn_load_stage(
    u32 dstbase, int j0, int t, int tid, int b, int h,
    const __half* __restrict__ kh,
    const __half* __restrict__ relh,
    const __half* __restrict__ vth)
{
    const int r0 = tid >> 3, c = tid & 7;
#pragma unroll
    for (int i = 0; i < 2; i++) {
        const int r = r0 + 32 * i;
        const u32 sw = (u32)(r * 128 + 16 * (c ^ (r & 7)));
        const size_t krow = (size_t)(b * LL + j0 + r) * DD + h * DHH + 8 * c;
        const size_t frow = (size_t)(2047 - 64 * t - r) * DD + h * DHH + 8 * c;
        const size_t vrow = (size_t)((b * 8 + h) * 64 + r) * LL + j0 + 8 * c;
        cp16(dstbase +          sw, kh   + krow);
        cp16(dstbase +  8192 +  sw, relh + frow);
        cp16(dstbase + 16384 +  sw, vth  + vrow);
    }
}

__global__ __launch_bounds__(256, 1)
void attn_mma_kernel(const __half* __restrict__ qh,
                     const __half* __restrict__ kh,
                     const __half* __restrict__ vth,
                     const __half* __restrict__ relh,
                     __half* __restrict__ oh)
{
    extern __shared__ char smem[];
    const u32 sb = smem_u32(smem);
    float* R3 = (float*)(smem + AT_R3OFF);

    const int tid = threadIdx.x, lane = tid & 31, w = tid >> 5;
    const int p   = blockIdx.x >> 4;
    const int bh  = blockIdx.x & 15;
    const int b   = bh >> 3, h = bh & 7;
    const int g   = lane >> 2, t4 = lane & 3;
    const int lr16 = lane & 15, lc = lane >> 4;

#pragma unroll 1
    for (int qq = 0; qq < 2; qq++) {
        const int q  = qq ? (15 - p) : p;
        const int i0 = q * 128;
        const int NT = 2 * q + 2;
        const int R0 = 16 * w + g, R1 = R0 + 8;
        const size_t rowg0 = (size_t)(b * LL + i0 + R0);

        u32 qfh[4][4];
        {
            const __half* ph_ = qh + rowg0 * DD + h * DHH + 2 * t4;
#pragma unroll
            for (int ks = 0; ks < 4; ks++) {
                qfh[ks][0] = *(const u32*)(ph_ + 16 * ks);
                qfh[ks][1] = *(const u32*)(ph_ + 16 * ks + 8 * DD);
                qfh[ks][2] = *(const u32*)(ph_ + 16 * ks + 8);
                qfh[ks][3] = *(const u32*)(ph_ + 16 * ks + 8 * DD + 8);
            }
        }

        float accO[8][4];
#pragma unroll
        for (int j = 0; j < 8; j++)
#pragma unroll
            for (int r = 0; r < 4; r++) accO[j][r] = 0.0f;
        float mrow0 = -1e30f, mrow1 = -1e30f, lrow0 = 0.0f, lrow1 = 0.0f;

        attn_load_stage(sb, i0 + 64, 0, tid, b, h, kh, relh, vth);
        CP_COMMIT();

#pragma unroll 1
        for (int t = 0; t < NT; t++) {
            const int j0 = i0 + 64 - 64 * t;
            if (t + 1 < NT) {
                attn_load_stage(sb + ((t + 1) & 1) * AT_STAGE, j0 - 64, t + 1,
                                tid, b, h, kh, relh, vth);
                CP_COMMIT();
                CP_WAIT(1);
            } else {
                CP_WAIT(0);
            }
            __syncthreads();

            const u32 st  = sb + (t & 1) * AT_STAGE;
            const u32 sKh = st, sFh = st + 8192, sVh = st + 16384;

            // ---- R = Qs @ Fchunk^T ----
            {
                float racc[8][4];
#pragma unroll
                for (int j = 0; j < 8; j++)
#pragma unroll
                    for (int r = 0; r < 4; r++) racc[j][r] = 0.0f;
#pragma unroll
                for (int ks = 0; ks < 4; ks++) {
                    u32 fh[4][4];
#pragma unroll
                    for (int ng = 0; ng < 4; ng++) {
                        const int row = 16 * ng + lr16;
                        const u32 off = (u32)(row * 128 + 16 * ((2 * ks + lc) ^ (row & 7)));
                        LDSM_X4(fh[ng], sFh + off);
                    }
#pragma unroll
                    for (int ng = 0; ng < 4; ng++) {
                        MMA_F16(racc[2*ng],   qfh[ks], fh[ng][0], fh[ng][2]);
                        MMA_F16(racc[2*ng+1], qfh[ks], fh[ng][1], fh[ng][3]);
                    }
                }
                float* Rb = R3 + (t % 3) * AT_SLOT;
#pragma unroll
                for (int j = 0; j < 8; j++) {
                    *(float2*)&Rb[R0 * AT_RSTR + 8 * j + 2 * t4] = make_float2(racc[j][0], racc[j][1]);
                    *(float2*)&Rb[R1 * AT_RSTR + 8 * j + 2 * t4] = make_float2(racc[j][2], racc[j][3]);
                }
            }
            __syncwarp();

            // ---- S = Qs @ K^T ----
            float sacc[8][4];
#pragma unroll
            for (int j = 0; j < 8; j++)
#pragma unroll
                for (int r = 0; r < 4; r++) sacc[j][r] = 0.0f;
#pragma unroll
            for (int ks = 0; ks < 4; ks++) {
                u32 bkh_[4][4];
#pragma unroll
                for (int ng = 0; ng < 4; ng++) {
                    const int row = 16 * ng + lr16;
                    const u32 off = (u32)(row * 128 + 16 * ((2 * ks + lc) ^ (row & 7)));
                    LDSM_X4(bkh_[ng], sKh + off);
                }
#pragma unroll
                for (int ng = 0; ng < 4; ng++) {
                    MMA_F16(sacc[2*ng],   qfh[ks], bkh_[ng][0], bkh_[ng][2]);
                    MMA_F16(sacc[2*ng+1], qfh[ks], bkh_[ng][1], bkh_[ng][3]);
                }
            }

            // ---- gather skew bias + mask + online softmax ----
            float mx0 = -1e30f, mx1 = -1e30f;
#pragma unroll
            for (int j = 0; j < 8; j++) {
#pragma unroll
                for (int c2 = 0; c2 < 2; c2++) {
                    const int dj = 8 * j + 2 * t4 + c2;
                    {
                        const int e = 64 + R0 - dj;
                        const int slot = (t + 1 + (e >> 6)) % 3;
                        float sv = sacc[j][c2] + R3[slot * AT_SLOT + R0 * AT_RSTR + (e & 63)];
                        if (t < 2 && (64 * (t - 1) + R0 - dj) < 0) sv = -1e30f;
                        sacc[j][c2] = sv;
                        mx0 = fmaxf(mx0, sv);
                    }
                    {
                        const int e = 64 + R1 - dj;
                        const int slot = (t + 1 + (e >> 6)) % 3;
                        float sv = sacc[j][2 + c2] + R3[slot * AT_SLOT + R1 * AT_RSTR + (e & 63)];
                        if (t < 2 && (64 * (t - 1) + R1 - dj) < 0) sv = -1e30f;
                        sacc[j][2 + c2] = sv;
                        mx1 = fmaxf(mx1, sv);
                    }
                }
            }
            mx0 = fmaxf(mx0, __shfl_xor_sync(0xffffffffu, mx0, 1));
            mx0 = fmaxf(mx0, __shfl_xor_sync(0xffffffffu, mx0, 2));
            mx1 = fmaxf(mx1, __shfl_xor_sync(0xffffffffu, mx1, 1));
            mx1 = fmaxf(mx1, __shfl_xor_sync(0xffffffffu, mx1, 2));

            const float mn0 = fmaxf(mrow0, mx0), mn1 = fmaxf(mrow1, mx1);
            const float al0 = __expf(mrow0 - mn0), al1 = __expf(mrow1 - mn1);
            mrow0 = mn0; mrow1 = mn1;

            float rs0 = 0.0f, rs1 = 0.0f;
#pragma unroll
            for (int j = 0; j < 8; j++) {
#pragma unroll
                for (int c2 = 0; c2 < 2; c2++) {
                    float sv = sacc[j][c2];
                    float e  = __expf(sv - mn0);
                    if (sv < -1e29f) e = 0.0f;
                    rs0 += e; sacc[j][c2] = e;
                    sv = sacc[j][2 + c2];
                    e  = __expf(sv - mn1);
                    if (sv < -1e29f) e = 0.0f;
                    rs1 += e; sacc[j][2 + c2] = e;
                }
            }
            rs0 += __shfl_xor_sync(0xffffffffu, rs0, 1);
            rs0 += __shfl_xor_sync(0xffffffffu, rs0, 2);
            rs1 += __shfl_xor_sync(0xffffffffu, rs1, 1);
            rs1 += __shfl_xor_sync(0xffffffffu, rs1, 2);
            lrow0 = lrow0 * al0 + rs0;
            lrow1 = lrow1 * al1 + rs1;
#pragma unroll
            for (int j = 0; j < 8; j++) {
                accO[j][0] *= al0; accO[j][1] *= al0;
                accO[j][2] *= al1; accO[j][3] *= al1;
            }

            // ---- O += P @ V (single pass) ----
#pragma unroll
            for (int ks = 0; ks < 4; ks++) {
                u32 ph_[4];
                ph_[0] = round2h(sacc[2*ks][0],   sacc[2*ks][1]);
                ph_[1] = round2h(sacc[2*ks][2],   sacc[2*ks][3]);
                ph_[2] = round2h(sacc[2*ks+1][0], sacc[2*ks+1][1]);
                ph_[3] = round2h(sacc[2*ks+1][2], sacc[2*ks+1][3]);
                u32 bvh_[4][4];
#pragma unroll
                for (int ng = 0; ng < 4; ng++) {
                    const int row = 16 * ng + lr16;
                    const u32 off = (u32)(row * 128 + 16 * ((2 * ks + lc) ^ (row & 7)));
                    LDSM_X4(bvh_[ng], sVh + off);
                }
#pragma unroll
                for (int ng = 0; ng < 4; ng++) {
                    MMA_F16(accO[2*ng],   ph_, bvh_[ng][0], bvh_[ng][2]);
                    MMA_F16(accO[2*ng+1], ph_, bvh_[ng][1], bvh_[ng][3]);
                }
            }
            __syncthreads();
        }

        // ---- epilogue: normalize, fp16 out (A-op of FFN1) ----
        const float inv0 = 1.0f / lrow0, inv1 = 1.0f / lrow1;
        __half* o0h = oh + rowg0 * DD + h * DHH + 2 * t4;
#pragma unroll
        for (int j = 0; j < 8; j++) {
            *(u32*)(o0h + 8 * j)          = round2h(accO[j][0] * inv0, accO[j][1] * inv0);
            *(u32*)(o0h + 8 * DD + 8 * j) = round2h(accO[j][2] * inv1, accO[j][3] * inv1);
        }
    }
}

// ---------------------------------------------------------------------------
// Launch
// ---------------------------------------------------------------------------
extern "C" void kernel_launch(void* const* d_in, const int* in_sizes, int n_in,
                              void* d_out, int out_size)
{
    const float* x   = (const float*)d_in[0];
    // d_in[1] = mask — handled analytically
    const float* wq  = (const float*)d_in[2];
    const float* bq  = (const float*)d_in[3];
    const float* wk  = (const float*)d_in[4];
    const float* bk  = (const float*)d_in[5];
    const float* wv  = (const float*)d_in[6];
    const float* bv  = (const float*)d_in[7];
    const float* rel = (const float*)d_in[8];
    const float* w1  = (const float*)d_in[9];
    const float* b1  = (const float*)d_in[10];
    const float* w2  = (const float*)d_in[11];
    const float* b2  = (const float*)d_in[12];
    float* out = (float*)d_out;

    __half *xh, *qh, *kh, *vth, *relh, *ah, *hhp;
    __half *wqh, *wkh, *wvh, *w1h, *w2h;
    cudaGetSymbolAddress((void**)&xh,  g_xh);
    cudaGetSymbolAddress((void**)&qh,  g_qh);
    cudaGetSymbolAddress((void**)&kh,  g_kh);
    cudaGetSymbolAddress((void**)&vth, g_vth);
    cudaGetSymbolAddress((void**)&relh, g_relh);
    cudaGetSymbolAddress((void**)&ah,  g_ah);
    cudaGetSymbolAddress((void**)&hhp, g_hh);
    cudaGetSymbolAddress((void**)&wqh, g_wqh);
    cudaGetSymbolAddress((void**)&wkh, g_wkh);
    cudaGetSymbolAddress((void**)&wvh, g_wvh);
    cudaGetSymbolAddress((void**)&w1h, g_w1h);
    cudaGetSymbolAddress((void**)&w2h, g_w2h);

    cudaFuncSetAttribute(tgemm_kernel<0>,  cudaFuncAttributeMaxDynamicSharedMemorySize, TGN_SMEM);
    cudaFuncSetAttribute(tgemm_kernel<1>,  cudaFuncAttributeMaxDynamicSharedMemorySize, TGN_SMEM);
    cudaFuncSetAttribute(qkv_fused_kernel, cudaFuncAttributeMaxDynamicSharedMemorySize, TGN_SMEM);
    cudaFuncSetAttribute(attn_mma_kernel,  cudaFuncAttributeMaxDynamicSharedMemorySize, AT_SMEM);

    // 0) Prep
    conv_xrel_kernel<<<(N4X + N4R + 255) / 256, 256>>>(
        (const float4*)x, (const float4*)rel, xh, relh);
    tsplit3_kernel<<<dim3(DD / 32, DD / 32, 3), 256>>>(
        wq, wk, wv, wqh, wkh, wvh);
    tsplit_ffn_kernel<<<dim3(DFCN / 32, DD / 32, 2), 256>>>(
        w1, w2, w1h, w2h);

    // 1) Fused QKV (all single-pass; V^T transpose epilogue)
    qkv_fused_kernel<<<dim3(DD / 128, MM / 128, 3), 256, TGN_SMEM>>>(
        xh, wqh, wkh, wvh, bq, bk, bv, qh, kh, vth);

    // 2) HMMA flash attention with relative bias (single-pass fp16)
    attn_mma_kernel<<<128, 256, AT_SMEM>>>(qh, kh, vth, relh, ah);

    // 3) FFN (single-pass fp16)
    tgemm_kernel<1><<<dim3(DFCN / 128, MM / 128), 256, TGN_SMEM>>>(
        ah, w1h, b1, nullptr, hhp, MM, DFCN, DD);
    tgemm_kernel<0><<<dim3(DD / 128, MM / 128), 256, TGN_SMEM>>>(
        hhp, w2h, b2, out, nullptr, MM, DD, DFCN);
}

// round 15
// speedup vs baseline: 2.1204x; 1.0336x over previous
#include <cuda_runtime.h>
#include <cuda_fp16.h>
#include <cstdint>
#include <cstddef>

// ---------------------------------------------------------------------------
// Problem constants
// ---------------------------------------------------------------------------
#define BB   2
#define LL   2048
#define DD   512
#define HH   8
#define DHH  64
#define DFCN 2048
#define MM   (BB * LL)        // 4096 rows

typedef unsigned long long u64;
typedef unsigned int u32;

// ---------------------------------------------------------------------------
// Scratch (device globals) — single-fp16 pipeline, fp32 accumulate.
// ---------------------------------------------------------------------------
__device__ __half g_xh[MM * DD];                       // x
__device__ __half g_qh[MM * DD];                       // scaled Q
__device__ __half g_kh[MM * DD];                       // K
__device__ __half g_vth[BB*HH*DHH * LL];               // V^T
__device__ __half g_relh[LL * DD];                     // rel
__device__ __half g_ah[MM * DD];                       // attn out
__device__ __half g_hh[MM * DFCN];                     // FFN hidden
__device__ float  g_part[2 * MM * DD];                 // split-K partials (FFN2)

// Transposed weights: T[n][k] = W[k][n]
__device__ __half g_wqh[DD * DD];
__device__ __half g_wkh[DD * DD];
__device__ __half g_wvh[DD * DD];
__device__ __half g_w1h[DFCN * DD];
__device__ __half g_w2h[DD * DFCN];

// ---------------------------------------------------------------------------
// Helpers
// ---------------------------------------------------------------------------
__device__ __forceinline__ u32 smem_u32(const void* p) {
    u32 a;
    asm("{ .reg .u64 t; cvta.to.shared.u64 t, %1; cvt.u32.u64 %0, t; }"
        : "=r"(a) : "l"(p));
    return a;
}

__device__ __forceinline__ u32 round2h(float x, float y) {
    __half2 h = __floats2half2_rn(x, y);
    return *(u32*)&h;
}

#define LDSM_X4(r, addr) \
    asm volatile("ldmatrix.sync.aligned.m8n8.x4.shared.b16 {%0,%1,%2,%3}, [%4];" \
        : "=r"((r)[0]), "=r"((r)[1]), "=r"((r)[2]), "=r"((r)[3]) : "r"(addr))

#define MMA_F16(d, a, b0, b1) \
    asm volatile("mma.sync.aligned.m16n8k16.row.col.f32.f16.f16.f32 " \
        "{%0,%1,%2,%3}, {%4,%5,%6,%7}, {%8,%9}, {%0,%1,%2,%3};" \
        : "+f"((d)[0]), "+f"((d)[1]), "+f"((d)[2]), "+f"((d)[3]) \
        : "r"((a)[0]), "r"((a)[1]), "r"((a)[2]), "r"((a)[3]), "r"(b0), "r"(b1))

__device__ __forceinline__ void cp16(u32 dst, const void* src) {
    asm volatile("cp.async.cg.shared.global [%0], [%1], 16;"
                 :: "r"(dst), "l"(src) : "memory");
}
#define CP_COMMIT()  asm volatile("cp.async.commit_group;" ::: "memory")
#define CP_WAIT(n)   asm volatile("cp.async.wait_group %0;" :: "n"(n) : "memory")

// ---------------------------------------------------------------------------
// Prep kernels
// ---------------------------------------------------------------------------
__global__ __launch_bounds__(256)
void tsplit3_kernel(const float* __restrict__ wq, const float* __restrict__ wk,
                    const float* __restrict__ wv,
                    __half* __restrict__ qhh, __half* __restrict__ khh,
                    __half* __restrict__ vhh)
{
    const int z = blockIdx.z;
    const float* W = z == 0 ? wq : z == 1 ? wk : wv;
    __half* Th = z == 0 ? qhh : z == 1 ? khh : vhh;

    __shared__ float t[32][33];
    const int n0 = blockIdx.x * 32, k0 = blockIdx.y * 32;
    const int tx = threadIdx.x & 31, ty = threadIdx.x >> 5;
#pragma unroll
    for (int i = 0; i < 4; i++)
        t[ty + 8 * i][tx] = W[(size_t)(k0 + ty + 8 * i) * DD + n0 + tx];
    __syncthreads();
#pragma unroll
    for (int i = 0; i < 4; i++) {
        int n = n0 + ty + 8 * i;
        Th[(size_t)n * DD + k0 + tx] = __float2half_rn(t[tx][ty + 8 * i]);
    }
}

__global__ __launch_bounds__(256)
void tsplit_ffn_kernel(const float* __restrict__ w1, const float* __restrict__ w2,
                       __half* __restrict__ w1h, __half* __restrict__ w2h)
{
    const int z = blockIdx.z;
    const float* W = z == 0 ? w1 : w2;
    __half* Th = z == 0 ? w1h : w2h;
    const int K = z == 0 ? DD : DFCN;
    const int N = z == 0 ? DFCN : DD;
    const int n0 = (z == 0 ? blockIdx.x : blockIdx.y) * 32;
    const int k0 = (z == 0 ? blockIdx.y : blockIdx.x) * 32;

    __shared__ float t[32][33];
    const int tx = threadIdx.x & 31, ty = threadIdx.x >> 5;
#pragma unroll
    for (int i = 0; i < 4; i++)
        t[ty + 8 * i][tx] = W[(size_t)(k0 + ty + 8 * i) * N + n0 + tx];
    __syncthreads();
#pragma unroll
    for (int i = 0; i < 4; i++) {
        int n = n0 + ty + 8 * i;
        Th[(size_t)n * K + k0 + tx] = __float2half_rn(t[tx][ty + 8 * i]);
    }
}

#define N4X (MM * DD / 4)
#define N4R (LL * DD / 4)
__global__ __launch_bounds__(256)
void conv_xrel_kernel(const float4* __restrict__ X, const float4* __restrict__ R,
                      __half* __restrict__ XH, __half* __restrict__ RH)
{
    int i = blockIdx.x * blockDim.x + threadIdx.x;
    const float4* src; __half* H; int j;
    if (i < N4X) { src = X; H = XH; j = i; }
    else if (i < N4X + N4R) { src = R; H = RH; j = i - N4X; }
    else return;
    float4 v = src[j];
    uint2 hp;
    hp.x = round2h(v.x, v.y);
    hp.y = round2h(v.z, v.w);
    *(uint2*)(H + 4 * (size_t)j) = hp;
}

// Split-K reduce: out = p0 + p1 + bias
__global__ __launch_bounds__(256)
void reduce2_kernel(const float4* __restrict__ p0, const float4* __restrict__ p1,
                    const float* __restrict__ bias, float4* __restrict__ out)
{
    int i = blockIdx.x * blockDim.x + threadIdx.x;
    if (i >= N4X) return;
    float4 a = p0[i], b = p1[i];
    const float4 bs = *(const float4*)&bias[(4 * i) & (DD - 1)];
    out[i] = make_float4(a.x + b.x + bs.x, a.y + b.y + bs.y,
                         a.z + b.z + bs.z, a.w + b.w + bs.w);
}

// ---------------------------------------------------------------------------
// fp16 HMMA GEMM core: C = A @ B^T. BK=64, 3-stage cp.async ring, 128x128 CTA
// tile, 8 warps (2x4), 64x32 warp tile. 128B smem rows, conflict-free swizzle
// c ^= (r&7). Stage = A + B = 32KB; 3 stages = 96KB -> 2 CTAs/SM.
// ---------------------------------------------------------------------------
#define TGX_TILE  16384                 // 128 x 64 x 2B
#define TGX_STAGE (2 * TGX_TILE)        // 32KB
#define TGX_SMEM  (3 * TGX_STAGE)       // 96KB

__device__ __forceinline__ void load_tile64(const __half* __restrict__ src,
                                            int ldk, u32 sdst, int tid)
{
#pragma unroll
    for (int i = 0; i < 4; i++) {
        int idx = tid + 256 * i;
        int r = idx >> 3, c = idx & 7;
        cp16(sdst + r * 128 + 16 * (c ^ (r & 7)), src + (size_t)r * ldk + 8 * c);
    }
}

__device__ __forceinline__ void tgx_stage_load(
    u32 sdst, const __half* A, const __half* B, int ldk, int kofs, int tid)
{
    load_tile64(A + kofs, ldk, sdst,            tid);
    load_tile64(B + kofs, ldk, sdst + TGX_TILE, tid);
}

__device__ __forceinline__ void tgx_compute_chunk(
    u32 base, int wm, int wn, int lr16, int lc, float acc[4][4][4])
{
    const u32 sA = base, sB = base + TGX_TILE;
#pragma unroll
    for (int ks = 0; ks < 4; ks++) {
        const int ch = 2 * ks + lc;
        u32 bh[2][4];
#pragma unroll
        for (int ng = 0; ng < 2; ng++) {
            int r = wn * 32 + ng * 16 + lr16;
            u32 off = r * 128 + 16 * (ch ^ (r & 7));
            LDSM_X4(bh[ng], sB + off);
        }
#pragma unroll
        for (int mt = 0; mt < 4; mt++) {
            int r = wm * 64 + mt * 16 + lr16;
            u32 off = r * 128 + 16 * (ch ^ (r & 7));
            u32 ah[4];
            LDSM_X4(ah, sA + off);
#pragma unroll
            for (int nt = 0; nt < 4; nt++) {
                const int ng = nt >> 1, hi = nt & 1;
                MMA_F16(acc[mt][nt], ah, bh[ng][hi], bh[ng][2 + hi]);
            }
        }
    }
}

__device__ __forceinline__ void tgx_mainloop(
    u32 sb, const __half* Abase, const __half* Bbase,
    int ldk, int Klen, int tid, int wm, int wn, int lr16, int lc,
    float acc[4][4][4])
{
    const int NC = Klen >> 6;
    tgx_stage_load(sb, Abase, Bbase, ldk, 0, tid);
    CP_COMMIT();
    if (NC > 1) {
        tgx_stage_load(sb + TGX_STAGE, Abase, Bbase, ldk, 64, tid);
        CP_COMMIT();
    }
    int sc = 0, sn = 2;
    for (int c = 0; c < NC; c++) {
        CP_WAIT(1);
        __syncthreads();
        if (c + 2 < NC) {
            tgx_stage_load(sb + sn * TGX_STAGE, Abase, Bbase, ldk, (c + 2) * 64, tid);
            CP_COMMIT();
        } else {
            CP_COMMIT();
        }
        tgx_compute_chunk(sb + sc * TGX_STAGE, wm, wn, lr16, lc, acc);
        sc = sc == 2 ? 0 : sc + 1;
        sn = sn == 2 ? 0 : sn + 1;
    }
}

// MODE 0: fp32 + bias. MODE 1: relu + fp16 out. MODE 2: fp32 partial, no bias
// (split-K; blockIdx.z selects K half and output partial buffer).
template <int MODE>
__global__ __launch_bounds__(256, 2)
void tgemm_kernel(const __half* __restrict__ A,
                  const __half* __restrict__ B,
                  const float* __restrict__ bias,
                  float* __restrict__ Cf,
                  __half* __restrict__ Ch,
                  int M, int N, int ldk, int Klen)
{
    extern __shared__ char smem[];
    const u32 sb = smem_u32(smem);
    const int tid  = threadIdx.x;
    const int wid  = tid >> 5, lane = tid & 31;
    const int wm   = wid >> 2, wn = wid & 3;
    const int m0   = blockIdx.y * 128;
    const int n0   = blockIdx.x * 128;
    const int kofs = blockIdx.z * Klen;
    const int lr16 = lane & 15, lc = lane >> 4;

    float acc[4][4][4];
#pragma unroll
    for (int mt = 0; mt < 4; mt++)
#pragma unroll
        for (int nt = 0; nt < 4; nt++)
#pragma unroll
            for (int r = 0; r < 4; r++) acc[mt][nt][r] = 0.0f;

    tgx_mainloop(sb, A + (size_t)m0 * ldk + kofs, B + (size_t)n0 * ldk + kofs,
                 ldk, Klen, tid, wm, wn, lr16, lc, acc);

    float* Cfz = (MODE == 2) ? (Cf + (size_t)blockIdx.z * M * N) : Cf;
    const int tg = lane >> 2;
    const int tc = (lane & 3) * 2;
#pragma unroll
    for (int mt = 0; mt < 4; mt++) {
#pragma unroll
        for (int half_ = 0; half_ < 2; half_++) {
            const int m = m0 + wm * 64 + mt * 16 + tg + 8 * half_;
#pragma unroll
            for (int nt = 0; nt < 4; nt++) {
                const int n = n0 + wn * 32 + nt * 8 + tc;
                float v0 = acc[mt][nt][2 * half_];
                float v1 = acc[mt][nt][2 * half_ + 1];
                if (MODE == 2) {
                    *(float2*)(Cfz + (size_t)m * N + n) = make_float2(v0, v1);
                } else if (MODE == 0) {
                    *(float2*)(Cfz + (size_t)m * N + n) =
                        make_float2(v0 + bias[n], v1 + bias[n + 1]);
                } else {
                    v0 = fmaxf(v0 + bias[n], 0.0f);
                    v1 = fmaxf(v1 + bias[n + 1], 0.0f);
                    *(u32*)(Ch + (size_t)m * N + n) = round2h(v0, v1);
                }
            }
        }
    }
}

// Fused QKV: z=0 Q (scale 1/8), z=1 K, z=2 V (smem transpose -> V^T fp16).
__global__ __launch_bounds__(256, 2)
void qkv_fused_kernel(const __half* __restrict__ xh,
                      const __half* __restrict__ wqh,
                      const __half* __restrict__ wkh,
                      const __half* __restrict__ wvh,
                      const float* __restrict__ bq, const float* __restrict__ bk,
                      const float* __restrict__ bv,
                      __half* __restrict__ qh, __half* __restrict__ kh,
                      __half* __restrict__ vth)
{
    extern __shared__ char smem[];
    const u32 sb = smem_u32(smem);
    const int tid  = threadIdx.x;
    const int wid  = tid >> 5, lane = tid & 31;
    const int wm   = wid >> 2, wn = wid & 3;
    const int m0   = blockIdx.y * 128;
    const int n0   = blockIdx.x * 128;
    const int z    = blockIdx.z;
    const int lr16 = lane & 15, lc = lane >> 4;

    const __half* B = z == 0 ? wqh : z == 1 ? wkh : wvh;
    const float* bias = z == 0 ? bq : z == 1 ? bk : bv;

    float acc[4][4][4];
#pragma unroll
    for (int mt = 0; mt < 4; mt++)
#pragma unroll
        for (int nt = 0; nt < 4; nt++)
#pragma unroll
            for (int r = 0; r < 4; r++) acc[mt][nt][r] = 0.0f;

    tgx_mainloop(sb, xh + (size_t)m0 * DD, B + (size_t)n0 * DD,
                 DD, DD, tid, wm, wn, lr16, lc, acc);

    const int tg = lane >> 2;
    const int tc = (lane & 3) * 2;

    if (z < 2) {
        const float scl = (z == 0) ? 0.125f : 1.0f;
        __half* C = z == 0 ? qh : kh;
#pragma unroll
        for (int mt = 0; mt < 4; mt++)
#pragma unroll
            for (int half_ = 0; half_ < 2; half_++) {
                const int m = m0 + wm * 64 + mt * 16 + tg + 8 * half_;
#pragma unroll
                for (int nt = 0; nt < 4; nt++) {
                    const int n = n0 + wn * 32 + nt * 8 + tc;
                    float v0 = (acc[mt][nt][2 * half_]     + bias[n])     * scl;
                    float v1 = (acc[mt][nt][2 * half_ + 1] + bias[n + 1]) * scl;
                    *(u32*)(C + (size_t)m * DD + n) = round2h(v0, v1);
                }
            }
    } else {
        // V: stage fp32 tile (64-col halves), write transposed fp16 V^T.
        float* tile = (float*)smem;     // [128][68] fp32 = 34.8KB < 96KB
#pragma unroll 1
        for (int hf = 0; hf < 2; hf++) {
            __syncthreads();
#pragma unroll
            for (int mt = 0; mt < 4; mt++) {
#pragma unroll
                for (int half_ = 0; half_ < 2; half_++) {
                    const int ml = wm * 64 + mt * 16 + tg + 8 * half_;
#pragma unroll
                    for (int nt = 0; nt < 4; nt++) {
                        const int nl = wn * 32 + nt * 8 + tc;
                        if ((nl & 64) == (hf << 6)) {
                            const int nll = nl & 63;
                            tile[ml * 68 + nll]     = acc[mt][nt][2 * half_]     + bias[n0 + nl];
                            tile[ml * 68 + nll + 1] = acc[mt][nt][2 * half_ + 1] + bias[n0 + nl + 1];
                        }
                    }
                }
            }
            __syncthreads();
            const int b    = m0 >> 11;
            const int tok0 = m0 & 2047;
            const int nl   = tid >> 2;
            const int mh   = (tid & 3) * 32;
            const size_t orow = (size_t)(b * 512 + n0 + hf * 64 + nl) * LL + tok0 + mh;
#pragma unroll
            for (int it = 0; it < 4; it++) {
                u32 hp[4];
#pragma unroll
                for (int j2 = 0; j2 < 4; j2++) {
                    float v0 = tile[(mh + 8 * it + 2 * j2)     * 68 + nl];
                    float v1 = tile[(mh + 8 * it + 2 * j2 + 1) * 68 + nl];
                    hp[j2] = round2h(v0, v1);
                }
                *(uint4*)(vth + orow + 8 * it) = *(uint4*)hp;
            }
        }
    }
}

// ---------------------------------------------------------------------------
// HMMA flash attention: single-pass fp16 (S, R, PV), fp32 accumulate.
//   logits[i,j] = Qs_i.K_j + Qs_i.rel[2047-(i-j)]  (Qs pre-scaled 1/8)
// Stage tiles: kh, fh, vh (3 x 8KB = 24KB).
// ---------------------------------------------------------------------------
#define AT_STAGE 24576
#define AT_R3OFF (2 * AT_STAGE)
#define AT_RSTR  66
#define AT_SLOT  (128 * AT_RSTR)
#define AT_SMEM  (AT_R3OFF + 3 * AT_SLOT * 4)   // 150528

__device__ __forceinline__ void attn_load_stage(
    u32 dstbase, int j0, int t, int tid, int b, int h,
    const __half* __restrict__ kh,
    const __half* __restrict__ relh,
    const __half* __restrict__ vth)
{
    const int r0 = tid >> 3, c = tid & 7;
#pragma unroll
    for (int i = 0; i < 2; i++) {
        const int r = r0 + 32 * i;
        const u32 sw = (u32)(r * 128 + 16 * (c ^ (r & 7)));
        const size_t krow = (size_t)(b * LL + j0 + r) * DD + h * DHH + 8 * c;
        const size_t frow = (size_t)(2047 - 64 * t - r) * DD + h * DHH + 8 * c;
        const size_t vrow = (size_t)((b * 8 + h) * 64 + r) * LL + j0 + 8 * c;
        cp16(dstbase +          sw, kh   + krow);
        cp16(dstbase +  8192 +  sw, relh + frow);
        cp16(dstbase + 16384 +  sw, vth  + vrow);
    }
}

__global__ __launch_bounds__(256, 1)
void attn_mma_kernel(const __half* __restrict__ qh,
                     const __half* __restrict__ kh,
                     const __half* __restrict__ vth,
                     const __half* __restrict__ relh,
                     __half* __restrict__ oh)
{
    extern __shared__ char smem[];
    const u32 sb = smem_u32(smem);
    float* R3 = (float*)(smem + AT_R3OFF);

    const int tid = threadIdx.x, lane = tid & 31, w = tid >> 5;
    const int p   = blockIdx.x >> 4;
    const int bh  = blockIdx.x & 15;
    const int b   = bh >> 3, h = bh & 7;
    const int g   = lane >> 2, t4 = lane & 3;
    const int lr16 = lane & 15, lc = lane >> 4;

#pragma unroll 1
    for (int qq = 0; qq < 2; qq++) {
        const int q  = qq ? (15 - p) : p;
        const int i0 = q * 128;
        const int NT = 2 * q + 2;
        const int R0 = 16 * w + g, R1 = R0 + 8;
        const size_t rowg0 = (size_t)(b * LL + i0 + R0);

        u32 qfh[4][4];
        {
            const __half* ph_ = qh + rowg0 * DD + h * DHH + 2 * t4;
#pragma unroll
            for (int ks = 0; ks < 4; ks++) {
                qfh[ks][0] = *(const u32*)(ph_ + 16 * ks);
                qfh[ks][1] = *(const u32*)(ph_ + 16 * ks + 8 * DD);
                qfh[ks][2] = *(const u32*)(ph_ + 16 * ks + 8);
                qfh[ks][3] = *(const u32*)(ph_ + 16 * ks + 8 * DD + 8);
            }
        }

        float accO[8][4];
#pragma unroll
        for (int j = 0; j < 8; j++)
#pragma unroll
            for (int r = 0; r < 4; r++) accO[j][r] = 0.0f;
        float mrow0 = -1e30f, mrow1 = -1e30f, lrow0 = 0.0f, lrow1 = 0.0f;

        attn_load_stage(sb, i0 + 64, 0, tid, b, h, kh, relh, vth);
        CP_COMMIT();

#pragma unroll 1
        for (int t = 0; t < NT; t++) {
            const int j0 = i0 + 64 - 64 * t;
            if (t + 1 < NT) {
                attn_load_stage(sb + ((t + 1) & 1) * AT_STAGE, j0 - 64, t + 1,
                                tid, b, h, kh, relh, vth);
                CP_COMMIT();
                CP_WAIT(1);
            } else {
                CP_WAIT(0);
            }
            __syncthreads();

            const u32 st  = sb + (t & 1) * AT_STAGE;
            const u32 sKh = st, sFh = st + 8192, sVh = st + 16384;

            // ---- R = Qs @ Fchunk^T ----
            {
                float racc[8][4];
#pragma unroll
                for (int j = 0; j < 8; j++)
#pragma unroll
                    for (int r = 0; r < 4; r++) racc[j][r] = 0.0f;
#pragma unroll
                for (int ks = 0; ks < 4; ks++) {
                    u32 fh[4][4];
#pragma unroll
                    for (int ng = 0; ng < 4; ng++) {
                        const int row = 16 * ng + lr16;
                        const u32 off = (u32)(row * 128 + 16 * ((2 * ks + lc) ^ (row & 7)));
                        LDSM_X4(fh[ng], sFh + off);
                    }
#pragma unroll
                    for (int ng = 0; ng < 4; ng++) {
                        MMA_F16(racc[2*ng],   qfh[ks], fh[ng][0], fh[ng][2]);
                        MMA_F16(racc[2*ng+1], qfh[ks], fh[ng][1], fh[ng][3]);
                    }
                }
                float* Rb = R3 + (t % 3) * AT_SLOT;
#pragma unroll
                for (int j = 0; j < 8; j++) {
                    *(float2*)&Rb[R0 * AT_RSTR + 8 * j + 2 * t4] = make_float2(racc[j][0], racc[j][1]);
                    *(float2*)&Rb[R1 * AT_RSTR + 8 * j + 2 * t4] = make_float2(racc[j][2], racc[j][3]);
                }
            }
            __syncwarp();

            // ---- S = Qs @ K^T ----
            float sacc[8][4];
#pragma unroll
            for (int j = 0; j < 8; j++)
#pragma unroll
                for (int r = 0; r < 4; r++) sacc[j][r] = 0.0f;
#pragma unroll
            for (int ks = 0; ks < 4; ks++) {
                u32 bkh_[4][4];
#pragma unroll
                for (int ng = 0; ng < 4; ng++) {
                    const int row = 16 * ng + lr16;
                    const u32 off = (u32)(row * 128 + 16 * ((2 * ks + lc) ^ (row & 7)));
                    LDSM_X4(bkh_[ng], sKh + off);
                }
#pragma unroll
                for (int ng = 0; ng < 4; ng++) {
                    MMA_F16(sacc[2*ng],   qfh[ks], bkh_[ng][0], bkh_[ng][2]);
                    MMA_F16(sacc[2*ng+1], qfh[ks], bkh_[ng][1], bkh_[ng][3]);
                }
            }

            // ---- gather skew bias + mask + online softmax ----
            float mx0 = -1e30f, mx1 = -1e30f;
#pragma unroll
            for (int j = 0; j < 8; j++) {
#pragma unroll
                for (int c2 = 0; c2 < 2; c2++) {
                    const int dj = 8 * j + 2 * t4 + c2;
                    {
                        const int e = 64 + R0 - dj;
                        const int slot = (t + 1 + (e >> 6)) % 3;
                        float sv = sacc[j][c2] + R3[slot * AT_SLOT + R0 * AT_RSTR + (e & 63)];
                        if (t < 2 && (64 * (t - 1) + R0 - dj) < 0) sv = -1e30f;
                        sacc[j][c2] = sv;
                        mx0 = fmaxf(mx0, sv);
                    }
                    {
                        const int e = 64 + R1 - dj;
                        const int slot = (t + 1 + (e >> 6)) % 3;
                        float sv = sacc[j][2 + c2] + R3[slot * AT_SLOT + R1 * AT_RSTR + (e & 63)];
                        if (t < 2 && (64 * (t - 1) + R1 - dj) < 0) sv = -1e30f;
                        sacc[j][2 + c2] = sv;
                        mx1 = fmaxf(mx1, sv);
                    }
                }
            }
            mx0 = fmaxf(mx0, __shfl_xor_sync(0xffffffffu, mx0, 1));
            mx0 = fmaxf(mx0, __shfl_xor_sync(0xffffffffu, mx0, 2));
            mx1 = fmaxf(mx1, __shfl_xor_sync(0xffffffffu, mx1, 1));
            mx1 = fmaxf(mx1, __shfl_xor_sync(0xffffffffu, mx1, 2));

            const float mn0 = fmaxf(mrow0, mx0), mn1 = fmaxf(mrow1, mx1);
            const float al0 = __expf(mrow0 - mn0), al1 = __expf(mrow1 - mn1);
            mrow0 = mn0; mrow1 = mn1;

            float rs0 = 0.0f, rs1 = 0.0f;
#pragma unroll
            for (int j = 0; j < 8; j++) {
#pragma unroll
                for (int c2 = 0; c2 < 2; c2++) {
                    float sv = sacc[j][c2];
                    float e  = __expf(sv - mn0);
                    if (sv < -1e29f) e = 0.0f;
                    rs0 += e; sacc[j][c2] = e;
                    sv = sacc[j][2 + c2];
                    e  = __expf(sv - mn1);
                    if (sv < -1e29f) e = 0.0f;
                    rs1 += e; sacc[j][2 + c2] = e;
                }
            }
            rs0 += __shfl_xor_sync(0xffffffffu, rs0, 1);
            rs0 += __shfl_xor_sync(0xffffffffu, rs0, 2);
            rs1 += __shfl_xor_sync(0xffffffffu, rs1, 1);
            rs1 += __shfl_xor_sync(0xffffffffu, rs1, 2);
            lrow0 = lrow0 * al0 + rs0;
            lrow1 = lrow1 * al1 + rs1;
#pragma unroll
            for (int j = 0; j < 8; j++) {
                accO[j][0] *= al0; accO[j][1] *= al0;
                accO[j][2] *= al1; accO[j][3] *= al1;
            }

            // ---- O += P @ V ----
#pragma unroll
            for (int ks = 0; ks < 4; ks++) {
                u32 ph_[4];
                ph_[0] = round2h(sacc[2*ks][0],   sacc[2*ks][1]);
                ph_[1] = round2h(sacc[2*ks][2],   sacc[2*ks][3]);
                ph_[2] = round2h(sacc[2*ks+1][0], sacc[2*ks+1][1]);
                ph_[3] = round2h(sacc[2*ks+1][2], sacc[2*ks+1][3]);
                u32 bvh_[4][4];
#pragma unroll
                for (int ng = 0; ng < 4; ng++) {
                    const int row = 16 * ng + lr16;
                    const u32 off = (u32)(row * 128 + 16 * ((2 * ks + lc) ^ (row & 7)));
                    LDSM_X4(bvh_[ng], sVh + off);
                }
#pragma unroll
                for (int ng = 0; ng < 4; ng++) {
                    MMA_F16(accO[2*ng],   ph_, bvh_[ng][0], bvh_[ng][2]);
                    MMA_F16(accO[2*ng+1], ph_, bvh_[ng][1], bvh_[ng][3]);
                }
            }
            __syncthreads();
        }

        // ---- epilogue: normalize, fp16 out (A-op of FFN1) ----
        const float inv0 = 1.0f / lrow0, inv1 = 1.0f / lrow1;
        __half* o0h = oh + rowg0 * DD + h * DHH + 2 * t4;
#pragma unroll
        for (int j = 0; j < 8; j++) {
            *(u32*)(o0h + 8 * j)          = round2h(accO[j][0] * inv0, accO[j][1] * inv0);
            *(u32*)(o0h + 8 * DD + 8 * j) = round2h(accO[j][2] * inv1, accO[j][3] * inv1);
        }
    }
}

// ---------------------------------------------------------------------------
// Launch
// ---------------------------------------------------------------------------
extern "C" void kernel_launch(void* const* d_in, const int* in_sizes, int n_in,
                              void* d_out, int out_size)
{
    const float* x   = (const float*)d_in[0];
    // d_in[1] = mask — handled analytically
    const float* wq  = (const float*)d_in[2];
    const float* bq  = (const float*)d_in[3];
    const float* wk  = (const float*)d_in[4];
    const float* bk  = (const float*)d_in[5];
    const float* wv  = (const float*)d_in[6];
    const float* bv  = (const float*)d_in[7];
    const float* rel = (const float*)d_in[8];
    const float* w1  = (const float*)d_in[9];
    const float* b1  = (const float*)d_in[10];
    const float* w2  = (const float*)d_in[11];
    const float* b2  = (const float*)d_in[12];
    float* out = (float*)d_out;

    __half *xh, *qh, *kh, *vth, *relh, *ah, *hhp;
    __half *wqh, *wkh, *wvh, *w1h, *w2h;
    float* part;
    cudaGetSymbolAddress((void**)&xh,  g_xh);
    cudaGetSymbolAddress((void**)&qh,  g_qh);
    cudaGetSymbolAddress((void**)&kh,  g_kh);
    cudaGetSymbolAddress((void**)&vth, g_vth);
    cudaGetSymbolAddress((void**)&relh, g_relh);
    cudaGetSymbolAddress((void**)&ah,  g_ah);
    cudaGetSymbolAddress((void**)&hhp, g_hh);
    cudaGetSymbolAddress((void**)&part, g_part);
    cudaGetSymbolAddress((void**)&wqh, g_wqh);
    cudaGetSymbolAddress((void**)&wkh, g_wkh);
    cudaGetSymbolAddress((void**)&wvh, g_wvh);
    cudaGetSymbolAddress((void**)&w1h, g_w1h);
    cudaGetSymbolAddress((void**)&w2h, g_w2h);

    cudaFuncSetAttribute(tgemm_kernel<1>,  cudaFuncAttributeMaxDynamicSharedMemorySize, TGX_SMEM);
    cudaFuncSetAttribute(tgemm_kernel<2>,  cudaFuncAttributeMaxDynamicSharedMemorySize, TGX_SMEM);
    cudaFuncSetAttribute(qkv_fused_kernel, cudaFuncAttributeMaxDynamicSharedMemorySize, TGX_SMEM);
    cudaFuncSetAttribute(attn_mma_kernel,  cudaFuncAttributeMaxDynamicSharedMemorySize, AT_SMEM);

    // 0) Prep
    conv_xrel_kernel<<<(N4X + N4R + 255) / 256, 256>>>(
        (const float4*)x, (const float4*)rel, xh, relh);
    tsplit3_kernel<<<dim3(DD / 32, DD / 32, 3), 256>>>(
        wq, wk, wv, wqh, wkh, wvh);
    tsplit_ffn_kernel<<<dim3(DFCN / 32, DD / 32, 2), 256>>>(
        w1, w2, w1h, w2h);

    // 1) Fused QKV
    qkv_fused_kernel<<<dim3(DD / 128, MM / 128, 3), 256, TGX_SMEM>>>(
        xh, wqh, wkh, wvh, bq, bk, bv, qh, kh, vth);

    // 2) HMMA flash attention with relative bias
    attn_mma_kernel<<<128, 256, AT_SMEM>>>(qh, kh, vth, relh, ah);

    // 3) FFN: FFN1 (relu, fp16 out); FFN2 split-K (2 halves) + reduce
    tgemm_kernel<1><<<dim3(DFCN / 128, MM / 128), 256, TGX_SMEM>>>(
        ah, w1h, b1, nullptr, hhp, MM, DFCN, DD, DD);
    tgemm_kernel<2><<<dim3(DD / 128, MM / 128, 2), 256, TGX_SMEM>>>(
        hhp, w2h, nullptr, part, nullptr, MM, DD, DFCN, DFCN / 2);
    reduce2_kernel<<<(N4X + 255) / 256, 256>>>(
        (const float4*)part, (const float4*)(part + (size_t)MM * DD), b2,
        (float4*)out);
}

// round 16
// speedup vs baseline: 2.1988x; 1.0370x over previous
#include <cuda_runtime.h>
#include <cuda_fp16.h>
#include <cstdint>
#include <cstddef>

// ---------------------------------------------------------------------------
// Problem constants
// ---------------------------------------------------------------------------
#define BB   2
#define LL   2048
#define DD   512
#define HH   8
#define DHH  64
#define DFCN 2048
#define MM   (BB * LL)        // 4096 rows

typedef unsigned long long u64;
typedef unsigned int u32;

// ---------------------------------------------------------------------------
// Scratch (device globals) — single-fp16 pipeline, fp32 accumulate.
// ---------------------------------------------------------------------------
__device__ __half g_xh[MM * DD];                       // x
__device__ __half g_qh[MM * DD];                       // Q scaled by log2e/8
__device__ __half g_kh[MM * DD];                       // K
__device__ __half g_vth[BB*HH*DHH * LL];               // V^T
__device__ __half g_relh[LL * DD];                     // rel
__device__ __half g_ah[MM * DD];                       // attn out
__device__ __half g_hh[MM * DFCN];                     // FFN hidden
__device__ float  g_part[2 * MM * DD];                 // split-K partials (FFN2)

// Transposed weights: T[n][k] = W[k][n]
__device__ __half g_wqh[DD * DD];
__device__ __half g_wkh[DD * DD];
__device__ __half g_wvh[DD * DD];
__device__ __half g_w1h[DFCN * DD];
__device__ __half g_w2h[DD * DFCN];

// ---------------------------------------------------------------------------
// Helpers
// ---------------------------------------------------------------------------
__device__ __forceinline__ u32 smem_u32(const void* p) {
    u32 a;
    asm("{ .reg .u64 t; cvta.to.shared.u64 t, %1; cvt.u32.u64 %0, t; }"
        : "=r"(a) : "l"(p));
    return a;
}

__device__ __forceinline__ u32 round2h(float x, float y) {
    __half2 h = __floats2half2_rn(x, y);
    return *(u32*)&h;
}

#define LDSM_X4(r, addr) \
    asm volatile("ldmatrix.sync.aligned.m8n8.x4.shared.b16 {%0,%1,%2,%3}, [%4];" \
        : "=r"((r)[0]), "=r"((r)[1]), "=r"((r)[2]), "=r"((r)[3]) : "r"(addr))

#define MMA_F16(d, a, b0, b1) \
    asm volatile("mma.sync.aligned.m16n8k16.row.col.f32.f16.f16.f32 " \
        "{%0,%1,%2,%3}, {%4,%5,%6,%7}, {%8,%9}, {%0,%1,%2,%3};" \
        : "+f"((d)[0]), "+f"((d)[1]), "+f"((d)[2]), "+f"((d)[3]) \
        : "r"((a)[0]), "r"((a)[1]), "r"((a)[2]), "r"((a)[3]), "r"(b0), "r"(b1))

__device__ __forceinline__ void cp16(u32 dst, const void* src) {
    asm volatile("cp.async.cg.shared.global [%0], [%1], 16;"
                 :: "r"(dst), "l"(src) : "memory");
}
#define CP_COMMIT()  asm volatile("cp.async.commit_group;" ::: "memory")
#define CP_WAIT(n)   asm volatile("cp.async.wait_group %0;" :: "n"(n) : "memory")

// ---------------------------------------------------------------------------
// Fused prep: one launch does x/rel fp16 convert + wq/wk/wv/w1/w2 transposes.
// Block layout: [0, NB_CONV)            convert sections
//               [NB_CONV, +768)         wq/wk/wv transpose (3 x 16 x 16)
//               [.., +2048)             w1/w2 transpose (2 x 64 x 16)
// ---------------------------------------------------------------------------
#define N4X (MM * DD / 4)
#define N4R (LL * DD / 4)
#define NB_CONV ((N4X + N4R) / 256)     // 3072
#define NB_W3   768
#define NB_FFN  2048
#define NB_PREP (NB_CONV + NB_W3 + NB_FFN)

__global__ __launch_bounds__(256)
void prep_all_kernel(const float4* __restrict__ X, const float4* __restrict__ R,
                     const float* __restrict__ wq, const float* __restrict__ wk,
                     const float* __restrict__ wv,
                     const float* __restrict__ w1, const float* __restrict__ w2,
                     __half* __restrict__ XH, __half* __restrict__ RH,
                     __half* __restrict__ wqh, __half* __restrict__ wkh,
                     __half* __restrict__ wvh,
                     __half* __restrict__ w1h, __half* __restrict__ w2h)
{
    const int bid = blockIdx.x;
    if (bid < NB_CONV) {
        int i = bid * 256 + threadIdx.x;
        const float4* src; __half* H; int j;
        if (i < N4X) { src = X; H = XH; j = i; }
        else         { src = R; H = RH; j = i - N4X; }
        float4 v = src[j];
        uint2 hp;
        hp.x = round2h(v.x, v.y);
        hp.y = round2h(v.z, v.w);
        *(uint2*)(H + 4 * (size_t)j) = hp;
        return;
    }

    __shared__ float t[32][33];
    const int tx = threadIdx.x & 31, ty = threadIdx.x >> 5;
    const float* W; __half* Th; int K, N, n0, k0;

    int wb = bid - NB_CONV;
    if (wb < NB_W3) {
        const int z = wb >> 8, r = wb & 255;
        W  = z == 0 ? wq : z == 1 ? wk : wv;
        Th = z == 0 ? wqh : z == 1 ? wkh : wvh;
        K = DD; N = DD;
        n0 = (r & 15) * 32; k0 = (r >> 4) * 32;
    } else {
        int wb2 = wb - NB_W3;
        const int z = wb2 >> 10, r = wb2 & 1023;
        W  = z == 0 ? w1 : w2;
        Th = z == 0 ? w1h : w2h;
        K = z == 0 ? DD : DFCN;
        N = z == 0 ? DFCN : DD;
        const int bx = r & 63, by = r >> 6;
        n0 = (z == 0 ? bx : by) * 32;
        k0 = (z == 0 ? by : bx) * 32;
    }

#pragma unroll
    for (int i = 0; i < 4; i++)
        t[ty + 8 * i][tx] = W[(size_t)(k0 + ty + 8 * i) * N + n0 + tx];
    __syncthreads();
#pragma unroll
    for (int i = 0; i < 4; i++) {
        int n = n0 + ty + 8 * i;
        Th[(size_t)n * K + k0 + tx] = __float2half_rn(t[tx][ty + 8 * i]);
    }
}

// Split-K reduce: out = p0 + p1 + bias
__global__ __launch_bounds__(256)
void reduce2_kernel(const float4* __restrict__ p0, const float4* __restrict__ p1,
                    const float* __restrict__ bias, float4* __restrict__ out)
{
    int i = blockIdx.x * blockDim.x + threadIdx.x;
    if (i >= N4X) return;
    float4 a = p0[i], b = p1[i];
    const float4 bs = *(const float4*)&bias[(4 * i) & (DD - 1)];
    out[i] = make_float4(a.x + b.x + bs.x, a.y + b.y + bs.y,
                         a.z + b.z + bs.z, a.w + b.w + bs.w);
}

// ---------------------------------------------------------------------------
// fp16 HMMA GEMM core: C = A @ B^T. BK=64, 3-stage cp.async ring, 128x128 CTA
// tile, 8 warps (2x4), 64x32 warp tile. 128B smem rows, swizzle c ^= (r&7).
// Stage = 32KB; 3 stages = 96KB -> 2 CTAs/SM.
// ---------------------------------------------------------------------------
#define TGX_TILE  16384
#define TGX_STAGE (2 * TGX_TILE)
#define TGX_SMEM  (3 * TGX_STAGE)

__device__ __forceinline__ void load_tile64(const __half* __restrict__ src,
                                            int ldk, u32 sdst, int tid)
{
#pragma unroll
    for (int i = 0; i < 4; i++) {
        int idx = tid + 256 * i;
        int r = idx >> 3, c = idx & 7;
        cp16(sdst + r * 128 + 16 * (c ^ (r & 7)), src + (size_t)r * ldk + 8 * c);
    }
}

__device__ __forceinline__ void tgx_stage_load(
    u32 sdst, const __half* A, const __half* B, int ldk, int kofs, int tid)
{
    load_tile64(A + kofs, ldk, sdst,            tid);
    load_tile64(B + kofs, ldk, sdst + TGX_TILE, tid);
}

__device__ __forceinline__ void tgx_compute_chunk(
    u32 base, int wm, int wn, int lr16, int lc, float acc[4][4][4])
{
    const u32 sA = base, sB = base + TGX_TILE;
#pragma unroll
    for (int ks = 0; ks < 4; ks++) {
        const int ch = 2 * ks + lc;
        u32 bh[2][4];
#pragma unroll
        for (int ng = 0; ng < 2; ng++) {
            int r = wn * 32 + ng * 16 + lr16;
            u32 off = r * 128 + 16 * (ch ^ (r & 7));
            LDSM_X4(bh[ng], sB + off);
        }
#pragma unroll
        for (int mt = 0; mt < 4; mt++) {
            int r = wm * 64 + mt * 16 + lr16;
            u32 off = r * 128 + 16 * (ch ^ (r & 7));
            u32 ah[4];
            LDSM_X4(ah, sA + off);
#pragma unroll
            for (int nt = 0; nt < 4; nt++) {
                const int ng = nt >> 1, hi = nt & 1;
                MMA_F16(acc[mt][nt], ah, bh[ng][hi], bh[ng][2 + hi]);
            }
        }
    }
}

__device__ __forceinline__ void tgx_mainloop(
    u32 sb, const __half* Abase, const __half* Bbase,
    int ldk, int Klen, int tid, int wm, int wn, int lr16, int lc,
    float acc[4][4][4])
{
    const int NC = Klen >> 6;
    tgx_stage_load(sb, Abase, Bbase, ldk, 0, tid);
    CP_COMMIT();
    if (NC > 1) {
        tgx_stage_load(sb + TGX_STAGE, Abase, Bbase, ldk, 64, tid);
        CP_COMMIT();
    }
    int sc = 0, sn = 2;
    for (int c = 0; c < NC; c++) {
        CP_WAIT(1);
        __syncthreads();
        if (c + 2 < NC) {
            tgx_stage_load(sb + sn * TGX_STAGE, Abase, Bbase, ldk, (c + 2) * 64, tid);
            CP_COMMIT();
        } else {
            CP_COMMIT();
        }
        tgx_compute_chunk(sb + sc * TGX_STAGE, wm, wn, lr16, lc, acc);
        sc = sc == 2 ? 0 : sc + 1;
        sn = sn == 2 ? 0 : sn + 1;
    }
}

// MODE 1: relu + fp16 out. MODE 2: fp32 partial, no bias (split-K via z).
template <int MODE>
__global__ __launch_bounds__(256, 2)
void tgemm_kernel(const __half* __restrict__ A,
                  const __half* __restrict__ B,
                  const float* __restrict__ bias,
                  float* __restrict__ Cf,
                  __half* __restrict__ Ch,
                  int M, int N, int ldk, int Klen)
{
    extern __shared__ char smem[];
    const u32 sb = smem_u32(smem);
    const int tid  = threadIdx.x;
    const int wid  = tid >> 5, lane = tid & 31;
    const int wm   = wid >> 2, wn = wid & 3;
    const int m0   = blockIdx.y * 128;
    const int n0   = blockIdx.x * 128;
    const int kofs = blockIdx.z * Klen;
    const int lr16 = lane & 15, lc = lane >> 4;

    float acc[4][4][4];
#pragma unroll
    for (int mt = 0; mt < 4; mt++)
#pragma unroll
        for (int nt = 0; nt < 4; nt++)
#pragma unroll
            for (int r = 0; r < 4; r++) acc[mt][nt][r] = 0.0f;

    tgx_mainloop(sb, A + (size_t)m0 * ldk + kofs, B + (size_t)n0 * ldk + kofs,
                 ldk, Klen, tid, wm, wn, lr16, lc, acc);

    float* Cfz = (MODE == 2) ? (Cf + (size_t)blockIdx.z * M * N) : Cf;
    const int tg = lane >> 2;
    const int tc = (lane & 3) * 2;
#pragma unroll
    for (int mt = 0; mt < 4; mt++) {
#pragma unroll
        for (int half_ = 0; half_ < 2; half_++) {
            const int m = m0 + wm * 64 + mt * 16 + tg + 8 * half_;
#pragma unroll
            for (int nt = 0; nt < 4; nt++) {
                const int n = n0 + wn * 32 + nt * 8 + tc;
                float v0 = acc[mt][nt][2 * half_];
                float v1 = acc[mt][nt][2 * half_ + 1];
                if (MODE == 2) {
                    *(float2*)(Cfz + (size_t)m * N + n) = make_float2(v0, v1);
                } else {
                    v0 = fmaxf(v0 + bias[n], 0.0f);
                    v1 = fmaxf(v1 + bias[n + 1], 0.0f);
                    *(u32*)(Ch + (size_t)m * N + n) = round2h(v0, v1);
                }
            }
        }
    }
}

// Fused QKV: z=0 Q (scale log2e/8), z=1 K, z=2 V (smem transpose -> V^T fp16).
__global__ __launch_bounds__(256, 2)
void qkv_fused_kernel(const __half* __restrict__ xh,
                      const __half* __restrict__ wqh,
                      const __half* __restrict__ wkh,
                      const __half* __restrict__ wvh,
                      const float* __restrict__ bq, const float* __restrict__ bk,
                      const float* __restrict__ bv,
                      __half* __restrict__ qh, __half* __restrict__ kh,
                      __half* __restrict__ vth)
{
    extern __shared__ char smem[];
    const u32 sb = smem_u32(smem);
    const int tid  = threadIdx.x;
    const int wid  = tid >> 5, lane = tid & 31;
    const int wm   = wid >> 2, wn = wid & 3;
    const int m0   = blockIdx.y * 128;
    const int n0   = blockIdx.x * 128;
    const int z    = blockIdx.z;
    const int lr16 = lane & 15, lc = lane >> 4;

    const __half* B = z == 0 ? wqh : z == 1 ? wkh : wvh;
    const float* bias = z == 0 ? bq : z == 1 ? bk : bv;

    float acc[4][4][4];
#pragma unroll
    for (int mt = 0; mt < 4; mt++)
#pragma unroll
        for (int nt = 0; nt < 4; nt++)
#pragma unroll
            for (int r = 0; r < 4; r++) acc[mt][nt][r] = 0.0f;

    tgx_mainloop(sb, xh + (size_t)m0 * DD, B + (size_t)n0 * DD,
                 DD, DD, tid, wm, wn, lr16, lc, acc);

    const int tg = lane >> 2;
    const int tc = (lane & 3) * 2;

    if (z < 2) {
        // Q scale folds softmax 1/sqrt(64) AND log2(e) so attention can exp2.
        const float scl = (z == 0) ? (0.125f * 1.4426950408889634f) : 1.0f;
        __half* C = z == 0 ? qh : kh;
#pragma unroll
        for (int mt = 0; mt < 4; mt++)
#pragma unroll
            for (int half_ = 0; half_ < 2; half_++) {
                const int m = m0 + wm * 64 + mt * 16 + tg + 8 * half_;
#pragma unroll
                for (int nt = 0; nt < 4; nt++) {
                    const int n = n0 + wn * 32 + nt * 8 + tc;
                    float v0 = (acc[mt][nt][2 * half_]     + bias[n])     * scl;
                    float v1 = (acc[mt][nt][2 * half_ + 1] + bias[n + 1]) * scl;
                    *(u32*)(C + (size_t)m * DD + n) = round2h(v0, v1);
                }
            }
    } else {
        // V: stage fp32 tile (64-col halves), write transposed fp16 V^T.
        float* tile = (float*)smem;     // [128][68] fp32
#pragma unroll 1
        for (int hf = 0; hf < 2; hf++) {
            __syncthreads();
#pragma unroll
            for (int mt = 0; mt < 4; mt++) {
#pragma unroll
                for (int half_ = 0; half_ < 2; half_++) {
                    const int ml = wm * 64 + mt * 16 + tg + 8 * half_;
#pragma unroll
                    for (int nt = 0; nt < 4; nt++) {
                        const int nl = wn * 32 + nt * 8 + tc;
                        if ((nl & 64) == (hf << 6)) {
                            const int nll = nl & 63;
                            tile[ml * 68 + nll]     = acc[mt][nt][2 * half_]     + bias[n0 + nl];
                            tile[ml * 68 + nll + 1] = acc[mt][nt][2 * half_ + 1] + bias[n0 + nl + 1];
                        }
                    }
                }
            }
            __syncthreads();
            const int b    = m0 >> 11;
            const int tok0 = m0 & 2047;
            const int nl   = tid >> 2;
            const int mh   = (tid & 3) * 32;
            const size_t orow = (size_t)(b * 512 + n0 + hf * 64 + nl) * LL + tok0 + mh;
#pragma unroll
            for (int it = 0; it < 4; it++) {
                u32 hp[4];
#pragma unroll
                for (int j2 = 0; j2 < 4; j2++) {
                    float v0 = tile[(mh + 8 * it + 2 * j2)     * 68 + nl];
                    float v1 = tile[(mh + 8 * it + 2 * j2 + 1) * 68 + nl];
                    hp[j2] = round2h(v0, v1);
                }
                *(uint4*)(vth + orow + 8 * it) = *(uint4*)hp;
            }
        }
    }
}

// ---------------------------------------------------------------------------
// HMMA flash attention: single-pass fp16 (S, R, PV), fp32 accumulate.
//   logits2[i,j] = Qs_i.K_j + Qs_i.rel[2047-(i-j)]   (already x log2e/8)
//   softmax via exp2.
// ---------------------------------------------------------------------------
#define AT_STAGE 24576
#define AT_R3OFF (2 * AT_STAGE)
#define AT_RSTR  66
#define AT_SLOT  (128 * AT_RSTR)
#define AT_SMEM  (AT_R3OFF + 3 * AT_SLOT * 4)   // 150528

__device__ __forceinline__ void attn_load_stage(
    u32 dstbase, int j0, int t, int tid, int b, int h,
    const __half* __restrict__ kh,
    const __half* __restrict__ relh,
    const __half* __restrict__ vth)
{
    const int r0 = tid >> 3, c = tid & 7;
#pragma unroll
    for (int i = 0; i < 2; i++) {
        const int r = r0 + 32 * i;
        const u32 sw = (u32)(r * 128 + 16 * (c ^ (r & 7)));
        const size_t krow = (size_t)(b * LL + j0 + r) * DD + h * DHH + 8 * c;
        const size_t frow = (size_t)(2047 - 64 * t - r) * DD + h * DHH + 8 * c;
        const size_t vrow = (size_t)((b * 8 + h) * 64 + r) * LL + j0 + 8 * c;
        cp16(dstbase +          sw, kh   + krow);
        cp16(dstbase +  8192 +  sw, relh + frow);
        cp16(dstbase + 16384 +  sw, vth  + vrow);
    }
}

__global__ __launch_bounds__(256, 1)
void attn_mma_kernel(const __half* __restrict__ qh,
                     const __half* __restrict__ kh,
                     const __half* __restrict__ vth,
                     const __half* __restrict__ relh,
                     __half* __restrict__ oh)
{
    extern __shared__ char smem[];
    const u32 sb = smem_u32(smem);
    float* R3 = (float*)(smem + AT_R3OFF);

    const int tid = threadIdx.x, lane = tid & 31, w = tid >> 5;
    const int p   = blockIdx.x >> 4;
    const int bh  = blockIdx.x & 15;
    const int b   = bh >> 3, h = bh & 7;
    const int g   = lane >> 2, t4 = lane & 3;
    const int lr16 = lane & 15, lc = lane >> 4;

#pragma unroll 1
    for (int qq = 0; qq < 2; qq++) {
        const int q  = qq ? (15 - p) : p;
        const int i0 = q * 128;
        const int NT = 2 * q + 2;
        const int R0 = 16 * w + g, R1 = R0 + 8;
        const size_t rowg0 = (size_t)(b * LL + i0 + R0);

        u32 qfh[4][4];
        {
            const __half* ph_ = qh + rowg0 * DD + h * DHH + 2 * t4;
#pragma unroll
            for (int ks = 0; ks < 4; ks++) {
                qfh[ks][0] = *(const u32*)(ph_ + 16 * ks);
                qfh[ks][1] = *(const u32*)(ph_ + 16 * ks + 8 * DD);
                qfh[ks][2] = *(const u32*)(ph_ + 16 * ks + 8);
                qfh[ks][3] = *(const u32*)(ph_ + 16 * ks + 8 * DD + 8);
            }
        }

        float accO[8][4];
#pragma unroll
        for (int j = 0; j < 8; j++)
#pragma unroll
            for (int r = 0; r < 4; r++) accO[j][r] = 0.0f;
        float mrow0 = -1e30f, mrow1 = -1e30f, lrow0 = 0.0f, lrow1 = 0.0f;

        attn_load_stage(sb, i0 + 64, 0, tid, b, h, kh, relh, vth);
        CP_COMMIT();

#pragma unroll 1
        for (int t = 0; t < NT; t++) {
            const int j0 = i0 + 64 - 64 * t;
            if (t + 1 < NT) {
                attn_load_stage(sb + ((t + 1) & 1) * AT_STAGE, j0 - 64, t + 1,
                                tid, b, h, kh, relh, vth);
                CP_COMMIT();
                CP_WAIT(1);
            } else {
                CP_WAIT(0);
            }
            __syncthreads();

            const u32 st  = sb + (t & 1) * AT_STAGE;
            const u32 sKh = st, sFh = st + 8192, sVh = st + 16384;

            // ---- R = Qs @ Fchunk^T ----
            {
                float racc[8][4];
#pragma unroll
                for (int j = 0; j < 8; j++)
#pragma unroll
                    for (int r = 0; r < 4; r++) racc[j][r] = 0.0f;
#pragma unroll
                for (int ks = 0; ks < 4; ks++) {
                    u32 fh[4][4];
#pragma unroll
                    for (int ng = 0; ng < 4; ng++) {
                        const int row = 16 * ng + lr16;
                        const u32 off = (u32)(row * 128 + 16 * ((2 * ks + lc) ^ (row & 7)));
                        LDSM_X4(fh[ng], sFh + off);
                    }
#pragma unroll
                    for (int ng = 0; ng < 4; ng++) {
                        MMA_F16(racc[2*ng],   qfh[ks], fh[ng][0], fh[ng][2]);
                        MMA_F16(racc[2*ng+1], qfh[ks], fh[ng][1], fh[ng][3]);
                    }
                }
                float* Rb = R3 + (t % 3) * AT_SLOT;
#pragma unroll
                for (int j = 0; j < 8; j++) {
                    *(float2*)&Rb[R0 * AT_RSTR + 8 * j + 2 * t4] = make_float2(racc[j][0], racc[j][1]);
                    *(float2*)&Rb[R1 * AT_RSTR + 8 * j + 2 * t4] = make_float2(racc[j][2], racc[j][3]);
                }
            }
            __syncwarp();

            // ---- S = Qs @ K^T ----
            float sacc[8][4];
#pragma unroll
            for (int j = 0; j < 8; j++)
#pragma unroll
                for (int r = 0; r < 4; r++) sacc[j][r] = 0.0f;
#pragma unroll
            for (int ks = 0; ks < 4; ks++) {
                u32 bkh_[4][4];
#pragma unroll
                for (int ng = 0; ng < 4; ng++) {
                    const int row = 16 * ng + lr16;
                    const u32 off = (u32)(row * 128 + 16 * ((2 * ks + lc) ^ (row & 7)));
                    LDSM_X4(bkh_[ng], sKh + off);
                }
#pragma unroll
                for (int ng = 0; ng < 4; ng++) {
                    MMA_F16(sacc[2*ng],   qfh[ks], bkh_[ng][0], bkh_[ng][2]);
                    MMA_F16(sacc[2*ng+1], qfh[ks], bkh_[ng][1], bkh_[ng][3]);
                }
            }

            // ---- gather skew bias + mask + online softmax (base-2) ----
            float mx0 = -1e30f, mx1 = -1e30f;
#pragma unroll
            for (int j = 0; j < 8; j++) {
#pragma unroll
                for (int c2 = 0; c2 < 2; c2++) {
                    const int dj = 8 * j + 2 * t4 + c2;
                    {
                        const int e = 64 + R0 - dj;
                        const int slot = (t + 1 + (e >> 6)) % 3;
                        float sv = sacc[j][c2] + R3[slot * AT_SLOT + R0 * AT_RSTR + (e & 63)];
                        if (t < 2 && (64 * (t - 1) + R0 - dj) < 0) sv = -1e30f;
                        sacc[j][c2] = sv;
                        mx0 = fmaxf(mx0, sv);
                    }
                    {
                        const int e = 64 + R1 - dj;
                        const int slot = (t + 1 + (e >> 6)) % 3;
                        float sv = sacc[j][2 + c2] + R3[slot * AT_SLOT + R1 * AT_RSTR + (e & 63)];
                        if (t < 2 && (64 * (t - 1) + R1 - dj) < 0) sv = -1e30f;
                        sacc[j][2 + c2] = sv;
                        mx1 = fmaxf(mx1, sv);
                    }
                }
            }
            mx0 = fmaxf(mx0, __shfl_xor_sync(0xffffffffu, mx0, 1));
            mx0 = fmaxf(mx0, __shfl_xor_sync(0xffffffffu, mx0, 2));
            mx1 = fmaxf(mx1, __shfl_xor_sync(0xffffffffu, mx1, 1));
            mx1 = fmaxf(mx1, __shfl_xor_sync(0xffffffffu, mx1, 2));

            const float mn0 = fmaxf(mrow0, mx0), mn1 = fmaxf(mrow1, mx1);
            const float al0 = exp2f(mrow0 - mn0), al1 = exp2f(mrow1 - mn1);
            mrow0 = mn0; mrow1 = mn1;

            float rs0 = 0.0f, rs1 = 0.0f;
#pragma unroll
            for (int j = 0; j < 8; j++) {
#pragma unroll
                for (int c2 = 0; c2 < 2; c2++) {
                    float e = exp2f(sacc[j][c2] - mn0);        // masked -> 0 by underflow
                    rs0 += e; sacc[j][c2] = e;
                    e = exp2f(sacc[j][2 + c2] - mn1);
                    rs1 += e; sacc[j][2 + c2] = e;
                }
            }
            rs0 += __shfl_xor_sync(0xffffffffu, rs0, 1);
            rs0 += __shfl_xor_sync(0xffffffffu, rs0, 2);
            rs1 += __shfl_xor_sync(0xffffffffu, rs1, 1);
            rs1 += __shfl_xor_sync(0xffffffffu, rs1, 2);
            lrow0 = lrow0 * al0 + rs0;
            lrow1 = lrow1 * al1 + rs1;
#pragma unroll
            for (int j = 0; j < 8; j++) {
                accO[j][0] *= al0; accO[j][1] *= al0;
                accO[j][2] *= al1; accO[j][3] *= al1;
            }

            // ---- O += P @ V ----
#pragma unroll
            for (int ks = 0; ks < 4; ks++) {
                u32 ph_[4];
                ph_[0] = round2h(sacc[2*ks][0],   sacc[2*ks][1]);
                ph_[1] = round2h(sacc[2*ks][2],   sacc[2*ks][3]);
                ph_[2] = round2h(sacc[2*ks+1][0], sacc[2*ks+1][1]);
                ph_[3] = round2h(sacc[2*ks+1][2], sacc[2*ks+1][3]);
                u32 bvh_[4][4];
#pragma unroll
                for (int ng = 0; ng < 4; ng++) {
                    const int row = 16 * ng + lr16;
                    const u32 off = (u32)(row * 128 + 16 * ((2 * ks + lc) ^ (row & 7)));
                    LDSM_X4(bvh_[ng], sVh + off);
                }
#pragma unroll
                for (int ng = 0; ng < 4; ng++) {
                    MMA_F16(accO[2*ng],   ph_, bvh_[ng][0], bvh_[ng][2]);
                    MMA_F16(accO[2*ng+1], ph_, bvh_[ng][1], bvh_[ng][3]);
                }
            }
            __syncthreads();
        }

        // ---- epilogue: normalize, fp16 out ----
        const float inv0 = 1.0f / lrow0, inv1 = 1.0f / lrow1;
        __half* o0h = oh + rowg0 * DD + h * DHH + 2 * t4;
#pragma unroll
        for (int j = 0; j < 8; j++) {
            *(u32*)(o0h + 8 * j)          = round2h(accO[j][0] * inv0, accO[j][1] * inv0);
            *(u32*)(o0h + 8 * DD + 8 * j) = round2h(accO[j][2] * inv1, accO[j][3] * inv1);
        }
    }
}

// ---------------------------------------------------------------------------
// Launch
// ---------------------------------------------------------------------------
extern "C" void kernel_launch(void* const* d_in, const int* in_sizes, int n_in,
                              void* d_out, int out_size)
{
    const float* x   = (const float*)d_in[0];
    // d_in[1] = mask — handled analytically
    const float* wq  = (const float*)d_in[2];
    const float* bq  = (const float*)d_in[3];
    const float* wk  = (const float*)d_in[4];
    const float* bk  = (const float*)d_in[5];
    const float* wv  = (const float*)d_in[6];
    const float* bv  = (const float*)d_in[7];
    const float* rel = (const float*)d_in[8];
    const float* w1  = (const float*)d_in[9];
    const float* b1  = (const float*)d_in[10];
    const float* w2  = (const float*)d_in[11];
    const float* b2  = (const float*)d_in[12];
    float* out = (float*)d_out;

    __half *xh, *qh, *kh, *vth, *relh, *ah, *hhp;
    __half *wqh, *wkh, *wvh, *w1h, *w2h;
    float* part;
    cudaGetSymbolAddress((void**)&xh,  g_xh);
    cudaGetSymbolAddress((void**)&qh,  g_qh);
    cudaGetSymbolAddress((void**)&kh,  g_kh);
    cudaGetSymbolAddress((void**)&vth, g_vth);
    cudaGetSymbolAddress((void**)&relh, g_relh);
    cudaGetSymbolAddress((void**)&ah,  g_ah);
    cudaGetSymbolAddress((void**)&hhp, g_hh);
    cudaGetSymbolAddress((void**)&part, g_part);
    cudaGetSymbolAddress((void**)&wqh, g_wqh);
    cudaGetSymbolAddress((void**)&wkh, g_wkh);
    cudaGetSymbolAddress((void**)&wvh, g_wvh);
    cudaGetSymbolAddress((void**)&w1h, g_w1h);
    cudaGetSymbolAddress((void**)&w2h, g_w2h);

    cudaFuncSetAttribute(tgemm_kernel<1>,  cudaFuncAttributeMaxDynamicSharedMemorySize, TGX_SMEM);
    cudaFuncSetAttribute(tgemm_kernel<2>,  cudaFuncAttributeMaxDynamicSharedMemorySize, TGX_SMEM);
    cudaFuncSetAttribute(qkv_fused_kernel, cudaFuncAttributeMaxDynamicSharedMemorySize, TGX_SMEM);
    cudaFuncSetAttribute(attn_mma_kernel,  cudaFuncAttributeMaxDynamicSharedMemorySize, AT_SMEM);

    // 0) Fused prep (converts + all weight transposes, one launch)
    prep_all_kernel<<<NB_PREP, 256>>>(
        (const float4*)x, (const float4*)rel, wq, wk, wv, w1, w2,
        xh, relh, wqh, wkh, wvh, w1h, w2h);

    // 1) Fused QKV (Q scaled by log2e/8)
    qkv_fused_kernel<<<dim3(DD / 128, MM / 128, 3), 256, TGX_SMEM>>>(
        xh, wqh, wkh, wvh, bq, bk, bv, qh, kh, vth);

    // 2) HMMA flash attention with relative bias (exp2 softmax)
    attn_mma_kernel<<<128, 256, AT_SMEM>>>(qh, kh, vth, relh, ah);

    // 3) FFN: FFN1 (relu, fp16 out); FFN2 split-K (2 halves) + reduce
    tgemm_kernel<1><<<dim3(DFCN / 128, MM / 128), 256, TGX_SMEM>>>(
        ah, w1h, b1, nullptr, hhp, MM, DFCN, DD, DD);
    tgemm_kernel<2><<<dim3(DD / 128, MM / 128, 2), 256, TGX_SMEM>>>(
        hhp, w2h, nullptr, part, nullptr, MM, DD, DFCN, DFCN / 2);
    reduce2_kernel<<<(N4X + 255) / 256, 256>>>(
        (const float4*)part, (const float4*)(part + (size_t)MM * DD), b2,
        (float4*)out);
}

// round 17
// speedup vs baseline: 2.2518x; 1.0241x over previous
#include <cuda_runtime.h>
#include <cuda_fp16.h>
#include <cstdint>
#include <cstddef>

// ---------------------------------------------------------------------------
// Problem constants
// ---------------------------------------------------------------------------
#define BB   2
#define LL   2048
#define DD   512
#define HH   8
#define DHH  64
#define DFCN 2048
#define MM   (BB * LL)        // 4096 rows

typedef unsigned long long u64;
typedef unsigned int u32;

// ---------------------------------------------------------------------------
// Scratch (device globals) — single-fp16 pipeline, fp32 accumulate.
// ---------------------------------------------------------------------------
__device__ __half g_xh[MM * DD];                       // x
__device__ __half g_qh[MM * DD];                       // Q scaled by log2e/8
__device__ __half g_kh[MM * DD];                       // K
__device__ __half g_vth[BB*HH*DHH * LL];               // V^T
__device__ __half g_relh[LL * DD];                     // rel
__device__ __half g_ah[MM * DD];                       // attn out
__device__ __half g_hh[MM * DFCN];                     // FFN hidden

// Transposed weights: T[n][k] = W[k][n]
__device__ __half g_wqh[DD * DD];
__device__ __half g_wkh[DD * DD];
__device__ __half g_wvh[DD * DD];
__device__ __half g_w1h[DFCN * DD];
__device__ __half g_w2h[DD * DFCN];

// ---------------------------------------------------------------------------
// Helpers
// ---------------------------------------------------------------------------
__device__ __forceinline__ u32 smem_u32(const void* p) {
    u32 a;
    asm("{ .reg .u64 t; cvta.to.shared.u64 t, %1; cvt.u32.u64 %0, t; }"
        : "=r"(a) : "l"(p));
    return a;
}

__device__ __forceinline__ u32 round2h(float x, float y) {
    __half2 h = __floats2half2_rn(x, y);
    return *(u32*)&h;
}

#define LDSM_X4(r, addr) \
    asm volatile("ldmatrix.sync.aligned.m8n8.x4.shared.b16 {%0,%1,%2,%3}, [%4];" \
        : "=r"((r)[0]), "=r"((r)[1]), "=r"((r)[2]), "=r"((r)[3]) : "r"(addr))

#define MMA_F16(d, a, b0, b1) \
    asm volatile("mma.sync.aligned.m16n8k16.row.col.f32.f16.f16.f32 " \
        "{%0,%1,%2,%3}, {%4,%5,%6,%7}, {%8,%9}, {%0,%1,%2,%3};" \
        : "+f"((d)[0]), "+f"((d)[1]), "+f"((d)[2]), "+f"((d)[3]) \
        : "r"((a)[0]), "r"((a)[1]), "r"((a)[2]), "r"((a)[3]), "r"(b0), "r"(b1))

__device__ __forceinline__ void cp16(u32 dst, const void* src) {
    asm volatile("cp.async.cg.shared.global [%0], [%1], 16;"
                 :: "r"(dst), "l"(src) : "memory");
}
#define CP_COMMIT()  asm volatile("cp.async.commit_group;" ::: "memory")
#define CP_WAIT(n)   asm volatile("cp.async.wait_group %0;" :: "n"(n) : "memory")

// ---------------------------------------------------------------------------
// Fused prep: one launch does x/rel fp16 convert + wq/wk/wv/w1/w2 transposes.
// ---------------------------------------------------------------------------
#define N4X (MM * DD / 4)
#define N4R (LL * DD / 4)
#define NB_CONV ((N4X + N4R) / 256)     // 3072
#define NB_W3   768
#define NB_FFN  2048
#define NB_PREP (NB_CONV + NB_W3 + NB_FFN)

__global__ __launch_bounds__(256)
void prep_all_kernel(const float4* __restrict__ X, const float4* __restrict__ R,
                     const float* __restrict__ wq, const float* __restrict__ wk,
                     const float* __restrict__ wv,
                     const float* __restrict__ w1, const float* __restrict__ w2,
                     __half* __restrict__ XH, __half* __restrict__ RH,
                     __half* __restrict__ wqh, __half* __restrict__ wkh,
                     __half* __restrict__ wvh,
                     __half* __restrict__ w1h, __half* __restrict__ w2h)
{
    const int bid = blockIdx.x;
    if (bid < NB_CONV) {
        int i = bid * 256 + threadIdx.x;
        const float4* src; __half* H; int j;
        if (i < N4X) { src = X; H = XH; j = i; }
        else         { src = R; H = RH; j = i - N4X; }
        float4 v = src[j];
        uint2 hp;
        hp.x = round2h(v.x, v.y);
        hp.y = round2h(v.z, v.w);
        *(uint2*)(H + 4 * (size_t)j) = hp;
        return;
    }

    __shared__ float t[32][33];
    const int tx = threadIdx.x & 31, ty = threadIdx.x >> 5;
    const float* W; __half* Th; int K, N, n0, k0;

    int wb = bid - NB_CONV;
    if (wb < NB_W3) {
        const int z = wb >> 8, r = wb & 255;
        W  = z == 0 ? wq : z == 1 ? wk : wv;
        Th = z == 0 ? wqh : z == 1 ? wkh : wvh;
        K = DD; N = DD;
        n0 = (r & 15) * 32; k0 = (r >> 4) * 32;
    } else {
        int wb2 = wb - NB_W3;
        const int z = wb2 >> 10, r = wb2 & 1023;
        W  = z == 0 ? w1 : w2;
        Th = z == 0 ? w1h : w2h;
        K = z == 0 ? DD : DFCN;
        N = z == 0 ? DFCN : DD;
        const int bx = r & 63, by = r >> 6;
        n0 = (z == 0 ? bx : by) * 32;
        k0 = (z == 0 ? by : bx) * 32;
    }

#pragma unroll
    for (int i = 0; i < 4; i++)
        t[ty + 8 * i][tx] = W[(size_t)(k0 + ty + 8 * i) * N + n0 + tx];
    __syncthreads();
#pragma unroll
    for (int i = 0; i < 4; i++) {
        int n = n0 + ty + 8 * i;
        Th[(size_t)n * K + k0 + tx] = __float2half_rn(t[tx][ty + 8 * i]);
    }
}

// ---------------------------------------------------------------------------
// fp16 HMMA GEMM core (128x128 tile): BK=64, 3-stage cp.async ring, 8 warps
// (2x4), 64x32 warp tile. 128B smem rows, swizzle c ^= (r&7). 96KB -> 2 CTA/SM.
// ---------------------------------------------------------------------------
#define TGX_TILE  16384
#define TGX_STAGE (2 * TGX_TILE)
#define TGX_SMEM  (3 * TGX_STAGE)

__device__ __forceinline__ void load_tile64(const __half* __restrict__ src,
                                            int ldk, u32 sdst, int tid)
{
#pragma unroll
    for (int i = 0; i < 4; i++) {
        int idx = tid + 256 * i;
        int r = idx >> 3, c = idx & 7;
        cp16(sdst + r * 128 + 16 * (c ^ (r & 7)), src + (size_t)r * ldk + 8 * c);
    }
}

__device__ __forceinline__ void tgx_stage_load(
    u32 sdst, const __half* A, const __half* B, int ldk, int kofs, int tid)
{
    load_tile64(A + kofs, ldk, sdst,            tid);
    load_tile64(B + kofs, ldk, sdst + TGX_TILE, tid);
}

__device__ __forceinline__ void tgx_compute_chunk(
    u32 base, int wm, int wn, int lr16, int lc, float acc[4][4][4])
{
    const u32 sA = base, sB = base + TGX_TILE;
#pragma unroll
    for (int ks = 0; ks < 4; ks++) {
        const int ch = 2 * ks + lc;
        u32 bh[2][4];
#pragma unroll
        for (int ng = 0; ng < 2; ng++) {
            int r = wn * 32 + ng * 16 + lr16;
            u32 off = r * 128 + 16 * (ch ^ (r & 7));
            LDSM_X4(bh[ng], sB + off);
        }
#pragma unroll
        for (int mt = 0; mt < 4; mt++) {
            int r = wm * 64 + mt * 16 + lr16;
            u32 off = r * 128 + 16 * (ch ^ (r & 7));
            u32 ah[4];
            LDSM_X4(ah, sA + off);
#pragma unroll
            for (int nt = 0; nt < 4; nt++) {
                const int ng = nt >> 1, hi = nt & 1;
                MMA_F16(acc[mt][nt], ah, bh[ng][hi], bh[ng][2 + hi]);
            }
        }
    }
}

__device__ __forceinline__ void tgx_mainloop(
    u32 sb, const __half* Abase, const __half* Bbase,
    int ldk, int Klen, int tid, int wm, int wn, int lr16, int lc,
    float acc[4][4][4])
{
    const int NC = Klen >> 6;
    tgx_stage_load(sb, Abase, Bbase, ldk, 0, tid);
    CP_COMMIT();
    if (NC > 1) {
        tgx_stage_load(sb + TGX_STAGE, Abase, Bbase, ldk, 64, tid);
        CP_COMMIT();
    }
    int sc = 0, sn = 2;
    for (int c = 0; c < NC; c++) {
        CP_WAIT(1);
        __syncthreads();
        if (c + 2 < NC) {
            tgx_stage_load(sb + sn * TGX_STAGE, Abase, Bbase, ldk, (c + 2) * 64, tid);
            CP_COMMIT();
        } else {
            CP_COMMIT();
        }
        tgx_compute_chunk(sb + sc * TGX_STAGE, wm, wn, lr16, lc, acc);
        sc = sc == 2 ? 0 : sc + 1;
        sn = sn == 2 ? 0 : sn + 1;
    }
}

// FFN1: relu + fp16 out.
__global__ __launch_bounds__(256, 2)
void tgemm_relu_kernel(const __half* __restrict__ A,
                       const __half* __restrict__ B,
                       const float* __restrict__ bias,
                       __half* __restrict__ Ch,
                       int M, int N, int K)
{
    extern __shared__ char smem[];
    const u32 sb = smem_u32(smem);
    const int tid  = threadIdx.x;
    const int wid  = tid >> 5, lane = tid & 31;
    const int wm   = wid >> 2, wn = wid & 3;
    const int m0   = blockIdx.y * 128;
    const int n0   = blockIdx.x * 128;
    const int lr16 = lane & 15, lc = lane >> 4;

    float acc[4][4][4];
#pragma unroll
    for (int mt = 0; mt < 4; mt++)
#pragma unroll
        for (int nt = 0; nt < 4; nt++)
#pragma unroll
            for (int r = 0; r < 4; r++) acc[mt][nt][r] = 0.0f;

    tgx_mainloop(sb, A + (size_t)m0 * K, B + (size_t)n0 * K,
                 K, K, tid, wm, wn, lr16, lc, acc);

    const int tg = lane >> 2;
    const int tc = (lane & 3) * 2;
#pragma unroll
    for (int mt = 0; mt < 4; mt++) {
#pragma unroll
        for (int half_ = 0; half_ < 2; half_++) {
            const int m = m0 + wm * 64 + mt * 16 + tg + 8 * half_;
#pragma unroll
            for (int nt = 0; nt < 4; nt++) {
                const int n = n0 + wn * 32 + nt * 8 + tc;
                float v0 = fmaxf(acc[mt][nt][2 * half_]     + bias[n],     0.0f);
                float v1 = fmaxf(acc[mt][nt][2 * half_ + 1] + bias[n + 1], 0.0f);
                *(u32*)(Ch + (size_t)m * N + n) = round2h(v0, v1);
            }
        }
    }
}

// ---------------------------------------------------------------------------
// FFN2: 128x64 tile, full K=2048 per CTA (grid 8 x 32 = 256 CTAs, balanced,
// deterministic — no split-K partials or reduce). 8 warps (4x2), 32x32 warp
// tile. Stage = A(16KB) + B(8KB) = 24KB; 3 stages = 72KB -> 2 CTA/SM.
// ---------------------------------------------------------------------------
#define TF2_ATILE 16384                 // 128 x 64 x 2B
#define TF2_BTILE 8192                  // 64 x 64 x 2B
#define TF2_STAGE (TF2_ATILE + TF2_BTILE)
#define TF2_SMEM  (3 * TF2_STAGE)       // 72KB

__device__ __forceinline__ void load_tile64r64(const __half* __restrict__ src,
                                               int ldk, u32 sdst, int tid)
{
    // 64 rows x 8 chunks = 512 chunks
#pragma unroll
    for (int i = 0; i < 2; i++) {
        int idx = tid + 256 * i;
        int r = idx >> 3, c = idx & 7;
        cp16(sdst + r * 128 + 16 * (c ^ (r & 7)), src + (size_t)r * ldk + 8 * c);
    }
}

__device__ __forceinline__ void tf2_stage_load(
    u32 sdst, const __half* A, const __half* B, int ldk, int kofs, int tid)
{
    load_tile64(A + kofs, ldk, sdst, tid);
    load_tile64r64(B + kofs, ldk, sdst + TF2_ATILE, tid);
}

__global__ __launch_bounds__(256, 2)
void ffn2_kernel(const __half* __restrict__ A,
                 const __half* __restrict__ B,
                 const float* __restrict__ bias,
                 float* __restrict__ Cf)
{
    extern __shared__ char smem[];
    const u32 sb = smem_u32(smem);
    const int tid  = threadIdx.x;
    const int wid  = tid >> 5, lane = tid & 31;
    const int wm   = wid >> 1, wn = wid & 1;     // 4 x 2 warp grid
    const int m0   = blockIdx.y * 128;
    const int n0   = blockIdx.x * 64;
    const int lr16 = lane & 15, lc = lane >> 4;
    const int K    = DFCN;

    float acc[2][4][4];
#pragma unroll
    for (int mt = 0; mt < 2; mt++)
#pragma unroll
        for (int nt = 0; nt < 4; nt++)
#pragma unroll
            for (int r = 0; r < 4; r++) acc[mt][nt][r] = 0.0f;

    const __half* Ab = A + (size_t)m0 * K;
    const __half* Bb = B + (size_t)n0 * K;
    const int NC = K >> 6;   // 32

    tf2_stage_load(sb, Ab, Bb, K, 0, tid);
    CP_COMMIT();
    tf2_stage_load(sb + TF2_STAGE, Ab, Bb, K, 64, tid);
    CP_COMMIT();

    int sc = 0, sn = 2;
    for (int c = 0; c < NC; c++) {
        CP_WAIT(1);
        __syncthreads();
        if (c + 2 < NC) {
            tf2_stage_load(sb + sn * TF2_STAGE, Ab, Bb, K, (c + 2) * 64, tid);
            CP_COMMIT();
        } else {
            CP_COMMIT();
        }
        const u32 base = sb + sc * TF2_STAGE;
        const u32 sA = base, sB = base + TF2_ATILE;
#pragma unroll
        for (int ks = 0; ks < 4; ks++) {
            const int ch = 2 * ks + lc;
            u32 bh[2][4];
#pragma unroll
            for (int ng = 0; ng < 2; ng++) {
                int r = wn * 32 + ng * 16 + lr16;
                u32 off = r * 128 + 16 * (ch ^ (r & 7));
                LDSM_X4(bh[ng], sB + off);
            }
#pragma unroll
            for (int mt = 0; mt < 2; mt++) {
                int r = wm * 32 + mt * 16 + lr16;
                u32 off = r * 128 + 16 * (ch ^ (r & 7));
                u32 ah[4];
                LDSM_X4(ah, sA + off);
#pragma unroll
                for (int nt = 0; nt < 4; nt++) {
                    const int ng = nt >> 1, hi = nt & 1;
                    MMA_F16(acc[mt][nt], ah, bh[ng][hi], bh[ng][2 + hi]);
                }
            }
        }
        sc = sc == 2 ? 0 : sc + 1;
        sn = sn == 2 ? 0 : sn + 1;
    }

    const int tg = lane >> 2;
    const int tc = (lane & 3) * 2;
#pragma unroll
    for (int mt = 0; mt < 2; mt++) {
#pragma unroll
        for (int half_ = 0; half_ < 2; half_++) {
            const int m = m0 + wm * 32 + mt * 16 + tg + 8 * half_;
#pragma unroll
            for (int nt = 0; nt < 4; nt++) {
                const int n = n0 + wn * 32 + nt * 8 + tc;
                *(float2*)(Cf + (size_t)m * DD + n) = make_float2(
                    acc[mt][nt][2 * half_]     + bias[n],
                    acc[mt][nt][2 * half_ + 1] + bias[n + 1]);
            }
        }
    }
}

// Fused QKV: z=0 Q (scale log2e/8), z=1 K, z=2 V (smem transpose -> V^T fp16).
__global__ __launch_bounds__(256, 2)
void qkv_fused_kernel(const __half* __restrict__ xh,
                      const __half* __restrict__ wqh,
                      const __half* __restrict__ wkh,
                      const __half* __restrict__ wvh,
                      const float* __restrict__ bq, const float* __restrict__ bk,
                      const float* __restrict__ bv,
                      __half* __restrict__ qh, __half* __restrict__ kh,
                      __half* __restrict__ vth)
{
    extern __shared__ char smem[];
    const u32 sb = smem_u32(smem);
    const int tid  = threadIdx.x;
    const int wid  = tid >> 5, lane = tid & 31;
    const int wm   = wid >> 2, wn = wid & 3;
    const int m0   = blockIdx.y * 128;
    const int n0   = blockIdx.x * 128;
    const int z    = blockIdx.z;
    const int lr16 = lane & 15, lc = lane >> 4;

    const __half* B = z == 0 ? wqh : z == 1 ? wkh : wvh;
    const float* bias = z == 0 ? bq : z == 1 ? bk : bv;

    float acc[4][4][4];
#pragma unroll
    for (int mt = 0; mt < 4; mt++)
#pragma unroll
        for (int nt = 0; nt < 4; nt++)
#pragma unroll
            for (int r = 0; r < 4; r++) acc[mt][nt][r] = 0.0f;

    tgx_mainloop(sb, xh + (size_t)m0 * DD, B + (size_t)n0 * DD,
                 DD, DD, tid, wm, wn, lr16, lc, acc);

    const int tg = lane >> 2;
    const int tc = (lane & 3) * 2;

    if (z < 2) {
        const float scl = (z == 0) ? (0.125f * 1.4426950408889634f) : 1.0f;
        __half* C = z == 0 ? qh : kh;
#pragma unroll
        for (int mt = 0; mt < 4; mt++)
#pragma unroll
            for (int half_ = 0; half_ < 2; half_++) {
                const int m = m0 + wm * 64 + mt * 16 + tg + 8 * half_;
#pragma unroll
                for (int nt = 0; nt < 4; nt++) {
                    const int n = n0 + wn * 32 + nt * 8 + tc;
                    float v0 = (acc[mt][nt][2 * half_]     + bias[n])     * scl;
                    float v1 = (acc[mt][nt][2 * half_ + 1] + bias[n + 1]) * scl;
                    *(u32*)(C + (size_t)m * DD + n) = round2h(v0, v1);
                }
            }
    } else {
        float* tile = (float*)smem;     // [128][68] fp32
#pragma unroll 1
        for (int hf = 0; hf < 2; hf++) {
            __syncthreads();
#pragma unroll
            for (int mt = 0; mt < 4; mt++) {
#pragma unroll
                for (int half_ = 0; half_ < 2; half_++) {
                    const int ml = wm * 64 + mt * 16 + tg + 8 * half_;
#pragma unroll
                    for (int nt = 0; nt < 4; nt++) {
                        const int nl = wn * 32 + nt * 8 + tc;
                        if ((nl & 64) == (hf << 6)) {
                            const int nll = nl & 63;
                            tile[ml * 68 + nll]     = acc[mt][nt][2 * half_]     + bias[n0 + nl];
                            tile[ml * 68 + nll + 1] = acc[mt][nt][2 * half_ + 1] + bias[n0 + nl + 1];
                        }
                    }
                }
            }
            __syncthreads();
            const int b    = m0 >> 11;
            const int tok0 = m0 & 2047;
            const int nl   = tid >> 2;
            const int mh   = (tid & 3) * 32;
            const size_t orow = (size_t)(b * 512 + n0 + hf * 64 + nl) * LL + tok0 + mh;
#pragma unroll
            for (int it = 0; it < 4; it++) {
                u32 hp[4];
#pragma unroll
                for (int j2 = 0; j2 < 4; j2++) {
                    float v0 = tile[(mh + 8 * it + 2 * j2)     * 68 + nl];
                    float v1 = tile[(mh + 8 * it + 2 * j2 + 1) * 68 + nl];
                    hp[j2] = round2h(v0, v1);
                }
                *(uint4*)(vth + orow + 8 * it) = *(uint4*)hp;
            }
        }
    }
}

// ---------------------------------------------------------------------------
// HMMA flash attention: single-pass fp16 (S, R, PV), fp32 accumulate, exp2.
// ---------------------------------------------------------------------------
#define AT_STAGE 24576
#define AT_R3OFF (2 * AT_STAGE)
#define AT_RSTR  66
#define AT_SLOT  (128 * AT_RSTR)
#define AT_SMEM  (AT_R3OFF + 3 * AT_SLOT * 4)   // 150528

__device__ __forceinline__ void attn_load_stage(
    u32 dstbase, int j0, int t, int tid, int b, int h,
    const __half* __restrict__ kh,
    const __half* __restrict__ relh,
    const __half* __restrict__ vth)
{
    const int r0 = tid >> 3, c = tid & 7;
#pragma unroll
    for (int i = 0; i < 2; i++) {
        const int r = r0 + 32 * i;
        const u32 sw = (u32)(r * 128 + 16 * (c ^ (r & 7)));
        const size_t krow = (size_t)(b * LL + j0 + r) * DD + h * DHH + 8 * c;
        const size_t frow = (size_t)(2047 - 64 * t - r) * DD + h * DHH + 8 * c;
        const size_t vrow = (size_t)((b * 8 + h) * 64 + r) * LL + j0 + 8 * c;
        cp16(dstbase +          sw, kh   + krow);
        cp16(dstbase +  8192 +  sw, relh + frow);
        cp16(dstbase + 16384 +  sw, vth  + vrow);
    }
}

__global__ __launch_bounds__(256, 1)
void attn_mma_kernel(const __half* __restrict__ qh,
                     const __half* __restrict__ kh,
                     const __half* __restrict__ vth,
                     const __half* __restrict__ relh,
                     __half* __restrict__ oh)
{
    extern __shared__ char smem[];
    const u32 sb = smem_u32(smem);
    float* R3 = (float*)(smem + AT_R3OFF);

    const int tid = threadIdx.x, lane = tid & 31, w = tid >> 5;
    const int p   = blockIdx.x >> 4;
    const int bh  = blockIdx.x & 15;
    const int b   = bh >> 3, h = bh & 7;
    const int g   = lane >> 2, t4 = lane & 3;
    const int lr16 = lane & 15, lc = lane >> 4;

#pragma unroll 1
    for (int qq = 0; qq < 2; qq++) {
        const int q  = qq ? (15 - p) : p;
        const int i0 = q * 128;
        const int NT = 2 * q + 2;
        const int R0 = 16 * w + g, R1 = R0 + 8;
        const size_t rowg0 = (size_t)(b * LL + i0 + R0);

        u32 qfh[4][4];
        {
            const __half* ph_ = qh + rowg0 * DD + h * DHH + 2 * t4;
#pragma unroll
            for (int ks = 0; ks < 4; ks++) {
                qfh[ks][0] = *(const u32*)(ph_ + 16 * ks);
                qfh[ks][1] = *(const u32*)(ph_ + 16 * ks + 8 * DD);
                qfh[ks][2] = *(const u32*)(ph_ + 16 * ks + 8);
                qfh[ks][3] = *(const u32*)(ph_ + 16 * ks + 8 * DD + 8);
            }
        }

        float accO[8][4];
#pragma unroll
        for (int j = 0; j < 8; j++)
#pragma unroll
            for (int r = 0; r < 4; r++) accO[j][r] = 0.0f;
        float mrow0 = -1e30f, mrow1 = -1e30f, lrow0 = 0.0f, lrow1 = 0.0f;

        attn_load_stage(sb, i0 + 64, 0, tid, b, h, kh, relh, vth);
        CP_COMMIT();

#pragma unroll 1
        for (int t = 0; t < NT; t++) {
            const int j0 = i0 + 64 - 64 * t;
            if (t + 1 < NT) {
                attn_load_stage(sb + ((t + 1) & 1) * AT_STAGE, j0 - 64, t + 1,
                                tid, b, h, kh, relh, vth);
                CP_COMMIT();
                CP_WAIT(1);
            } else {
                CP_WAIT(0);
            }
            __syncthreads();

            const u32 st  = sb + (t & 1) * AT_STAGE;
            const u32 sKh = st, sFh = st + 8192, sVh = st + 16384;

            // ---- R = Qs @ Fchunk^T ----
            {
                float racc[8][4];
#pragma unroll
                for (int j = 0; j < 8; j++)
#pragma unroll
                    for (int r = 0; r < 4; r++) racc[j][r] = 0.0f;
#pragma unroll
                for (int ks = 0; ks < 4; ks++) {
                    u32 fh[4][4];
#pragma unroll
                    for (int ng = 0; ng < 4; ng++) {
                        const int row = 16 * ng + lr16;
                        const u32 off = (u32)(row * 128 + 16 * ((2 * ks + lc) ^ (row & 7)));
                        LDSM_X4(fh[ng], sFh + off);
                    }
#pragma unroll
                    for (int ng = 0; ng < 4; ng++) {
                        MMA_F16(racc[2*ng],   qfh[ks], fh[ng][0], fh[ng][2]);
                        MMA_F16(racc[2*ng+1], qfh[ks], fh[ng][1], fh[ng][3]);
                    }
                }
                float* Rb = R3 + (t % 3) * AT_SLOT;
#pragma unroll
                for (int j = 0; j < 8; j++) {
                    *(float2*)&Rb[R0 * AT_RSTR + 8 * j + 2 * t4] = make_float2(racc[j][0], racc[j][1]);
                    *(float2*)&Rb[R1 * AT_RSTR + 8 * j + 2 * t4] = make_float2(racc[j][2], racc[j][3]);
                }
            }
            __syncwarp();

            // ---- S = Qs @ K^T ----
            float sacc[8][4];
#pragma unroll
            for (int j = 0; j < 8; j++)
#pragma unroll
                for (int r = 0; r < 4; r++) sacc[j][r] = 0.0f;
#pragma unroll
            for (int ks = 0; ks < 4; ks++) {
                u32 bkh_[4][4];
#pragma unroll
                for (int ng = 0; ng < 4; ng++) {
                    const int row = 16 * ng + lr16;
                    const u32 off = (u32)(row * 128 + 16 * ((2 * ks + lc) ^ (row & 7)));
                    LDSM_X4(bkh_[ng], sKh + off);
                }
#pragma unroll
                for (int ng = 0; ng < 4; ng++) {
                    MMA_F16(sacc[2*ng],   qfh[ks], bkh_[ng][0], bkh_[ng][2]);
                    MMA_F16(sacc[2*ng+1], qfh[ks], bkh_[ng][1], bkh_[ng][3]);
                }
            }

            // ---- gather skew bias + mask + online softmax (base-2) ----
            float mx0 = -1e30f, mx1 = -1e30f;
#pragma unroll
            for (int j = 0; j < 8; j++) {
#pragma unroll
                for (int c2 = 0; c2 < 2; c2++) {
                    const int dj = 8 * j + 2 * t4 + c2;
                    {
                        const int e = 64 + R0 - dj;
                        const int slot = (t + 1 + (e >> 6)) % 3;
                        float sv = sacc[j][c2] + R3[slot * AT_SLOT + R0 * AT_RSTR + (e & 63)];
                        if (t < 2 && (64 * (t - 1) + R0 - dj) < 0) sv = -1e30f;
                        sacc[j][c2] = sv;
                        mx0 = fmaxf(mx0, sv);
                    }
                    {
                        const int e = 64 + R1 - dj;
                        const int slot = (t + 1 + (e >> 6)) % 3;
                        float sv = sacc[j][2 + c2] + R3[slot * AT_SLOT + R1 * AT_RSTR + (e & 63)];
                        if (t < 2 && (64 * (t - 1) + R1 - dj) < 0) sv = -1e30f;
                        sacc[j][2 + c2] = sv;
                        mx1 = fmaxf(mx1, sv);
                    }
                }
            }
            mx0 = fmaxf(mx0, __shfl_xor_sync(0xffffffffu, mx0, 1));
            mx0 = fmaxf(mx0, __shfl_xor_sync(0xffffffffu, mx0, 2));
            mx1 = fmaxf(mx1, __shfl_xor_sync(0xffffffffu, mx1, 1));
            mx1 = fmaxf(mx1, __shfl_xor_sync(0xffffffffu, mx1, 2));

            const float mn0 = fmaxf(mrow0, mx0), mn1 = fmaxf(mrow1, mx1);
            const float al0 = exp2f(mrow0 - mn0), al1 = exp2f(mrow1 - mn1);
            mrow0 = mn0; mrow1 = mn1;

            float rs0 = 0.0f, rs1 = 0.0f;
#pragma unroll
            for (int j = 0; j < 8; j++) {
#pragma unroll
                for (int c2 = 0; c2 < 2; c2++) {
                    float e = exp2f(sacc[j][c2] - mn0);
                    rs0 += e; sacc[j][c2] = e;
                    e = exp2f(sacc[j][2 + c2] - mn1);
                    rs1 += e; sacc[j][2 + c2] = e;
                }
            }
            rs0 += __shfl_xor_sync(0xffffffffu, rs0, 1);
            rs0 += __shfl_xor_sync(0xffffffffu, rs0, 2);
            rs1 += __shfl_xor_sync(0xffffffffu, rs1, 1);
            rs1 += __shfl_xor_sync(0xffffffffu, rs1, 2);
            lrow0 = lrow0 * al0 + rs0;
            lrow1 = lrow1 * al1 + rs1;
#pragma unroll
            for (int j = 0; j < 8; j++) {
                accO[j][0] *= al0; accO[j][1] *= al0;
                accO[j][2] *= al1; accO[j][3] *= al1;
            }

            // ---- O += P @ V ----
#pragma unroll
            for (int ks = 0; ks < 4; ks++) {
                u32 ph_[4];
                ph_[0] = round2h(sacc[2*ks][0],   sacc[2*ks][1]);
                ph_[1] = round2h(sacc[2*ks][2],   sacc[2*ks][3]);
                ph_[2] = round2h(sacc[2*ks+1][0], sacc[2*ks+1][1]);
                ph_[3] = round2h(sacc[2*ks+1][2], sacc[2*ks+1][3]);
                u32 bvh_[4][4];
#pragma unroll
                for (int ng = 0; ng < 4; ng++) {
                    const int row = 16 * ng + lr16;
                    const u32 off = (u32)(row * 128 + 16 * ((2 * ks + lc) ^ (row & 7)));
                    LDSM_X4(bvh_[ng], sVh + off);
                }
#pragma unroll
                for (int ng = 0; ng < 4; ng++) {
                    MMA_F16(accO[2*ng],   ph_, bvh_[ng][0], bvh_[ng][2]);
                    MMA_F16(accO[2*ng+1], ph_, bvh_[ng][1], bvh_[ng][3]);
                }
            }
            __syncthreads();
        }

        // ---- epilogue: normalize, fp16 out ----
        const float inv0 = 1.0f / lrow0, inv1 = 1.0f / lrow1;
        __half* o0h = oh + rowg0 * DD + h * DHH + 2 * t4;
#pragma unroll
        for (int j = 0; j < 8; j++) {
            *(u32*)(o0h + 8 * j)          = round2h(accO[j][0] * inv0, accO[j][1] * inv0);
            *(u32*)(o0h + 8 * DD + 8 * j) = round2h(accO[j][2] * inv1, accO[j][3] * inv1);
        }
    }
}

// ---------------------------------------------------------------------------
// Launch
// ---------------------------------------------------------------------------
extern "C" void kernel_launch(void* const* d_in, const int* in_sizes, int n_in,
                              void* d_out, int out_size)
{
    const float* x   = (const float*)d_in[0];
    // d_in[1] = mask — handled analytically
    const float* wq  = (const float*)d_in[2];
    const float* bq  = (const float*)d_in[3];
    const float* wk  = (const float*)d_in[4];
    const float* bk  = (const float*)d_in[5];
    const float* wv  = (const float*)d_in[6];
    const float* bv  = (const float*)d_in[7];
    const float* rel = (const float*)d_in[8];
    const float* w1  = (const float*)d_in[9];
    const float* b1  = (const float*)d_in[10];
    const float* w2  = (const float*)d_in[11];
    const float* b2  = (const float*)d_in[12];
    float* out = (float*)d_out;

    __half *xh, *qh, *kh, *vth, *relh, *ah, *hhp;
    __half *wqh, *wkh, *wvh, *w1h, *w2h;
    cudaGetSymbolAddress((void**)&xh,  g_xh);
    cudaGetSymbolAddress((void**)&qh,  g_qh);
    cudaGetSymbolAddress((void**)&kh,  g_kh);
    cudaGetSymbolAddress((void**)&vth, g_vth);
    cudaGetSymbolAddress((void**)&relh, g_relh);
    cudaGetSymbolAddress((void**)&ah,  g_ah);
    cudaGetSymbolAddress((void**)&hhp, g_hh);
    cudaGetSymbolAddress((void**)&wqh, g_wqh);
    cudaGetSymbolAddress((void**)&wkh, g_wkh);
    cudaGetSymbolAddress((void**)&wvh, g_wvh);
    cudaGetSymbolAddress((void**)&w1h, g_w1h);
    cudaGetSymbolAddress((void**)&w2h, g_w2h);

    cudaFuncSetAttribute(tgemm_relu_kernel, cudaFuncAttributeMaxDynamicSharedMemorySize, TGX_SMEM);
    cudaFuncSetAttribute(ffn2_kernel,       cudaFuncAttributeMaxDynamicSharedMemorySize, TF2_SMEM);
    cudaFuncSetAttribute(qkv_fused_kernel,  cudaFuncAttributeMaxDynamicSharedMemorySize, TGX_SMEM);
    cudaFuncSetAttribute(attn_mma_kernel,   cudaFuncAttributeMaxDynamicSharedMemorySize, AT_SMEM);

    // 0) Fused prep
    prep_all_kernel<<<NB_PREP, 256>>>(
        (const float4*)x, (const float4*)rel, wq, wk, wv, w1, w2,
        xh, relh, wqh, wkh, wvh, w1h, w2h);

    // 1) Fused QKV (Q scaled by log2e/8)
    qkv_fused_kernel<<<dim3(DD / 128, MM / 128, 3), 256, TGX_SMEM>>>(
        xh, wqh, wkh, wvh, bq, bk, bv, qh, kh, vth);

    // 2) HMMA flash attention with relative bias (exp2 softmax)
    attn_mma_kernel<<<128, 256, AT_SMEM>>>(qh, kh, vth, relh, ah);

    // 3) FFN1 (relu, fp16 out); FFN2 (128x64 tiles, direct fp32 out + bias)
    tgemm_relu_kernel<<<dim3(DFCN / 128, MM / 128), 256, TGX_SMEM>>>(
        ah, w1h, b1, hhp, MM, DFCN, DD);
    ffn2_kernel<<<dim3(DD / 64, MM / 128), 256, TF2_SMEM>>>(
        hhp, w2h, b2, out);
}